// round 9
// baseline (speedup 1.0000x reference)
#include <cuda_runtime.h>
#include <cuda_bf16.h>
#include <math.h>

#define NB 128
#define NT 256
#define BR 32
#define AS  264     // activation & weight-chunk row stride (bf16 units) = 528B
#define WS  264

// ---- smem layout ----
#define F_SWF 0                    // 256*32 fp32 final weights
#define F_XS  8192                 // 32*33
#define F_TE  9248
#define F_HT  9264
#define F_TF  9296
#define F_CF  9312
#define B_A0H 18656                // 32*264 (A2 aliases A0)
#define B_A0L 27104
#define B_A1H 35552
#define B_A1L 44000
#define B_SW0H 52448
#define B_SW0L 60896
#define B_SW1H 69344
#define B_SW1L 77792
#define B_SW2H 86240
#define B_SW2L 94688
#define SMEM_BYTES 206272

// pre-split weights (bf16 hi/lo), layout [k][n]; w0 k-padded to 192
#define W0_OFF 0
#define W1_OFF (192*256)
#define W2_OFF (192*256 + 256*256)
#define W_TOT  (192*256 + 256*256 + 256*256)
__device__ __nv_bfloat16 g_whi[W_TOT];
__device__ __nv_bfloat16 g_wlo[W_TOT];

// ---- packed f32x2 helpers (final layer) ------------------------------------
#define FMA2(acc, aa, bb) \
    asm("fma.rn.f32x2 %0, %1, %2, %0;" : "+l"(acc) : "l"(aa), "l"(bb))
#define PACK_DUP(dst, fv) do { \
    unsigned _pi = __float_as_uint(fv); \
    asm("mov.b64 %0, {%1, %1};" : "=l"(dst) : "r"(_pi)); } while (0)
#define UNPACK2(lo, hi, src) do { \
    unsigned _u0, _u1; \
    asm("mov.b64 {%0, %1}, %2;" : "=r"(_u0), "=r"(_u1) : "l"(src)); \
    lo = __uint_as_float(_u0); hi = __uint_as_float(_u1); } while (0)

// ---------------- threefry2x32-20 (exact JAX) ------------------------------
__device__ __forceinline__ unsigned rotl32(unsigned x, int r) {
    return __funnelshift_l(x, x, r);
}
__device__ __forceinline__ void threefry2x32(unsigned k0, unsigned k1,
                                             unsigned &x0, unsigned &x1) {
    unsigned k2 = k0 ^ k1 ^ 0x1BD11BDAu;
#define TFR(r) { x0 += x1; x1 = rotl32(x1, r); x1 ^= x0; }
    x0 += k0; x1 += k1;
    TFR(13) TFR(15) TFR(26) TFR(6)
    x0 += k1; x1 += k2 + 1u;
    TFR(17) TFR(29) TFR(16) TFR(24)
    x0 += k2; x1 += k0 + 2u;
    TFR(13) TFR(15) TFR(26) TFR(6)
    x0 += k0; x1 += k1 + 3u;
    TFR(17) TFR(29) TFR(16) TFR(24)
    x0 += k1; x1 += k2 + 4u;
    TFR(13) TFR(15) TFR(26) TFR(6)
    x0 += k2; x1 += k0 + 5u;
#undef TFR
}

// ---------------- XLA ErfInv f32 (Giles) ------------------------------------
__device__ __forceinline__ float erfinv_xla(float x) {
    float w = -log1pf(-x * x);
    float p;
    if (w < 5.0f) {
        w -= 2.5f;
        p = 2.81022636e-08f;
        p = fmaf(p, w, 3.43273939e-07f);
        p = fmaf(p, w, -3.5233877e-06f);
        p = fmaf(p, w, -4.39150654e-06f);
        p = fmaf(p, w, 0.00021858087f);
        p = fmaf(p, w, -0.00125372503f);
        p = fmaf(p, w, -0.00417768164f);
        p = fmaf(p, w, 0.246640727f);
        p = fmaf(p, w, 1.50140941f);
    } else {
        w = sqrtf(w) - 3.0f;
        p = -0.000200214257f;
        p = fmaf(p, w, 0.000100950558f);
        p = fmaf(p, w, 0.00134934322f);
        p = fmaf(p, w, -0.00367342844f);
        p = fmaf(p, w, 0.00573950773f);
        p = fmaf(p, w, -0.0076224613f);
        p = fmaf(p, w, 0.00943887047f);
        p = fmaf(p, w, 1.00167406f);
        p = fmaf(p, w, 2.83297682f);
    }
    return p * x;
}

__device__ __forceinline__ float mish_f(float x) {
    if (x > 20.0f) return x;
    float u = expf(x);
    float s = u * (u + 2.0f);
    return x * (s / (s + 2.0f));
}

// ---------------- cp.async helpers ------------------------------------------
__device__ __forceinline__ void cp16b(__nv_bfloat16* dst, const __nv_bfloat16* src) {
    unsigned sa = (unsigned)__cvta_generic_to_shared(dst);
    asm volatile("cp.async.cg.shared.global [%0], [%1], 16;\n" :: "r"(sa), "l"(src));
}
#define CP_COMMIT() asm volatile("cp.async.commit_group;\n" ::: "memory")
#define CP_WAIT(n)  asm volatile("cp.async.wait_group %0;\n" :: "n"(n) : "memory")

// stage one 32x256 bf16 chunk (hi+lo); NT=256 -> 4+4 cp.async per thread
__device__ __forceinline__ void stage_w(__nv_bfloat16* dh, __nv_bfloat16* dl,
                                        const __nv_bfloat16* sh,
                                        const __nv_bfloat16* sl, int tid) {
#pragma unroll
    for (int l = 0; l < 4; ++l) {
        int idx = l * NT + tid;       // 1024 16B units
        int row = idx >> 5, u = idx & 31;
        cp16b(dh + row * WS + u * 8, sh + row * 256 + u * 8);
    }
#pragma unroll
    for (int l = 0; l < 4; ++l) {
        int idx = l * NT + tid;
        int row = idx >> 5, u = idx & 31;
        cp16b(dl + row * WS + u * 8, sl + row * 256 + u * 8);
    }
}

// ---------------- mma / ldmatrix wrappers ------------------------------------
__device__ __forceinline__ void mma_bf16(float* c, const unsigned* a,
                                         unsigned b0, unsigned b1) {
    asm volatile(
        "mma.sync.aligned.m16n8k16.row.col.f32.bf16.bf16.f32 "
        "{%0,%1,%2,%3}, {%4,%5,%6,%7}, {%8,%9}, {%0,%1,%2,%3};"
        : "+f"(c[0]), "+f"(c[1]), "+f"(c[2]), "+f"(c[3])
        : "r"(a[0]), "r"(a[1]), "r"(a[2]), "r"(a[3]), "r"(b0), "r"(b1));
}
__device__ __forceinline__ void ldsm4t(unsigned* r, const __nv_bfloat16* p) {
    unsigned addr = (unsigned)__cvta_generic_to_shared(p);
    asm volatile("ldmatrix.sync.aligned.m8n8.x4.trans.shared.b16 {%0,%1,%2,%3}, [%4];"
        : "=r"(r[0]), "=r"(r[1]), "=r"(r[2]), "=r"(r[3]) : "r"(addr));
}

__device__ __forceinline__ void store_split2(__nv_bfloat16* H, __nv_bfloat16* L,
                                             int off, float v0, float v1) {
    __nv_bfloat16 h0 = __float2bfloat16(v0), h1 = __float2bfloat16(v1);
    __nv_bfloat16 l0 = __float2bfloat16(v0 - __bfloat162float(h0));
    __nv_bfloat16 l1 = __float2bfloat16(v1 - __bfloat162float(h1));
    *reinterpret_cast<unsigned*>(H + off) =
        (unsigned)__bfloat16_as_ushort(h0) | ((unsigned)__bfloat16_as_ushort(h1) << 16);
    *reinterpret_cast<unsigned*>(L + off) =
        (unsigned)__bfloat16_as_ushort(l0) | ((unsigned)__bfloat16_as_ushort(l1) << 16);
}

// ------- split-bf16 dense layer, 8 warps, 3 accumulator sets (short chains) --
template <int NCH>
__device__ __forceinline__ void gemm_layer(const __nv_bfloat16* __restrict__ Wh,
                                           const __nv_bfloat16* __restrict__ Wl,
                                           const float* __restrict__ bias,
                                           const __nv_bfloat16* INh,
                                           const __nv_bfloat16* INl,
                                           __nv_bfloat16* OUTh, __nv_bfloat16* OUTl,
                                           __nv_bfloat16* const* SBh,
                                           __nv_bfloat16* const* SBl, int tid) {
    const int lane = tid & 31, w = tid >> 5;    // 8 warps
    const int g = lane >> 2, t = lane & 3;
    const int mrow = (w & 1) << 4;              // 0 or 16
    const int q = w >> 1;                        // 0..3 -> cols 64q..64q+63
    const int krow_l = (lane & 7) + ((lane >> 3) & 1) * 8;
    const int nc_l = (lane >> 4) * 8;

    // 8 m16n8 tiles per warp, 3 independent accumulator sets (hh, hl, lh)
    float aHH[8][4], aHL[8][4], aLH[8][4];
#pragma unroll
    for (int i = 0; i < 8; ++i)
#pragma unroll
        for (int j = 0; j < 4; ++j) { aHH[i][j] = 0.f; aHL[i][j] = 0.f; aLH[i][j] = 0.f; }

    __syncthreads();                 // prev layer's smem use complete
    stage_w(SBh[0], SBl[0], Wh, Wl, tid);
    CP_COMMIT();

#pragma unroll 1
    for (int c = 0; c < NCH; ++c) {
        if (c + 1 < NCH) {
            int nb = (c + 1) % 3;
            stage_w(SBh[nb], SBl[nb],
                    Wh + (c + 1) * 32 * 256, Wl + (c + 1) * 32 * 256, tid);
            CP_COMMIT(); CP_WAIT(1);
        } else {
            CP_WAIT(0);
        }
        __syncthreads();
        const __nv_bfloat16* swh = SBh[c % 3];
        const __nv_bfloat16* swl = SBl[c % 3];
#pragma unroll
        for (int kk = 0; kk < 2; ++kk) {
            const int kg = c * 32 + kk * 16;
            const __nv_bfloat16* ah_p = INh + (mrow + g) * AS + kg + 2 * t;
            const __nv_bfloat16* al_p = INl + (mrow + g) * AS + kg + 2 * t;
            unsigned ah[4], al[4];
            ah[0] = *reinterpret_cast<const unsigned*>(ah_p);
            ah[1] = *reinterpret_cast<const unsigned*>(ah_p + 8 * AS);
            ah[2] = *reinterpret_cast<const unsigned*>(ah_p + 8);
            ah[3] = *reinterpret_cast<const unsigned*>(ah_p + 8 * AS + 8);
            al[0] = *reinterpret_cast<const unsigned*>(al_p);
            al[1] = *reinterpret_cast<const unsigned*>(al_p + 8 * AS);
            al[2] = *reinterpret_cast<const unsigned*>(al_p + 8);
            al[3] = *reinterpret_cast<const unsigned*>(al_p + 8 * AS + 8);
            const int krow = kk * 16 + krow_l;
#pragma unroll
            for (int p = 0; p < 4; ++p) {
                const int ncol = (q << 6) + (p << 4) + nc_l;
                unsigned bh[4], bl[4];
                ldsm4t(bh, swh + krow * WS + ncol);
                ldsm4t(bl, swl + krow * WS + ncol);
                // three INDEPENDENT chains per tile
                mma_bf16(aHH[2 * p],     ah, bh[0], bh[1]);
                mma_bf16(aHL[2 * p],     ah, bl[0], bl[1]);
                mma_bf16(aLH[2 * p],     al, bh[0], bh[1]);
                mma_bf16(aHH[2 * p + 1], ah, bh[2], bh[3]);
                mma_bf16(aHL[2 * p + 1], ah, bl[2], bl[3]);
                mma_bf16(aLH[2 * p + 1], al, bh[2], bh[3]);
            }
        }
    }

    // epilogue: merge terms + bias + mish, split-store
#pragma unroll
    for (int nt = 0; nt < 8; ++nt) {
        const int col = (q << 6) + (nt << 3) + 2 * t;
        float b0v = bias[col], b1v = bias[col + 1];
        float v00 = mish_f(aHH[nt][0] + aHL[nt][0] + aLH[nt][0] + b0v);
        float v01 = mish_f(aHH[nt][1] + aHL[nt][1] + aLH[nt][1] + b1v);
        float v10 = mish_f(aHH[nt][2] + aHL[nt][2] + aLH[nt][2] + b0v);
        float v11 = mish_f(aHH[nt][3] + aHL[nt][3] + aLH[nt][3] + b1v);
        store_split2(OUTh, OUTl, (mrow + g) * AS + col, v00, v01);
        store_split2(OUTh, OUTl, (mrow + g + 8) * AS + col, v10, v11);
    }
}

// ---------------- init: split fp32 weights -> global bf16 hi/lo --------------
__global__ void split_weights(const float* __restrict__ w0,
                              const float* __restrict__ w1,
                              const float* __restrict__ w2) {
    int idx = blockIdx.x * blockDim.x + threadIdx.x;
    if (idx >= W_TOT) return;
    float v;
    if (idx < W1_OFF) {
        int k = idx >> 8, n = idx & 255;
        v = (k < 176) ? w0[k * 256 + n] : 0.f;
    } else if (idx < W2_OFF) {
        v = w1[idx - W1_OFF];
    } else {
        v = w2[idx - W2_OFF];
    }
    __nv_bfloat16 hi = __float2bfloat16(v);
    __nv_bfloat16 lo = __float2bfloat16(v - __bfloat162float(hi));
    g_whi[idx] = hi;
    g_wlo[idx] = lo;
}

// ---------------- persistent sampler -----------------------------------------
__global__ void __launch_bounds__(NT, 1)
diff_all(const float* __restrict__ state, const float* __restrict__ x_init,
         const float* __restrict__ w_t1, const float* __restrict__ b_t1,
         const float* __restrict__ w_t2, const float* __restrict__ b_t2,
         const float* __restrict__ b0,  const float* __restrict__ b1,
         const float* __restrict__ b2,
         const float* __restrict__ wf,  const float* __restrict__ bf,
         float* __restrict__ outp)
{
    extern __shared__ char smraw[];
    float* smf = reinterpret_cast<float*>(smraw);
    __nv_bfloat16* smb = reinterpret_cast<__nv_bfloat16*>(smraw);

    float* SWF = smf + F_SWF;
    float* XS  = smf + F_XS;
    float* TE  = smf + F_TE;
    float* HT  = smf + F_HT;
    float* TF  = smf + F_TF;
    float* CF  = smf + F_CF;
    unsigned* CFu = reinterpret_cast<unsigned*>(CF);

    __nv_bfloat16* A0h = smb + B_A0H;  __nv_bfloat16* A0l = smb + B_A0L;
    __nv_bfloat16* A1h = smb + B_A1H;  __nv_bfloat16* A1l = smb + B_A1L;
    __nv_bfloat16* SBh[3] = { smb + B_SW0H, smb + B_SW1H, smb + B_SW2H };
    __nv_bfloat16* SBl[3] = { smb + B_SW0L, smb + B_SW1L, smb + B_SW2L };

    const int tid = threadIdx.x;
    const int r0  = blockIdx.x * BR;

    // ---- one-time staging
    for (int idx = tid; idx < BR * 32; idx += NT) {
        int r = idx >> 5, c = idx & 31;
        XS[r * 33 + c] = x_init[(r0 + r) * 32 + c];
    }
    for (int idx = tid; idx < 256 * 32; idx += NT) SWF[idx] = wf[idx];
    __syncthreads();

#pragma unroll 1
    for (int i = 999; i >= 0; --i) {
        if (tid == 0) {
            double nn    = (double)(i + 1);
            double ac    = exp(-1e-4 * nn - 4.95e-6 * nn * nn);
            double nm    = nn - 1.0;
            double acp   = (i == 0) ? 1.0 : exp(-1e-4 * nm - 4.95e-6 * nm * nm);
            double beta  = 1.0 - exp(-1e-4 - 4.95e-6 * (2.0 * nn - 1.0));
            double alpha = 1.0 - beta;
            CF[0] = (float)sqrt(1.0 / ac);
            CF[1] = (float)sqrt(1.0 / ac - 1.0);
            CF[2] = (float)(beta * sqrt(acp) / (1.0 - ac));
            CF[3] = (float)((1.0 - acp) * sqrt(alpha) / (1.0 - ac));
            double pv = beta * (1.0 - acp) / (1.0 - ac);
            if (pv < 1e-20) pv = 1e-20;
            float lv = (float)log(pv);
            CF[4] = (float)exp((double)(0.5f * lv));
            unsigned a0 = 0u, a1 = (unsigned)i;
            threefry2x32(0u, 1u, a0, a1);
            CFu[5] = a0; CFu[6] = a1;
        }
        if (tid < 8) {
            float c8   = (float)(-9.210340371976184 / 7.0);
            float freq = expf(c8 * (float)tid);
            float ang  = (float)i * freq;
            TE[tid]     = (float)sin((double)ang);
            TE[tid + 8] = (float)cos((double)ang);
        }
        __syncthreads();
        if (tid < 32) {
            float h = b_t1[tid];
#pragma unroll
            for (int k = 0; k < 16; ++k) h = fmaf(TE[k], w_t1[k * 32 + tid], h);
            HT[tid] = mish_f(h);
        }
        __syncthreads();
        if (tid < 16) {
            float v = b_t2[tid];
#pragma unroll
            for (int k = 0; k < 32; ++k) v = fmaf(HT[k], w_t2[k * 16 + tid], v);
            TF[tid] = v;
        }
        __syncthreads();

        // ---- rebuild A0 (aliased by layer-2 output last step)
        for (int idx = tid; idx < 32 * 48; idx += NT) {
            int r = idx & 31, c = idx >> 5;
            float v = (c < 32) ? XS[r * 33 + c] : TF[c - 32];
            __nv_bfloat16 hi = __float2bfloat16(v);
            __nv_bfloat16 lo = __float2bfloat16(v - __bfloat162float(hi));
            A0h[r * AS + c] = hi;
            A0l[r * AS + c] = lo;
        }
        for (int idx = tid; idx < 32 * 128; idx += NT) {
            int r = idx >> 7, c = idx & 127;
            float v = state[(r0 + r) * 128 + c];
            __nv_bfloat16 hi = __float2bfloat16(v);
            __nv_bfloat16 lo = __float2bfloat16(v - __bfloat162float(hi));
            A0h[r * AS + 48 + c] = hi;
            A0l[r * AS + 48 + c] = lo;
        }
        for (int idx = tid; idx < 32 * 16; idx += NT) {
            int r = idx >> 4, c = idx & 15;
            __nv_bfloat16 z = __float2bfloat16(0.f);
            A0h[r * AS + 176 + c] = z;
            A0l[r * AS + 176 + c] = z;
        }

        gemm_layer<6>(g_whi + W0_OFF, g_wlo + W0_OFF, b0, A0h, A0l,
                      A1h, A1l, SBh, SBl, tid);
        gemm_layer<8>(g_whi + W1_OFF, g_wlo + W1_OFF, b1, A1h, A1l,
                      A0h, A0l, SBh, SBl, tid);            // A2 := A0 space
        gemm_layer<8>(g_whi + W2_OFF, g_wlo + W2_OFF, b2, A0h, A0l,
                      A1h, A1l, SBh, SBl, tid);
        __syncthreads();

        // ---- final 256 -> 32 (exact fp32): row = tid>>3, 4 cols; 2 partials
        const int row = tid >> 3;
        const int cg  = tid & 7;
        unsigned long long f0a = 0ull, f1a = 0ull, f0b = 0ull, f1b = 0ull;
        const __nv_bfloat16* inh = A1h + row * AS;
        const __nv_bfloat16* inl = A1l + row * AS;
#pragma unroll 4
        for (int k2 = 0; k2 < 256; k2 += 2) {
            __nv_bfloat162 ph = *reinterpret_cast<const __nv_bfloat162*>(inh + k2);
            __nv_bfloat162 pl = *reinterpret_cast<const __nv_bfloat162*>(inl + k2);
            float a0 = __bfloat162float(ph.x) + __bfloat162float(pl.x);
            float a1 = __bfloat162float(ph.y) + __bfloat162float(pl.y);
            {
                const float* wp = SWF + (k2 << 5) + (cg << 2);
                unsigned long long w01 = *reinterpret_cast<const unsigned long long*>(wp);
                unsigned long long w23 = *reinterpret_cast<const unsigned long long*>(wp + 2);
                unsigned long long aa; PACK_DUP(aa, a0);
                FMA2(f0a, aa, w01); FMA2(f1a, aa, w23);
            }
            {
                const float* wp = SWF + ((k2 + 1) << 5) + (cg << 2);
                unsigned long long w01 = *reinterpret_cast<const unsigned long long*>(wp);
                unsigned long long w23 = *reinterpret_cast<const unsigned long long*>(wp + 2);
                unsigned long long aa; PACK_DUP(aa, a1);
                FMA2(f0b, aa, w01); FMA2(f1b, aa, w23);
            }
        }
        float4 bb = *reinterpret_cast<const float4*>(bf + (cg << 2));
        float e0a, e1a, e2a, e3a, e0b, e1b, e2b, e3b;
        UNPACK2(e0a, e1a, f0a); UNPACK2(e2a, e3a, f1a);
        UNPACK2(e0b, e1b, f0b); UNPACK2(e2b, e3b, f1b);
        float eps[4] = { e0a + e0b + bb.x, e1a + e1b + bb.y,
                         e2a + e2b + bb.z, e3a + e3b + bb.w };

        float sr = CF[0], srm1 = CF[1], c1 = CF[2], c2 = CF[3], sig = CF[4];
        unsigned fk0 = CFu[5], fk1 = CFu[6];

        const int R = r0 + row;
#pragma unroll
        for (int cc = 0; cc < 4; ++cc) {
            int   j  = (cg << 2) + cc;
            float xv = XS[row * 33 + j];
            float x0 = fminf(1.f, fmaxf(-1.f, sr * xv - srm1 * eps[cc]));
            float mean = c1 * x0 + c2 * xv;
            if (i != 0) {
                unsigned f = (unsigned)(R * 32 + j);
                unsigned b0r = 0u, b1r = f;
                threefry2x32(fk0, fk1, b0r, b1r);
                unsigned bits = b0r ^ b1r;
                float fv = __uint_as_float((bits >> 9) | 0x3f800000u) - 1.0f;
                const float lo = -0.99999994f;
                float u   = fmaxf(lo, fmaf(fv, 2.0f, lo));
                float nrm = 1.4142135623730951f * erfinv_xla(u);
                XS[row * 33 + j] = mean + sig * nrm;
            } else {
                float xf = fminf(1.f, fmaxf(-1.f, mean));
                XS[row * 33 + j] = xf;
                outp[R * 32 + j] = xf;
            }
        }
        __syncthreads();
    }
}

extern "C" void kernel_launch(void* const* d_in, const int* in_sizes, int n_in,
                              void* d_out, int out_size) {
    const float* state = (const float*)d_in[0];
    const float* xinit = (const float*)d_in[1];
    const float* w_t1  = (const float*)d_in[2];
    const float* b_t1  = (const float*)d_in[3];
    const float* w_t2  = (const float*)d_in[4];
    const float* b_t2  = (const float*)d_in[5];
    const float* w0    = (const float*)d_in[6];
    const float* b0    = (const float*)d_in[7];
    const float* w1    = (const float*)d_in[8];
    const float* b1    = (const float*)d_in[9];
    const float* w2    = (const float*)d_in[10];
    const float* b2    = (const float*)d_in[11];
    const float* wf    = (const float*)d_in[12];
    const float* bf    = (const float*)d_in[13];
    float* outp = (float*)d_out;

    cudaFuncSetAttribute(diff_all, cudaFuncAttributeMaxDynamicSharedMemorySize, SMEM_BYTES);

    split_weights<<<(W_TOT + 255) / 256, 256>>>(w0, w1, w2);
    diff_all<<<NB, NT, SMEM_BYTES>>>(state, xinit,
        w_t1, b_t1, w_t2, b_t2,
        b0, b1, b2, wf, bf, outp);
}

// round 10
// speedup vs baseline: 1.2643x; 1.2643x over previous
#include <cuda_runtime.h>
#include <cuda_bf16.h>
#include <math.h>

#define NB 128
#define NT 512
#define BR 32
#define AS  264     // activation row stride (bf16 units) = 528B (conflict-free LDS)

// ---- smem layout ----
// floats
#define F_SWF 0                    // 256*32 fp32 final weights
#define F_XS  8192                 // 32*33
#define F_TE  9248
#define F_HT  9264
#define F_TF  9296
#define F_CF  9312                 // end 9328 floats = 37312 B
// mbarriers at byte 37312 (3 x 8B), pad to 37376
#define MBAR_BYTE 37312
// bf16 activations from byte 37376 = unit 18688
#define B_A0H 18688
#define B_A0L 27136
#define B_A1H 35584
#define B_A1L 44032                // ends unit 52480 = byte 104960
// weight ring: 3 x 32KB from byte 104960
#define WB_BYTE 104960
#define WB_UNIT 52480              // bf16 unit offset
#define SMEM_BYTES (104960 + 3*32768)

// pre-split weights: per 32-row chunk: 16KB hi then 16KB lo, XOR-swizzled.
// chunk count: layer0 6 (k padded to 192), layer1 8, layer2 8 = 22
#define NCHUNK_TOT 22
#define W_ELEMS (NCHUNK_TOT * 16384)
__device__ __align__(128) __nv_bfloat16 g_w[W_ELEMS];

// ---- packed f32x2 helpers (final layer) ------------------------------------
#define FMA2(acc, aa, bb) \
    asm("fma.rn.f32x2 %0, %1, %2, %0;" : "+l"(acc) : "l"(aa), "l"(bb))
#define PACK_DUP(dst, fv) do { \
    unsigned _pi = __float_as_uint(fv); \
    asm("mov.b64 %0, {%1, %1};" : "=l"(dst) : "r"(_pi)); } while (0)
#define UNPACK2(lo, hi, src) do { \
    unsigned _u0, _u1; \
    asm("mov.b64 {%0, %1}, %2;" : "=r"(_u0), "=r"(_u1) : "l"(src)); \
    lo = __uint_as_float(_u0); hi = __uint_as_float(_u1); } while (0)

// ---------------- threefry2x32-20 (exact JAX) ------------------------------
__device__ __forceinline__ unsigned rotl32(unsigned x, int r) {
    return __funnelshift_l(x, x, r);
}
__device__ __forceinline__ void threefry2x32(unsigned k0, unsigned k1,
                                             unsigned &x0, unsigned &x1) {
    unsigned k2 = k0 ^ k1 ^ 0x1BD11BDAu;
#define TFR(r) { x0 += x1; x1 = rotl32(x1, r); x1 ^= x0; }
    x0 += k0; x1 += k1;
    TFR(13) TFR(15) TFR(26) TFR(6)
    x0 += k1; x1 += k2 + 1u;
    TFR(17) TFR(29) TFR(16) TFR(24)
    x0 += k2; x1 += k0 + 2u;
    TFR(13) TFR(15) TFR(26) TFR(6)
    x0 += k0; x1 += k1 + 3u;
    TFR(17) TFR(29) TFR(16) TFR(24)
    x0 += k1; x1 += k2 + 4u;
    TFR(13) TFR(15) TFR(26) TFR(6)
    x0 += k2; x1 += k0 + 5u;
#undef TFR
}

// ---------------- XLA ErfInv f32 (Giles) ------------------------------------
__device__ __forceinline__ float erfinv_xla(float x) {
    float w = -log1pf(-x * x);
    float p;
    if (w < 5.0f) {
        w -= 2.5f;
        p = 2.81022636e-08f;
        p = fmaf(p, w, 3.43273939e-07f);
        p = fmaf(p, w, -3.5233877e-06f);
        p = fmaf(p, w, -4.39150654e-06f);
        p = fmaf(p, w, 0.00021858087f);
        p = fmaf(p, w, -0.00125372503f);
        p = fmaf(p, w, -0.00417768164f);
        p = fmaf(p, w, 0.246640727f);
        p = fmaf(p, w, 1.50140941f);
    } else {
        w = sqrtf(w) - 3.0f;
        p = -0.000200214257f;
        p = fmaf(p, w, 0.000100950558f);
        p = fmaf(p, w, 0.00134934322f);
        p = fmaf(p, w, -0.00367342844f);
        p = fmaf(p, w, 0.00573950773f);
        p = fmaf(p, w, -0.0076224613f);
        p = fmaf(p, w, 0.00943887047f);
        p = fmaf(p, w, 1.00167406f);
        p = fmaf(p, w, 2.83297682f);
    }
    return p * x;
}

__device__ __forceinline__ float mish_f(float x) {
    if (x > 20.0f) return x;
    float u = expf(x);
    float s = u * (u + 2.0f);
    return x * (s / (s + 2.0f));
}

// ---------------- mbarrier + bulk-copy helpers --------------------------------
#define MBAR_INIT(addr, cnt) \
    asm volatile("mbarrier.init.shared.b64 [%0], %1;" :: "r"(addr), "r"(cnt) : "memory")
#define MBAR_EXPECT_TX(addr, bytes) \
    asm volatile("mbarrier.arrive.expect_tx.shared.b64 _, [%0], %1;" :: "r"(addr), "r"(bytes) : "memory")
#define MBAR_WAIT(addr, parity) do { \
    unsigned _done = 0; \
    while (!_done) { \
        asm volatile("{\n\t.reg .pred p;\n\t" \
            "mbarrier.try_wait.parity.acquire.cta.shared::cta.b64 p, [%1], %2, 0x989680;\n\t" \
            "selp.b32 %0, 1, 0, p;\n\t}" \
            : "=r"(_done) : "r"(addr), "r"(parity) : "memory"); \
    } } while (0)

__device__ __forceinline__ void bulk_stage(unsigned dst_smem,
                                           const __nv_bfloat16* src,
                                           unsigned mbar) {
    asm volatile(
        "cp.async.bulk.shared::cluster.global.mbarrier::complete_tx::bytes "
        "[%0], [%1], %2, [%3];"
        :: "r"(dst_smem), "l"(src), "r"(32768u), "r"(mbar) : "memory");
}

// ---------------- mma / ldmatrix wrappers ------------------------------------
__device__ __forceinline__ void mma_bf16(float* c, const unsigned* a,
                                         unsigned b0, unsigned b1) {
    asm volatile(
        "mma.sync.aligned.m16n8k16.row.col.f32.bf16.bf16.f32 "
        "{%0,%1,%2,%3}, {%4,%5,%6,%7}, {%8,%9}, {%0,%1,%2,%3};"
        : "+f"(c[0]), "+f"(c[1]), "+f"(c[2]), "+f"(c[3])
        : "r"(a[0]), "r"(a[1]), "r"(a[2]), "r"(a[3]), "r"(b0), "r"(b1));
}
__device__ __forceinline__ void ldsm4t(unsigned* r, const __nv_bfloat16* p) {
    unsigned addr = (unsigned)__cvta_generic_to_shared(p);
    asm volatile("ldmatrix.sync.aligned.m8n8.x4.trans.shared.b16 {%0,%1,%2,%3}, [%4];"
        : "=r"(r[0]), "=r"(r[1]), "=r"(r[2]), "=r"(r[3]) : "r"(addr));
}

__device__ __forceinline__ void store_split2(__nv_bfloat16* H, __nv_bfloat16* L,
                                             int off, float v0, float v1) {
    __nv_bfloat16 h0 = __float2bfloat16(v0), h1 = __float2bfloat16(v1);
    __nv_bfloat16 l0 = __float2bfloat16(v0 - __bfloat162float(h0));
    __nv_bfloat16 l1 = __float2bfloat16(v1 - __bfloat162float(h1));
    *reinterpret_cast<unsigned*>(H + off) =
        (unsigned)__bfloat16_as_ushort(h0) | ((unsigned)__bfloat16_as_ushort(h1) << 16);
    *reinterpret_cast<unsigned*>(L + off) =
        (unsigned)__bfloat16_as_ushort(l0) | ((unsigned)__bfloat16_as_ushort(l1) << 16);
}

// ------- split-bf16 dense layer, 16 warps, bulk-staged ring ------------------
// One cp.async.bulk per 32KB chunk; 3-buffer ring; 1 __syncthreads per chunk.
template <int NCH>
__device__ __forceinline__ void gemm_layer(const __nv_bfloat16* __restrict__ Wsrc,
                                           const float* __restrict__ bias,
                                           const __nv_bfloat16* INh,
                                           const __nv_bfloat16* INl,
                                           __nv_bfloat16* OUTh, __nv_bfloat16* OUTl,
                                           __nv_bfloat16* smb, unsigned smem_u32,
                                           int& gc, unsigned& phbits, int tid) {
    const int lane = tid & 31, w = tid >> 5;    // 16 warps
    const int g = lane >> 2, t = lane & 3;
    const int mrow = (w & 1) << 4;              // 0 or 16
    const int q = w >> 1;                        // 0..7 -> cols 32q..32q+31
    const int krow_l = (lane & 7) + ((lane >> 3) & 1) * 8;
    const int nc_l = (lane >> 4) * 8;

    float acc[4][4];
#pragma unroll
    for (int i = 0; i < 4; ++i)
#pragma unroll
        for (int j = 0; j < 4; ++j) acc[i][j] = 0.f;

    __syncthreads();                 // prev layer's smem use complete
    if (tid == 0) {
        int b = gc % 3;
        unsigned mb = smem_u32 + MBAR_BYTE + 8u * b;
        MBAR_EXPECT_TX(mb, 32768u);
        bulk_stage(smem_u32 + WB_BYTE + 32768u * b, Wsrc, mb);
    }

#pragma unroll 1
    for (int c = 0; c < NCH; ++c) {
        if (c + 1 < NCH && tid == 0) {
            int nb = (gc + c + 1) % 3;
            unsigned mb = smem_u32 + MBAR_BYTE + 8u * nb;
            MBAR_EXPECT_TX(mb, 32768u);
            bulk_stage(smem_u32 + WB_BYTE + 32768u * nb, Wsrc + (c + 1) * 16384, mb);
        }
        int cb = (gc + c) % 3;
        MBAR_WAIT(smem_u32 + MBAR_BYTE + 8u * cb, (phbits >> cb) & 1u);
        phbits ^= (1u << cb);
        __syncthreads();
        const __nv_bfloat16* swh = smb + WB_UNIT + cb * 16384;   // hi half
        const __nv_bfloat16* swl = swh + 8192;                    // lo half
#pragma unroll
        for (int kk = 0; kk < 2; ++kk) {
            const int kg = c * 32 + kk * 16;
            const __nv_bfloat16* ah_p = INh + (mrow + g) * AS + kg + 2 * t;
            const __nv_bfloat16* al_p = INl + (mrow + g) * AS + kg + 2 * t;
            unsigned ah[4], al[4];
            ah[0] = *reinterpret_cast<const unsigned*>(ah_p);
            ah[1] = *reinterpret_cast<const unsigned*>(ah_p + 8 * AS);
            ah[2] = *reinterpret_cast<const unsigned*>(ah_p + 8);
            ah[3] = *reinterpret_cast<const unsigned*>(ah_p + 8 * AS + 8);
            al[0] = *reinterpret_cast<const unsigned*>(al_p);
            al[1] = *reinterpret_cast<const unsigned*>(al_p + 8 * AS);
            al[2] = *reinterpret_cast<const unsigned*>(al_p + 8);
            al[3] = *reinterpret_cast<const unsigned*>(al_p + 8 * AS + 8);
            const int krow = kk * 16 + krow_l;
            const int swz = (krow & 7);
            const int rbase = krow * 256;
#pragma unroll
            for (int p = 0; p < 2; ++p) {
                const int ncol = (q << 5) + (p << 4) + nc_l;
                const int off = rbase + ((((ncol >> 3) ^ swz)) << 3);
                unsigned bh[4], bl[4];
                ldsm4t(bh, swh + off);
                ldsm4t(bl, swl + off);
                mma_bf16(acc[2 * p],     ah, bh[0], bh[1]);
                mma_bf16(acc[2 * p],     ah, bl[0], bl[1]);
                mma_bf16(acc[2 * p],     al, bh[0], bh[1]);
                mma_bf16(acc[2 * p + 1], ah, bh[2], bh[3]);
                mma_bf16(acc[2 * p + 1], ah, bl[2], bl[3]);
                mma_bf16(acc[2 * p + 1], al, bh[2], bh[3]);
            }
        }
    }
    gc += NCH;

    // epilogue: bias + mish, split-store (next layer entry-syncs)
#pragma unroll
    for (int nt = 0; nt < 4; ++nt) {
        const int col = (q << 5) + (nt << 3) + 2 * t;
        float b0v = bias[col], b1v = bias[col + 1];
        float v00 = mish_f(acc[nt][0] + b0v);
        float v01 = mish_f(acc[nt][1] + b1v);
        float v10 = mish_f(acc[nt][2] + b0v);
        float v11 = mish_f(acc[nt][3] + b1v);
        store_split2(OUTh, OUTl, (mrow + g) * AS + col, v00, v01);
        store_split2(OUTh, OUTl, (mrow + g + 8) * AS + col, v10, v11);
    }
}

// ------- init: split fp32 weights -> swizzled interleaved bf16 hi/lo chunks --
__global__ void split_weights(const float* __restrict__ w0,
                              const float* __restrict__ w1,
                              const float* __restrict__ w2) {
    int idx = blockIdx.x * blockDim.x + threadIdx.x;   // over 22*8192 hi elems
    if (idx >= NCHUNK_TOT * 8192) return;
    int gch = idx >> 13;           // global chunk 0..21
    int r   = (idx >> 8) & 31;     // row in chunk
    int n   = idx & 255;           // col
    float v;
    if (gch < 6) {
        int k = gch * 32 + r;
        v = (k < 176) ? w0[k * 256 + n] : 0.f;
    } else if (gch < 14) {
        int k = (gch - 6) * 32 + r;
        v = w1[k * 256 + n];
    } else {
        int k = (gch - 14) * 32 + r;
        v = w2[k * 256 + n];
    }
    __nv_bfloat16 hi = __float2bfloat16(v);
    __nv_bfloat16 lo = __float2bfloat16(v - __bfloat162float(hi));
    int pos = gch * 16384 + r * 256 + (((n >> 3) ^ (r & 7)) << 3) + (n & 7);
    g_w[pos] = hi;
    g_w[pos + 8192] = lo;
}

// ---------------- persistent sampler -----------------------------------------
__global__ void __launch_bounds__(NT, 1)
diff_all(const float* __restrict__ state, const float* __restrict__ x_init,
         const float* __restrict__ w_t1, const float* __restrict__ b_t1,
         const float* __restrict__ w_t2, const float* __restrict__ b_t2,
         const float* __restrict__ b0,  const float* __restrict__ b1,
         const float* __restrict__ b2,
         const float* __restrict__ wf,  const float* __restrict__ bf,
         float* __restrict__ outp)
{
    extern __shared__ __align__(16) char smraw[];
    float* smf = reinterpret_cast<float*>(smraw);
    __nv_bfloat16* smb = reinterpret_cast<__nv_bfloat16*>(smraw);
    unsigned smem_u32 = (unsigned)__cvta_generic_to_shared(smraw);

    float* SWF = smf + F_SWF;
    float* XS  = smf + F_XS;
    float* TE  = smf + F_TE;
    float* HT  = smf + F_HT;
    float* TF  = smf + F_TF;
    float* CF  = smf + F_CF;
    unsigned* CFu = reinterpret_cast<unsigned*>(CF);

    __nv_bfloat16* A0h = smb + B_A0H;  __nv_bfloat16* A0l = smb + B_A0L;
    __nv_bfloat16* A1h = smb + B_A1H;  __nv_bfloat16* A1l = smb + B_A1L;

    const int tid = threadIdx.x;
    const int r0  = blockIdx.x * BR;

    // ---- one-time init: mbarriers, x, final weights
    if (tid == 0) {
#pragma unroll
        for (int b = 0; b < 3; ++b) MBAR_INIT(smem_u32 + MBAR_BYTE + 8u * b, 1u);
    }
    for (int idx = tid; idx < BR * 32; idx += NT) {
        int r = idx >> 5, c = idx & 31;
        XS[r * 33 + c] = x_init[(r0 + r) * 32 + c];
    }
    for (int idx = tid; idx < 256 * 32; idx += NT) SWF[idx] = wf[idx];
    __syncthreads();

    int gc = 0;
    unsigned phbits = 0;

#pragma unroll 1
    for (int i = 999; i >= 0; --i) {
        if (tid == 0) {
            double nn    = (double)(i + 1);
            double ac    = exp(-1e-4 * nn - 4.95e-6 * nn * nn);
            double nm    = nn - 1.0;
            double acp   = (i == 0) ? 1.0 : exp(-1e-4 * nm - 4.95e-6 * nm * nm);
            double beta  = 1.0 - exp(-1e-4 - 4.95e-6 * (2.0 * nn - 1.0));
            double alpha = 1.0 - beta;
            CF[0] = (float)sqrt(1.0 / ac);
            CF[1] = (float)sqrt(1.0 / ac - 1.0);
            CF[2] = (float)(beta * sqrt(acp) / (1.0 - ac));
            CF[3] = (float)((1.0 - acp) * sqrt(alpha) / (1.0 - ac));
            double pv = beta * (1.0 - acp) / (1.0 - ac);
            if (pv < 1e-20) pv = 1e-20;
            float lv = (float)log(pv);
            CF[4] = (float)exp((double)(0.5f * lv));
            unsigned a0 = 0u, a1 = (unsigned)i;
            threefry2x32(0u, 1u, a0, a1);
            CFu[5] = a0; CFu[6] = a1;
        }
        if (tid < 8) {
            float c8   = (float)(-9.210340371976184 / 7.0);
            float freq = expf(c8 * (float)tid);
            float ang  = (float)i * freq;
            TE[tid]     = (float)sin((double)ang);
            TE[tid + 8] = (float)cos((double)ang);
        }
        __syncthreads();
        if (tid < 32) {
            float h = b_t1[tid];
#pragma unroll
            for (int k = 0; k < 16; ++k) h = fmaf(TE[k], w_t1[k * 32 + tid], h);
            HT[tid] = mish_f(h);
        }
        __syncthreads();
        if (tid < 16) {
            float v = b_t2[tid];
#pragma unroll
            for (int k = 0; k < 32; ++k) v = fmaf(HT[k], w_t2[k * 16 + tid], v);
            TF[tid] = v;
        }
        __syncthreads();

        // ---- rebuild A0 (aliased by layer-2 output last step)
        for (int idx = tid; idx < 32 * 48; idx += NT) {
            int r = idx & 31, c = idx >> 5;
            float v = (c < 32) ? XS[r * 33 + c] : TF[c - 32];
            __nv_bfloat16 hi = __float2bfloat16(v);
            __nv_bfloat16 lo = __float2bfloat16(v - __bfloat162float(hi));
            A0h[r * AS + c] = hi;
            A0l[r * AS + c] = lo;
        }
        for (int idx = tid; idx < 32 * 128; idx += NT) {
            int r = idx >> 7, c = idx & 127;
            float v = state[(r0 + r) * 128 + c];
            __nv_bfloat16 hi = __float2bfloat16(v);
            __nv_bfloat16 lo = __float2bfloat16(v - __bfloat162float(hi));
            A0h[r * AS + 48 + c] = hi;
            A0l[r * AS + 48 + c] = lo;
        }
        for (int idx = tid; idx < 32 * 16; idx += NT) {
            int r = idx >> 4, c = idx & 15;
            __nv_bfloat16 z = __float2bfloat16(0.f);
            A0h[r * AS + 176 + c] = z;
            A0l[r * AS + 176 + c] = z;
        }

        gemm_layer<6>(g_w,              b0, A0h, A0l, A1h, A1l, smb, smem_u32, gc, phbits, tid);
        gemm_layer<8>(g_w + 6  * 16384, b1, A1h, A1l, A0h, A0l, smb, smem_u32, gc, phbits, tid);
        gemm_layer<8>(g_w + 14 * 16384, b2, A0h, A0l, A1h, A1l, smb, smem_u32, gc, phbits, tid);
        __syncthreads();

        // ---- final 256 -> 32 (exact fp32): row = tid>>4, 2 cols at (tid&15)*2
        const int row = tid >> 4;
        const int cp  = tid & 15;
        unsigned long long f0 = 0ull;
        const __nv_bfloat16* inh = A1h + row * AS;
        const __nv_bfloat16* inl = A1l + row * AS;
#pragma unroll 4
        for (int k2 = 0; k2 < 256; k2 += 2) {
            __nv_bfloat162 ph = *reinterpret_cast<const __nv_bfloat162*>(inh + k2);
            __nv_bfloat162 pl = *reinterpret_cast<const __nv_bfloat162*>(inl + k2);
            float a0 = __bfloat162float(ph.x) + __bfloat162float(pl.x);
            float a1 = __bfloat162float(ph.y) + __bfloat162float(pl.y);
#pragma unroll
            for (int kk = 0; kk < 2; ++kk) {
                float a = kk ? a1 : a0;
                const float* wp = SWF + ((k2 + kk) << 5) + (cp << 1);
                unsigned long long w01 = *reinterpret_cast<const unsigned long long*>(wp);
                unsigned long long aa;
                PACK_DUP(aa, a);
                FMA2(f0, aa, w01);
            }
        }
        float e0, e1;
        UNPACK2(e0, e1, f0);
        float eps[2] = { e0 + bf[cp * 2], e1 + bf[cp * 2 + 1] };

        float sr = CF[0], srm1 = CF[1], c1 = CF[2], c2 = CF[3], sig = CF[4];
        unsigned fk0 = CFu[5], fk1 = CFu[6];

        const int R = r0 + row;
#pragma unroll
        for (int cc = 0; cc < 2; ++cc) {
            int   j  = (cp << 1) + cc;
            float xv = XS[row * 33 + j];
            float x0 = fminf(1.f, fmaxf(-1.f, sr * xv - srm1 * eps[cc]));
            float mean = c1 * x0 + c2 * xv;
            if (i != 0) {
                unsigned f = (unsigned)(R * 32 + j);
                unsigned b0r = 0u, b1r = f;
                threefry2x32(fk0, fk1, b0r, b1r);
                unsigned bits = b0r ^ b1r;
                float fv = __uint_as_float((bits >> 9) | 0x3f800000u) - 1.0f;
                const float lo = -0.99999994f;
                float u   = fmaxf(lo, fmaf(fv, 2.0f, lo));
                float nrm = 1.4142135623730951f * erfinv_xla(u);
                XS[row * 33 + j] = mean + sig * nrm;
            } else {
                float xf = fminf(1.f, fmaxf(-1.f, mean));
                XS[row * 33 + j] = xf;
                outp[R * 32 + j] = xf;
            }
        }
        __syncthreads();
    }
}

extern "C" void kernel_launch(void* const* d_in, const int* in_sizes, int n_in,
                              void* d_out, int out_size) {
    const float* state = (const float*)d_in[0];
    const float* xinit = (const float*)d_in[1];
    const float* w_t1  = (const float*)d_in[2];
    const float* b_t1  = (const float*)d_in[3];
    const float* w_t2  = (const float*)d_in[4];
    const float* b_t2  = (const float*)d_in[5];
    const float* w0    = (const float*)d_in[6];
    const float* b0    = (const float*)d_in[7];
    const float* w1    = (const float*)d_in[8];
    const float* b1    = (const float*)d_in[9];
    const float* w2    = (const float*)d_in[10];
    const float* b2    = (const float*)d_in[11];
    const float* wf    = (const float*)d_in[12];
    const float* bf    = (const float*)d_in[13];
    float* outp = (float*)d_out;

    cudaFuncSetAttribute(diff_all, cudaFuncAttributeMaxDynamicSharedMemorySize, SMEM_BYTES);

    split_weights<<<(NCHUNK_TOT * 8192 + 255) / 256, 256>>>(w0, w1, w2);
    diff_all<<<NB, NT, SMEM_BYTES>>>(state, xinit,
        w_t1, b_t1, w_t2, b_t2,
        b0, b1, b2, wf, bf, outp);
}

// round 11
// speedup vs baseline: 1.3039x; 1.0313x over previous
#include <cuda_runtime.h>
#include <cuda_bf16.h>
#include <math.h>

#define NB 128
#define NT 512
#define BR 32
#define AS  264     // activation row stride (bf16 units) = 528B (conflict-free LDS)

// ---- smem layout ----
// floats
#define F_SWF 0                    // 256*32 fp32 final weights
#define F_XS  8192                 // 32*33
#define F_TE  9248
#define F_HT  9264
#define F_TF  9296
#define F_CF  9312                 // end 9328 floats = 37312 B
// mbarriers at byte 37312 (3 x 8B)
#define MBAR_BYTE 37312
// bf16 activations from byte 37376 = unit 18688
#define B_A0H 18688
#define B_A0L 27136
#define B_A1H 35584
#define B_A1L 44032                // ends unit 52480 = byte 104960
// weight ring: 3 x 32KB from byte 104960
#define WB_BYTE 104960
#define WB_UNIT 52480
#define SMEM_BYTES (104960 + 3*32768)

// pre-split weights: per 32-row chunk: 16KB hi then 16KB lo, XOR-swizzled.
#define NCHUNK_TOT 22
#define W_ELEMS (NCHUNK_TOT * 16384)
__device__ __align__(128) __nv_bfloat16 g_w[W_ELEMS];

// ---- packed f32x2 helpers (final layer) ------------------------------------
#define FMA2(acc, aa, bb) \
    asm("fma.rn.f32x2 %0, %1, %2, %0;" : "+l"(acc) : "l"(aa), "l"(bb))
#define PACK_DUP(dst, fv) do { \
    unsigned _pi = __float_as_uint(fv); \
    asm("mov.b64 %0, {%1, %1};" : "=l"(dst) : "r"(_pi)); } while (0)
#define UNPACK2(lo, hi, src) do { \
    unsigned _u0, _u1; \
    asm("mov.b64 {%0, %1}, %2;" : "=r"(_u0), "=r"(_u1) : "l"(src)); \
    lo = __uint_as_float(_u0); hi = __uint_as_float(_u1); } while (0)

// ---------------- threefry2x32-20 (exact JAX) ------------------------------
__device__ __forceinline__ unsigned rotl32(unsigned x, int r) {
    return __funnelshift_l(x, x, r);
}
__device__ __forceinline__ void threefry2x32(unsigned k0, unsigned k1,
                                             unsigned &x0, unsigned &x1) {
    unsigned k2 = k0 ^ k1 ^ 0x1BD11BDAu;
#define TFR(r) { x0 += x1; x1 = rotl32(x1, r); x1 ^= x0; }
    x0 += k0; x1 += k1;
    TFR(13) TFR(15) TFR(26) TFR(6)
    x0 += k1; x1 += k2 + 1u;
    TFR(17) TFR(29) TFR(16) TFR(24)
    x0 += k2; x1 += k0 + 2u;
    TFR(13) TFR(15) TFR(26) TFR(6)
    x0 += k0; x1 += k1 + 3u;
    TFR(17) TFR(29) TFR(16) TFR(24)
    x0 += k1; x1 += k2 + 4u;
    TFR(13) TFR(15) TFR(26) TFR(6)
    x0 += k2; x1 += k0 + 5u;
#undef TFR
}

// ---------------- XLA ErfInv f32 (Giles) ------------------------------------
__device__ __forceinline__ float erfinv_xla(float x) {
    float w = -log1pf(-x * x);
    float p;
    if (w < 5.0f) {
        w -= 2.5f;
        p = 2.81022636e-08f;
        p = fmaf(p, w, 3.43273939e-07f);
        p = fmaf(p, w, -3.5233877e-06f);
        p = fmaf(p, w, -4.39150654e-06f);
        p = fmaf(p, w, 0.00021858087f);
        p = fmaf(p, w, -0.00125372503f);
        p = fmaf(p, w, -0.00417768164f);
        p = fmaf(p, w, 0.246640727f);
        p = fmaf(p, w, 1.50140941f);
    } else {
        w = sqrtf(w) - 3.0f;
        p = -0.000200214257f;
        p = fmaf(p, w, 0.000100950558f);
        p = fmaf(p, w, 0.00134934322f);
        p = fmaf(p, w, -0.00367342844f);
        p = fmaf(p, w, 0.00573950773f);
        p = fmaf(p, w, -0.0076224613f);
        p = fmaf(p, w, 0.00943887047f);
        p = fmaf(p, w, 1.00167406f);
        p = fmaf(p, w, 2.83297682f);
    }
    return p * x;
}

// ---------------- MUFU-free mish -------------------------------------------
// exp via exp2 range reduction + degree-6 Taylor (rel err ~1.2e-7), FMA pipe only
__device__ __forceinline__ float exp_fma(float x) {
    float y = x * 1.4426950408889634f;
    y = fmaxf(y, -120.0f);
    float n = rintf(y);
    float f = y - n;
    float p =       1.5403530393381609e-4f;
    p = fmaf(p, f, 1.3333558146428443e-3f);
    p = fmaf(p, f, 9.6181298420718030e-3f);
    p = fmaf(p, f, 5.5504108664821580e-2f);
    p = fmaf(p, f, 2.4022650695910070e-1f);
    p = fmaf(p, f, 6.9314718055994530e-1f);
    p = fmaf(p, f, 1.0f);
    int e = (int)n;
    return p * __int_as_float((e + 127) << 23);
}
// reciprocal via bit-trick seed + 3 Newton steps (rel err ~1e-7), FMA pipe only
__device__ __forceinline__ float rcp_fma(float d) {
    float r = __int_as_float(0x7EF311C3 - __float_as_int(d));
    r = r * fmaf(-d, r, 2.0f);
    r = r * fmaf(-d, r, 2.0f);
    r = r * fmaf(-d, r, 2.0f);
    return r;
}
__device__ __forceinline__ float mish_f(float x) {
    if (x > 20.0f) return x;
    float u = exp_fma(x);
    float s = u * (u + 2.0f);
    return x * s * rcp_fma(s + 2.0f);
}

// ---------------- mbarrier + bulk-copy helpers --------------------------------
#define MBAR_INIT(addr, cnt) \
    asm volatile("mbarrier.init.shared.b64 [%0], %1;" :: "r"(addr), "r"(cnt) : "memory")
#define MBAR_EXPECT_TX(addr, bytes) \
    asm volatile("mbarrier.arrive.expect_tx.shared.b64 _, [%0], %1;" :: "r"(addr), "r"(bytes) : "memory")
#define MBAR_WAIT(addr, parity) do { \
    unsigned _done = 0; \
    while (!_done) { \
        asm volatile("{\n\t.reg .pred p;\n\t" \
            "mbarrier.try_wait.parity.acquire.cta.shared::cta.b64 p, [%1], %2, 0x989680;\n\t" \
            "selp.b32 %0, 1, 0, p;\n\t}" \
            : "=r"(_done) : "r"(addr), "r"(parity) : "memory"); \
    } } while (0)

__device__ __forceinline__ void bulk_stage(unsigned dst_smem,
                                           const __nv_bfloat16* src,
                                           unsigned mbar) {
    asm volatile(
        "cp.async.bulk.shared::cluster.global.mbarrier::complete_tx::bytes "
        "[%0], [%1], %2, [%3];"
        :: "r"(dst_smem), "l"(src), "r"(32768u), "r"(mbar) : "memory");
}

// ---------------- mma / ldmatrix wrappers ------------------------------------
__device__ __forceinline__ void mma_bf16(float* c, const unsigned* a,
                                         unsigned b0, unsigned b1) {
    asm volatile(
        "mma.sync.aligned.m16n8k16.row.col.f32.bf16.bf16.f32 "
        "{%0,%1,%2,%3}, {%4,%5,%6,%7}, {%8,%9}, {%0,%1,%2,%3};"
        : "+f"(c[0]), "+f"(c[1]), "+f"(c[2]), "+f"(c[3])
        : "r"(a[0]), "r"(a[1]), "r"(a[2]), "r"(a[3]), "r"(b0), "r"(b1));
}
__device__ __forceinline__ void ldsm4t(unsigned* r, const __nv_bfloat16* p) {
    unsigned addr = (unsigned)__cvta_generic_to_shared(p);
    asm volatile("ldmatrix.sync.aligned.m8n8.x4.trans.shared.b16 {%0,%1,%2,%3}, [%4];"
        : "=r"(r[0]), "=r"(r[1]), "=r"(r[2]), "=r"(r[3]) : "r"(addr));
}

__device__ __forceinline__ void store_split2(__nv_bfloat16* H, __nv_bfloat16* L,
                                             int off, float v0, float v1) {
    __nv_bfloat16 h0 = __float2bfloat16(v0), h1 = __float2bfloat16(v1);
    __nv_bfloat16 l0 = __float2bfloat16(v0 - __bfloat162float(h0));
    __nv_bfloat16 l1 = __float2bfloat16(v1 - __bfloat162float(h1));
    *reinterpret_cast<unsigned*>(H + off) =
        (unsigned)__bfloat16_as_ushort(h0) | ((unsigned)__bfloat16_as_ushort(h1) << 16);
    *reinterpret_cast<unsigned*>(L + off) =
        (unsigned)__bfloat16_as_ushort(l0) | ((unsigned)__bfloat16_as_ushort(l1) << 16);
}

// ------- split-bf16 dense layer, 16 warps, bulk-staged ring ------------------
template <int NCH>
__device__ __forceinline__ void gemm_layer(const __nv_bfloat16* __restrict__ Wsrc,
                                           const float* __restrict__ bias,
                                           const __nv_bfloat16* INh,
                                           const __nv_bfloat16* INl,
                                           __nv_bfloat16* OUTh, __nv_bfloat16* OUTl,
                                           __nv_bfloat16* smb, unsigned smem_u32,
                                           int& gc, unsigned& phbits, int tid) {
    const int lane = tid & 31, w = tid >> 5;    // 16 warps
    const int g = lane >> 2, t = lane & 3;
    const int mrow = (w & 1) << 4;              // 0 or 16
    const int q = w >> 1;                        // 0..7 -> cols 32q..32q+31
    const int krow_l = (lane & 7) + ((lane >> 3) & 1) * 8;
    const int nc_l = (lane >> 4) * 8;

    float acc[4][4];
#pragma unroll
    for (int i = 0; i < 4; ++i)
#pragma unroll
        for (int j = 0; j < 4; ++j) acc[i][j] = 0.f;

    __syncthreads();                 // prev layer's smem use complete
    if (tid == 0) {
        int b = gc % 3;
        unsigned mb = smem_u32 + MBAR_BYTE + 8u * b;
        MBAR_EXPECT_TX(mb, 32768u);
        bulk_stage(smem_u32 + WB_BYTE + 32768u * b, Wsrc, mb);
    }

#pragma unroll 1
    for (int c = 0; c < NCH; ++c) {
        if (c + 1 < NCH && tid == 0) {
            int nb = (gc + c + 1) % 3;
            unsigned mb = smem_u32 + MBAR_BYTE + 8u * nb;
            MBAR_EXPECT_TX(mb, 32768u);
            bulk_stage(smem_u32 + WB_BYTE + 32768u * nb, Wsrc + (c + 1) * 16384, mb);
        }
        int cb = (gc + c) % 3;
        MBAR_WAIT(smem_u32 + MBAR_BYTE + 8u * cb, (phbits >> cb) & 1u);
        phbits ^= (1u << cb);
        __syncthreads();
        const __nv_bfloat16* swh = smb + WB_UNIT + cb * 16384;   // hi half
        const __nv_bfloat16* swl = swh + 8192;                    // lo half
#pragma unroll
        for (int kk = 0; kk < 2; ++kk) {
            const int kg = c * 32 + kk * 16;
            const __nv_bfloat16* ah_p = INh + (mrow + g) * AS + kg + 2 * t;
            const __nv_bfloat16* al_p = INl + (mrow + g) * AS + kg + 2 * t;
            unsigned ah[4], al[4];
            ah[0] = *reinterpret_cast<const unsigned*>(ah_p);
            ah[1] = *reinterpret_cast<const unsigned*>(ah_p + 8 * AS);
            ah[2] = *reinterpret_cast<const unsigned*>(ah_p + 8);
            ah[3] = *reinterpret_cast<const unsigned*>(ah_p + 8 * AS + 8);
            al[0] = *reinterpret_cast<const unsigned*>(al_p);
            al[1] = *reinterpret_cast<const unsigned*>(al_p + 8 * AS);
            al[2] = *reinterpret_cast<const unsigned*>(al_p + 8);
            al[3] = *reinterpret_cast<const unsigned*>(al_p + 8 * AS + 8);
            const int krow = kk * 16 + krow_l;
            const int swz = (krow & 7);
            const int rbase = krow * 256;
#pragma unroll
            for (int p = 0; p < 2; ++p) {
                const int ncol = (q << 5) + (p << 4) + nc_l;
                const int off = rbase + ((((ncol >> 3) ^ swz)) << 3);
                unsigned bh[4], bl[4];
                ldsm4t(bh, swh + off);
                ldsm4t(bl, swl + off);
                mma_bf16(acc[2 * p],     ah, bh[0], bh[1]);
                mma_bf16(acc[2 * p],     ah, bl[0], bl[1]);
                mma_bf16(acc[2 * p],     al, bh[0], bh[1]);
                mma_bf16(acc[2 * p + 1], ah, bh[2], bh[3]);
                mma_bf16(acc[2 * p + 1], ah, bl[2], bl[3]);
                mma_bf16(acc[2 * p + 1], al, bh[2], bh[3]);
            }
        }
    }
    gc += NCH;

    // epilogue: bias + mish (MUFU-free), split-store
#pragma unroll
    for (int nt = 0; nt < 4; ++nt) {
        const int col = (q << 5) + (nt << 3) + 2 * t;
        float b0v = bias[col], b1v = bias[col + 1];
        float v00 = mish_f(acc[nt][0] + b0v);
        float v01 = mish_f(acc[nt][1] + b1v);
        float v10 = mish_f(acc[nt][2] + b0v);
        float v11 = mish_f(acc[nt][3] + b1v);
        store_split2(OUTh, OUTl, (mrow + g) * AS + col, v00, v01);
        store_split2(OUTh, OUTl, (mrow + g + 8) * AS + col, v10, v11);
    }
}

// ------- init: split fp32 weights -> swizzled interleaved bf16 hi/lo chunks --
__global__ void split_weights(const float* __restrict__ w0,
                              const float* __restrict__ w1,
                              const float* __restrict__ w2) {
    int idx = blockIdx.x * blockDim.x + threadIdx.x;
    if (idx >= NCHUNK_TOT * 8192) return;
    int gch = idx >> 13;
    int r   = (idx >> 8) & 31;
    int n   = idx & 255;
    float v;
    if (gch < 6) {
        int k = gch * 32 + r;
        v = (k < 176) ? w0[k * 256 + n] : 0.f;
    } else if (gch < 14) {
        int k = (gch - 6) * 32 + r;
        v = w1[k * 256 + n];
    } else {
        int k = (gch - 14) * 32 + r;
        v = w2[k * 256 + n];
    }
    __nv_bfloat16 hi = __float2bfloat16(v);
    __nv_bfloat16 lo = __float2bfloat16(v - __bfloat162float(hi));
    int pos = gch * 16384 + r * 256 + (((n >> 3) ^ (r & 7)) << 3) + (n & 7);
    g_w[pos] = hi;
    g_w[pos + 8192] = lo;
}

// ---------------- persistent sampler -----------------------------------------
__global__ void __launch_bounds__(NT, 1)
diff_all(const float* __restrict__ state, const float* __restrict__ x_init,
         const float* __restrict__ w_t1, const float* __restrict__ b_t1,
         const float* __restrict__ w_t2, const float* __restrict__ b_t2,
         const float* __restrict__ b0,  const float* __restrict__ b1,
         const float* __restrict__ b2,
         const float* __restrict__ wf,  const float* __restrict__ bf,
         float* __restrict__ outp)
{
    extern __shared__ __align__(16) char smraw[];
    float* smf = reinterpret_cast<float*>(smraw);
    __nv_bfloat16* smb = reinterpret_cast<__nv_bfloat16*>(smraw);
    unsigned smem_u32 = (unsigned)__cvta_generic_to_shared(smraw);

    float* SWF = smf + F_SWF;
    float* XS  = smf + F_XS;
    float* TE  = smf + F_TE;
    float* HT  = smf + F_HT;
    float* TF  = smf + F_TF;
    float* CF  = smf + F_CF;
    unsigned* CFu = reinterpret_cast<unsigned*>(CF);

    __nv_bfloat16* A0h = smb + B_A0H;  __nv_bfloat16* A0l = smb + B_A0L;
    __nv_bfloat16* A1h = smb + B_A1H;  __nv_bfloat16* A1l = smb + B_A1L;

    const int tid = threadIdx.x;
    const int r0  = blockIdx.x * BR;

    if (tid == 0) {
#pragma unroll
        for (int b = 0; b < 3; ++b) MBAR_INIT(smem_u32 + MBAR_BYTE + 8u * b, 1u);
    }
    for (int idx = tid; idx < BR * 32; idx += NT) {
        int r = idx >> 5, c = idx & 31;
        XS[r * 33 + c] = x_init[(r0 + r) * 32 + c];
    }
    for (int idx = tid; idx < 256 * 32; idx += NT) SWF[idx] = wf[idx];
    __syncthreads();

    int gc = 0;
    unsigned phbits = 0;

#pragma unroll 1
    for (int i = 999; i >= 0; --i) {
        if (tid == 0) {
            double nn    = (double)(i + 1);
            double ac    = exp(-1e-4 * nn - 4.95e-6 * nn * nn);
            double nm    = nn - 1.0;
            double acp   = (i == 0) ? 1.0 : exp(-1e-4 * nm - 4.95e-6 * nm * nm);
            double beta  = 1.0 - exp(-1e-4 - 4.95e-6 * (2.0 * nn - 1.0));
            double alpha = 1.0 - beta;
            CF[0] = (float)sqrt(1.0 / ac);
            CF[1] = (float)sqrt(1.0 / ac - 1.0);
            CF[2] = (float)(beta * sqrt(acp) / (1.0 - ac));
            CF[3] = (float)((1.0 - acp) * sqrt(alpha) / (1.0 - ac));
            double pv = beta * (1.0 - acp) / (1.0 - ac);
            if (pv < 1e-20) pv = 1e-20;
            float lv = (float)log(pv);
            CF[4] = (float)exp((double)(0.5f * lv));
            unsigned a0 = 0u, a1 = (unsigned)i;
            threefry2x32(0u, 1u, a0, a1);
            CFu[5] = a0; CFu[6] = a1;
        }
        if (tid < 8) {
            float c8   = (float)(-9.210340371976184 / 7.0);
            float freq = expf(c8 * (float)tid);
            float ang  = (float)i * freq;
            TE[tid]     = (float)sin((double)ang);
            TE[tid + 8] = (float)cos((double)ang);
        }
        __syncthreads();
        if (tid < 32) {
            float h = b_t1[tid];
#pragma unroll
            for (int k = 0; k < 16; ++k) h = fmaf(TE[k], w_t1[k * 32 + tid], h);
            HT[tid] = mish_f(h);
        }
        __syncthreads();
        if (tid < 16) {
            float v = b_t2[tid];
#pragma unroll
            for (int k = 0; k < 32; ++k) v = fmaf(HT[k], w_t2[k * 16 + tid], v);
            TF[tid] = v;
        }
        __syncthreads();

        // ---- rebuild A0 (aliased by layer-2 output last step)
        for (int idx = tid; idx < 32 * 48; idx += NT) {
            int r = idx & 31, c = idx >> 5;
            float v = (c < 32) ? XS[r * 33 + c] : TF[c - 32];
            __nv_bfloat16 hi = __float2bfloat16(v);
            __nv_bfloat16 lo = __float2bfloat16(v - __bfloat162float(hi));
            A0h[r * AS + c] = hi;
            A0l[r * AS + c] = lo;
        }
        for (int idx = tid; idx < 32 * 128; idx += NT) {
            int r = idx >> 7, c = idx & 127;
            float v = state[(r0 + r) * 128 + c];
            __nv_bfloat16 hi = __float2bfloat16(v);
            __nv_bfloat16 lo = __float2bfloat16(v - __bfloat162float(hi));
            A0h[r * AS + 48 + c] = hi;
            A0l[r * AS + 48 + c] = lo;
        }
        for (int idx = tid; idx < 32 * 16; idx += NT) {
            int r = idx >> 4, c = idx & 15;
            __nv_bfloat16 z = __float2bfloat16(0.f);
            A0h[r * AS + 176 + c] = z;
            A0l[r * AS + 176 + c] = z;
        }

        gemm_layer<6>(g_w,              b0, A0h, A0l, A1h, A1l, smb, smem_u32, gc, phbits, tid);
        gemm_layer<8>(g_w + 6  * 16384, b1, A1h, A1l, A0h, A0l, smb, smem_u32, gc, phbits, tid);
        gemm_layer<8>(g_w + 14 * 16384, b2, A0h, A0l, A1h, A1l, smb, smem_u32, gc, phbits, tid);
        __syncthreads();

        // ---- final 256 -> 32 (exact fp32): row = tid>>4, 2 cols at (tid&15)*2
        const int row = tid >> 4;
        const int cp  = tid & 15;
        unsigned long long f0 = 0ull;
        const __nv_bfloat16* inh = A1h + row * AS;
        const __nv_bfloat16* inl = A1l + row * AS;
#pragma unroll 4
        for (int k2 = 0; k2 < 256; k2 += 2) {
            __nv_bfloat162 ph = *reinterpret_cast<const __nv_bfloat162*>(inh + k2);
            __nv_bfloat162 pl = *reinterpret_cast<const __nv_bfloat162*>(inl + k2);
            float a0 = __bfloat162float(ph.x) + __bfloat162float(pl.x);
            float a1 = __bfloat162float(ph.y) + __bfloat162float(pl.y);
#pragma unroll
            for (int kk = 0; kk < 2; ++kk) {
                float a = kk ? a1 : a0;
                const float* wp = SWF + ((k2 + kk) << 5) + (cp << 1);
                unsigned long long w01 = *reinterpret_cast<const unsigned long long*>(wp);
                unsigned long long aa;
                PACK_DUP(aa, a);
                FMA2(f0, aa, w01);
            }
        }
        float e0, e1;
        UNPACK2(e0, e1, f0);
        float eps[2] = { e0 + bf[cp * 2], e1 + bf[cp * 2 + 1] };

        float sr = CF[0], srm1 = CF[1], c1 = CF[2], c2 = CF[3], sig = CF[4];
        unsigned fk0 = CFu[5], fk1 = CFu[6];

        const int R = r0 + row;
#pragma unroll
        for (int cc = 0; cc < 2; ++cc) {
            int   j  = (cp << 1) + cc;
            float xv = XS[row * 33 + j];
            float x0 = fminf(1.f, fmaxf(-1.f, sr * xv - srm1 * eps[cc]));
            float mean = c1 * x0 + c2 * xv;
            if (i != 0) {
                unsigned f = (unsigned)(R * 32 + j);
                unsigned b0r = 0u, b1r = f;
                threefry2x32(fk0, fk1, b0r, b1r);
                unsigned bits = b0r ^ b1r;
                float fv = __uint_as_float((bits >> 9) | 0x3f800000u) - 1.0f;
                const float lo = -0.99999994f;
                float u   = fmaxf(lo, fmaf(fv, 2.0f, lo));
                float nrm = 1.4142135623730951f * erfinv_xla(u);
                XS[row * 33 + j] = mean + sig * nrm;
            } else {
                float xf = fminf(1.f, fmaxf(-1.f, mean));
                XS[row * 33 + j] = xf;
                outp[R * 32 + j] = xf;
            }
        }
        __syncthreads();
    }
}

extern "C" void kernel_launch(void* const* d_in, const int* in_sizes, int n_in,
                              void* d_out, int out_size) {
    const float* state = (const float*)d_in[0];
    const float* xinit = (const float*)d_in[1];
    const float* w_t1  = (const float*)d_in[2];
    const float* b_t1  = (const float*)d_in[3];
    const float* w_t2  = (const float*)d_in[4];
    const float* b_t2  = (const float*)d_in[5];
    const float* w0    = (const float*)d_in[6];
    const float* b0    = (const float*)d_in[7];
    const float* w1    = (const float*)d_in[8];
    const float* b1    = (const float*)d_in[9];
    const float* w2    = (const float*)d_in[10];
    const float* b2    = (const float*)d_in[11];
    const float* wf    = (const float*)d_in[12];
    const float* bf    = (const float*)d_in[13];
    float* outp = (float*)d_out;

    cudaFuncSetAttribute(diff_all, cudaFuncAttributeMaxDynamicSharedMemorySize, SMEM_BYTES);

    split_weights<<<(NCHUNK_TOT * 8192 + 255) / 256, 256>>>(w0, w1, w2);
    diff_all<<<NB, NT, SMEM_BYTES>>>(state, xinit,
        w_t1, b_t1, w_t2, b_t2,
        b0, b1, b2, wf, bf, outp);
}

// round 12
// speedup vs baseline: 1.6929x; 1.2984x over previous
#include <cuda_runtime.h>
#include <cuda_bf16.h>
#include <math.h>

#define NB 128
#define NT 512
#define BR 32
#define AS  264     // activation row stride (bf16 units) = 528B (conflict-free LDS)

// ---- smem layout (unchanged from R11) ----
#define F_SWF 0                    // 256*32 fp32 final weights
#define F_XS  8192                 // 32*33
#define MBAR_BYTE 37312
#define B_A0H 18688
#define B_A0L 27136
#define B_A1H 35584
#define B_A1L 44032
#define WB_BYTE 104960
#define WB_UNIT 52480
#define SMEM_BYTES (104960 + 3*32768)

// pre-split weights: per 32-row chunk: 16KB hi then 16KB lo, XOR-swizzled.
#define NCHUNK_TOT 22
#define W_ELEMS (NCHUNK_TOT * 16384)
__device__ __align__(128) __nv_bfloat16 g_w[W_ELEMS];
// per-step scalars: [i*8 + {sr,srm1,c1,c2,sig,fk0,fk1,pad}] and time-MLP out
__device__ float g_cf[1000 * 8];
__device__ float g_tf[1000 * 16];

// ---- packed f32x2 helpers (final layer) ------------------------------------
#define FMA2(acc, aa, bb) \
    asm("fma.rn.f32x2 %0, %1, %2, %0;" : "+l"(acc) : "l"(aa), "l"(bb))
#define PACK_DUP(dst, fv) do { \
    unsigned _pi = __float_as_uint(fv); \
    asm("mov.b64 %0, {%1, %1};" : "=l"(dst) : "r"(_pi)); } while (0)
#define UNPACK2(lo, hi, src) do { \
    unsigned _u0, _u1; \
    asm("mov.b64 {%0, %1}, %2;" : "=r"(_u0), "=r"(_u1) : "l"(src)); \
    lo = __uint_as_float(_u0); hi = __uint_as_float(_u1); } while (0)

// ---------------- threefry2x32-20 (exact JAX) ------------------------------
__device__ __forceinline__ unsigned rotl32(unsigned x, int r) {
    return __funnelshift_l(x, x, r);
}
__device__ __forceinline__ void threefry2x32(unsigned k0, unsigned k1,
                                             unsigned &x0, unsigned &x1) {
    unsigned k2 = k0 ^ k1 ^ 0x1BD11BDAu;
#define TFR(r) { x0 += x1; x1 = rotl32(x1, r); x1 ^= x0; }
    x0 += k0; x1 += k1;
    TFR(13) TFR(15) TFR(26) TFR(6)
    x0 += k1; x1 += k2 + 1u;
    TFR(17) TFR(29) TFR(16) TFR(24)
    x0 += k2; x1 += k0 + 2u;
    TFR(13) TFR(15) TFR(26) TFR(6)
    x0 += k0; x1 += k1 + 3u;
    TFR(17) TFR(29) TFR(16) TFR(24)
    x0 += k1; x1 += k2 + 4u;
    TFR(13) TFR(15) TFR(26) TFR(6)
    x0 += k2; x1 += k0 + 5u;
#undef TFR
}

// ---------------- XLA ErfInv f32 (Giles) ------------------------------------
__device__ __forceinline__ float erfinv_xla(float x) {
    float w = -log1pf(-x * x);
    float p;
    if (w < 5.0f) {
        w -= 2.5f;
        p = 2.81022636e-08f;
        p = fmaf(p, w, 3.43273939e-07f);
        p = fmaf(p, w, -3.5233877e-06f);
        p = fmaf(p, w, -4.39150654e-06f);
        p = fmaf(p, w, 0.00021858087f);
        p = fmaf(p, w, -0.00125372503f);
        p = fmaf(p, w, -0.00417768164f);
        p = fmaf(p, w, 0.246640727f);
        p = fmaf(p, w, 1.50140941f);
    } else {
        w = sqrtf(w) - 3.0f;
        p = -0.000200214257f;
        p = fmaf(p, w, 0.000100950558f);
        p = fmaf(p, w, 0.00134934322f);
        p = fmaf(p, w, -0.00367342844f);
        p = fmaf(p, w, 0.00573950773f);
        p = fmaf(p, w, -0.0076224613f);
        p = fmaf(p, w, 0.00943887047f);
        p = fmaf(p, w, 1.00167406f);
        p = fmaf(p, w, 2.83297682f);
    }
    return p * x;
}

// ---------------- MUFU-free mish -------------------------------------------
__device__ __forceinline__ float exp_fma(float x) {
    float y = x * 1.4426950408889634f;
    y = fmaxf(y, -120.0f);
    float n = rintf(y);
    float f = y - n;
    float p =       1.5403530393381609e-4f;
    p = fmaf(p, f, 1.3333558146428443e-3f);
    p = fmaf(p, f, 9.6181298420718030e-3f);
    p = fmaf(p, f, 5.5504108664821580e-2f);
    p = fmaf(p, f, 2.4022650695910070e-1f);
    p = fmaf(p, f, 6.9314718055994530e-1f);
    p = fmaf(p, f, 1.0f);
    int e = (int)n;
    return p * __int_as_float((e + 127) << 23);
}
__device__ __forceinline__ float rcp_fma(float d) {
    float r = __int_as_float(0x7EF311C3 - __float_as_int(d));
    r = r * fmaf(-d, r, 2.0f);
    r = r * fmaf(-d, r, 2.0f);
    r = r * fmaf(-d, r, 2.0f);
    return r;
}
__device__ __forceinline__ float mish_f(float x) {
    if (x > 20.0f) return x;
    float u = exp_fma(x);
    float s = u * (u + 2.0f);
    return x * s * rcp_fma(s + 2.0f);
}

// ---------------- mbarrier + bulk-copy helpers --------------------------------
#define MBAR_INIT(addr, cnt) \
    asm volatile("mbarrier.init.shared.b64 [%0], %1;" :: "r"(addr), "r"(cnt) : "memory")
#define MBAR_EXPECT_TX(addr, bytes) \
    asm volatile("mbarrier.arrive.expect_tx.shared.b64 _, [%0], %1;" :: "r"(addr), "r"(bytes) : "memory")
#define MBAR_WAIT(addr, parity) do { \
    unsigned _done = 0; \
    while (!_done) { \
        asm volatile("{\n\t.reg .pred p;\n\t" \
            "mbarrier.try_wait.parity.acquire.cta.shared::cta.b64 p, [%1], %2, 0x989680;\n\t" \
            "selp.b32 %0, 1, 0, p;\n\t}" \
            : "=r"(_done) : "r"(addr), "r"(parity) : "memory"); \
    } } while (0)

__device__ __forceinline__ void bulk_stage(unsigned dst_smem,
                                           const __nv_bfloat16* src,
                                           unsigned mbar) {
    asm volatile(
        "cp.async.bulk.shared::cluster.global.mbarrier::complete_tx::bytes "
        "[%0], [%1], %2, [%3];"
        :: "r"(dst_smem), "l"(src), "r"(32768u), "r"(mbar) : "memory");
}

// ---------------- mma / ldmatrix wrappers ------------------------------------
__device__ __forceinline__ void mma_bf16(float* c, const unsigned* a,
                                         unsigned b0, unsigned b1) {
    asm volatile(
        "mma.sync.aligned.m16n8k16.row.col.f32.bf16.bf16.f32 "
        "{%0,%1,%2,%3}, {%4,%5,%6,%7}, {%8,%9}, {%0,%1,%2,%3};"
        : "+f"(c[0]), "+f"(c[1]), "+f"(c[2]), "+f"(c[3])
        : "r"(a[0]), "r"(a[1]), "r"(a[2]), "r"(a[3]), "r"(b0), "r"(b1));
}
__device__ __forceinline__ void ldsm4t(unsigned* r, const __nv_bfloat16* p) {
    unsigned addr = (unsigned)__cvta_generic_to_shared(p);
    asm volatile("ldmatrix.sync.aligned.m8n8.x4.trans.shared.b16 {%0,%1,%2,%3}, [%4];"
        : "=r"(r[0]), "=r"(r[1]), "=r"(r[2]), "=r"(r[3]) : "r"(addr));
}

__device__ __forceinline__ void store_split2(__nv_bfloat16* H, __nv_bfloat16* L,
                                             int off, float v0, float v1) {
    __nv_bfloat16 h0 = __float2bfloat16(v0), h1 = __float2bfloat16(v1);
    __nv_bfloat16 l0 = __float2bfloat16(v0 - __bfloat162float(h0));
    __nv_bfloat16 l1 = __float2bfloat16(v1 - __bfloat162float(h1));
    *reinterpret_cast<unsigned*>(H + off) =
        (unsigned)__bfloat16_as_ushort(h0) | ((unsigned)__bfloat16_as_ushort(h1) << 16);
    *reinterpret_cast<unsigned*>(L + off) =
        (unsigned)__bfloat16_as_ushort(l0) | ((unsigned)__bfloat16_as_ushort(l1) << 16);
}

// ------- split-bf16 dense layer, 16 warps, bulk-staged ring ------------------
template <int NCH>
__device__ __forceinline__ void gemm_layer(const __nv_bfloat16* __restrict__ Wsrc,
                                           const float* __restrict__ bias,
                                           const __nv_bfloat16* INh,
                                           const __nv_bfloat16* INl,
                                           __nv_bfloat16* OUTh, __nv_bfloat16* OUTl,
                                           __nv_bfloat16* smb, unsigned smem_u32,
                                           int& gc, unsigned& phbits, int tid) {
    const int lane = tid & 31, w = tid >> 5;    // 16 warps
    const int g = lane >> 2, t = lane & 3;
    const int mrow = (w & 1) << 4;              // 0 or 16
    const int q = w >> 1;                        // 0..7 -> cols 32q..32q+31
    const int krow_l = (lane & 7) + ((lane >> 3) & 1) * 8;
    const int nc_l = (lane >> 4) * 8;

    float acc[4][4];
#pragma unroll
    for (int i = 0; i < 4; ++i)
#pragma unroll
        for (int j = 0; j < 4; ++j) acc[i][j] = 0.f;

    __syncthreads();                 // prev layer's smem use complete
    if (tid == 0) {
        int b = gc % 3;
        unsigned mb = smem_u32 + MBAR_BYTE + 8u * b;
        MBAR_EXPECT_TX(mb, 32768u);
        bulk_stage(smem_u32 + WB_BYTE + 32768u * b, Wsrc, mb);
    }

#pragma unroll 1
    for (int c = 0; c < NCH; ++c) {
        if (c + 1 < NCH && tid == 0) {
            int nb = (gc + c + 1) % 3;
            unsigned mb = smem_u32 + MBAR_BYTE + 8u * nb;
            MBAR_EXPECT_TX(mb, 32768u);
            bulk_stage(smem_u32 + WB_BYTE + 32768u * nb, Wsrc + (c + 1) * 16384, mb);
        }
        int cb = (gc + c) % 3;
        if (tid == 0) MBAR_WAIT(smem_u32 + MBAR_BYTE + 8u * cb, (phbits >> cb) & 1u);
        phbits ^= (1u << cb);
        __syncthreads();             // releases data staged by leader's wait
        const __nv_bfloat16* swh = smb + WB_UNIT + cb * 16384;   // hi half
        const __nv_bfloat16* swl = swh + 8192;                    // lo half
#pragma unroll
        for (int kk = 0; kk < 2; ++kk) {
            const int kg = c * 32 + kk * 16;
            const __nv_bfloat16* ah_p = INh + (mrow + g) * AS + kg + 2 * t;
            const __nv_bfloat16* al_p = INl + (mrow + g) * AS + kg + 2 * t;
            unsigned ah[4], al[4];
            ah[0] = *reinterpret_cast<const unsigned*>(ah_p);
            ah[1] = *reinterpret_cast<const unsigned*>(ah_p + 8 * AS);
            ah[2] = *reinterpret_cast<const unsigned*>(ah_p + 8);
            ah[3] = *reinterpret_cast<const unsigned*>(ah_p + 8 * AS + 8);
            al[0] = *reinterpret_cast<const unsigned*>(al_p);
            al[1] = *reinterpret_cast<const unsigned*>(al_p + 8 * AS);
            al[2] = *reinterpret_cast<const unsigned*>(al_p + 8);
            al[3] = *reinterpret_cast<const unsigned*>(al_p + 8 * AS + 8);
            const int krow = kk * 16 + krow_l;
            const int swz = (krow & 7);
            const int rbase = krow * 256;
#pragma unroll
            for (int p = 0; p < 2; ++p) {
                const int ncol = (q << 5) + (p << 4) + nc_l;
                const int off = rbase + ((((ncol >> 3) ^ swz)) << 3);
                unsigned bh[4], bl[4];
                ldsm4t(bh, swh + off);
                ldsm4t(bl, swl + off);
                mma_bf16(acc[2 * p],     ah, bh[0], bh[1]);
                mma_bf16(acc[2 * p],     ah, bl[0], bl[1]);
                mma_bf16(acc[2 * p],     al, bh[0], bh[1]);
                mma_bf16(acc[2 * p + 1], ah, bh[2], bh[3]);
                mma_bf16(acc[2 * p + 1], ah, bl[2], bl[3]);
                mma_bf16(acc[2 * p + 1], al, bh[2], bh[3]);
            }
        }
    }
    gc += NCH;

    // epilogue: bias + mish (MUFU-free), split-store
#pragma unroll
    for (int nt = 0; nt < 4; ++nt) {
        const int col = (q << 5) + (nt << 3) + 2 * t;
        float b0v = bias[col], b1v = bias[col + 1];
        float v00 = mish_f(acc[nt][0] + b0v);
        float v01 = mish_f(acc[nt][1] + b1v);
        float v10 = mish_f(acc[nt][2] + b0v);
        float v11 = mish_f(acc[nt][3] + b1v);
        store_split2(OUTh, OUTl, (mrow + g) * AS + col, v00, v01);
        store_split2(OUTh, OUTl, (mrow + g + 8) * AS + col, v10, v11);
    }
}

// ------- init: split fp32 weights -> swizzled interleaved bf16 hi/lo chunks --
__global__ void split_weights(const float* __restrict__ w0,
                              const float* __restrict__ w1,
                              const float* __restrict__ w2) {
    int idx = blockIdx.x * blockDim.x + threadIdx.x;
    if (idx >= NCHUNK_TOT * 8192) return;
    int gch = idx >> 13;
    int r   = (idx >> 8) & 31;
    int n   = idx & 255;
    float v;
    if (gch < 6) {
        int k = gch * 32 + r;
        v = (k < 176) ? w0[k * 256 + n] : 0.f;
    } else if (gch < 14) {
        int k = (gch - 6) * 32 + r;
        v = w1[k * 256 + n];
    } else {
        int k = (gch - 14) * 32 + r;
        v = w2[k * 256 + n];
    }
    __nv_bfloat16 hi = __float2bfloat16(v);
    __nv_bfloat16 lo = __float2bfloat16(v - __bfloat162float(hi));
    int pos = gch * 16384 + r * 256 + (((n >> 3) ^ (r & 7)) << 3) + (n & 7);
    g_w[pos] = hi;
    g_w[pos + 8192] = lo;
}

// ------- init: per-step coefficients + time-MLP output (same math as before) -
__global__ void precompute(const float* __restrict__ w_t1,
                           const float* __restrict__ b_t1,
                           const float* __restrict__ w_t2,
                           const float* __restrict__ b_t2) {
    int i = blockIdx.x * blockDim.x + threadIdx.x;
    if (i >= 1000) return;
    // coefficients (double, identical formulas/order)
    double nn    = (double)(i + 1);
    double ac    = exp(-1e-4 * nn - 4.95e-6 * nn * nn);
    double nm    = nn - 1.0;
    double acp   = (i == 0) ? 1.0 : exp(-1e-4 * nm - 4.95e-6 * nm * nm);
    double beta  = 1.0 - exp(-1e-4 - 4.95e-6 * (2.0 * nn - 1.0));
    double alpha = 1.0 - beta;
    g_cf[i * 8 + 0] = (float)sqrt(1.0 / ac);
    g_cf[i * 8 + 1] = (float)sqrt(1.0 / ac - 1.0);
    g_cf[i * 8 + 2] = (float)(beta * sqrt(acp) / (1.0 - ac));
    g_cf[i * 8 + 3] = (float)((1.0 - acp) * sqrt(alpha) / (1.0 - ac));
    double pv = beta * (1.0 - acp) / (1.0 - ac);
    if (pv < 1e-20) pv = 1e-20;
    float lv = (float)log(pv);
    g_cf[i * 8 + 4] = (float)exp((double)(0.5f * lv));
    unsigned a0 = 0u, a1 = (unsigned)i;
    threefry2x32(0u, 1u, a0, a1);
    g_cf[i * 8 + 5] = __uint_as_float(a0);
    g_cf[i * 8 + 6] = __uint_as_float(a1);
    // time embedding + tiny MLP (identical order to the in-loop version)
    float te[16];
    for (int t = 0; t < 8; ++t) {
        float c8   = (float)(-9.210340371976184 / 7.0);
        float freq = expf(c8 * (float)t);
        float ang  = (float)i * freq;
        te[t]     = (float)sin((double)ang);
        te[t + 8] = (float)cos((double)ang);
    }
    float ht[32];
    for (int j = 0; j < 32; ++j) {
        float h = b_t1[j];
        for (int k = 0; k < 16; ++k) h = fmaf(te[k], w_t1[k * 32 + j], h);
        ht[j] = mish_f(h);
    }
    for (int j = 0; j < 16; ++j) {
        float v = b_t2[j];
        for (int k = 0; k < 32; ++k) v = fmaf(ht[k], w_t2[k * 16 + j], v);
        g_tf[i * 16 + j] = v;
    }
}

// ---------------- persistent sampler -----------------------------------------
__global__ void __launch_bounds__(NT, 1)
diff_all(const float* __restrict__ state, const float* __restrict__ x_init,
         const float* __restrict__ b0,  const float* __restrict__ b1,
         const float* __restrict__ b2,
         const float* __restrict__ wf,  const float* __restrict__ bf,
         float* __restrict__ outp)
{
    extern __shared__ __align__(16) char smraw[];
    float* smf = reinterpret_cast<float*>(smraw);
    __nv_bfloat16* smb = reinterpret_cast<__nv_bfloat16*>(smraw);
    unsigned smem_u32 = (unsigned)__cvta_generic_to_shared(smraw);

    float* SWF = smf + F_SWF;
    float* XS  = smf + F_XS;

    __nv_bfloat16* A0h = smb + B_A0H;  __nv_bfloat16* A0l = smb + B_A0L;
    __nv_bfloat16* A1h = smb + B_A1H;  __nv_bfloat16* A1l = smb + B_A1L;

    const int tid = threadIdx.x;
    const int r0  = blockIdx.x * BR;

    if (tid == 0) {
#pragma unroll
        for (int b = 0; b < 3; ++b) MBAR_INIT(smem_u32 + MBAR_BYTE + 8u * b, 1u);
    }
    for (int idx = tid; idx < BR * 32; idx += NT) {
        int r = idx >> 5, c = idx & 31;
        XS[r * 33 + c] = x_init[(r0 + r) * 32 + c];
    }
    for (int idx = tid; idx < 256 * 32; idx += NT) SWF[idx] = wf[idx];
    __syncthreads();

    int gc = 0;
    unsigned phbits = 0;

#pragma unroll 1
    for (int i = 999; i >= 0; --i) {
        // ---- rebuild A0 (aliased by layer-2 output last step)
        for (int idx = tid; idx < 32 * 48; idx += NT) {
            int r = idx & 31, c = idx >> 5;
            float v = (c < 32) ? XS[r * 33 + c] : __ldg(&g_tf[i * 16 + (c - 32)]);
            __nv_bfloat16 hi = __float2bfloat16(v);
            __nv_bfloat16 lo = __float2bfloat16(v - __bfloat162float(hi));
            A0h[r * AS + c] = hi;
            A0l[r * AS + c] = lo;
        }
        for (int idx = tid; idx < 32 * 128; idx += NT) {
            int r = idx >> 7, c = idx & 127;
            float v = state[(r0 + r) * 128 + c];
            __nv_bfloat16 hi = __float2bfloat16(v);
            __nv_bfloat16 lo = __float2bfloat16(v - __bfloat162float(hi));
            A0h[r * AS + 48 + c] = hi;
            A0l[r * AS + 48 + c] = lo;
        }
        for (int idx = tid; idx < 32 * 16; idx += NT) {
            int r = idx >> 4, c = idx & 15;
            __nv_bfloat16 z = __float2bfloat16(0.f);
            A0h[r * AS + 176 + c] = z;
            A0l[r * AS + 176 + c] = z;
        }

        gemm_layer<6>(g_w,              b0, A0h, A0l, A1h, A1l, smb, smem_u32, gc, phbits, tid);
        gemm_layer<8>(g_w + 6  * 16384, b1, A1h, A1l, A0h, A0l, smb, smem_u32, gc, phbits, tid);
        gemm_layer<8>(g_w + 14 * 16384, b2, A0h, A0l, A1h, A1l, smb, smem_u32, gc, phbits, tid);
        __syncthreads();

        // ---- final 256 -> 32 (exact fp32): row = tid>>4, 2 cols at (tid&15)*2
        const int row = tid >> 4;
        const int cp  = tid & 15;
        unsigned long long f0 = 0ull;
        const __nv_bfloat16* inh = A1h + row * AS;
        const __nv_bfloat16* inl = A1l + row * AS;
#pragma unroll 4
        for (int k2 = 0; k2 < 256; k2 += 2) {
            __nv_bfloat162 ph = *reinterpret_cast<const __nv_bfloat162*>(inh + k2);
            __nv_bfloat162 pl = *reinterpret_cast<const __nv_bfloat162*>(inl + k2);
            float a0 = __bfloat162float(ph.x) + __bfloat162float(pl.x);
            float a1 = __bfloat162float(ph.y) + __bfloat162float(pl.y);
#pragma unroll
            for (int kk = 0; kk < 2; ++kk) {
                float a = kk ? a1 : a0;
                const float* wp = SWF + ((k2 + kk) << 5) + (cp << 1);
                unsigned long long w01 = *reinterpret_cast<const unsigned long long*>(wp);
                unsigned long long aa;
                PACK_DUP(aa, a);
                FMA2(f0, aa, w01);
            }
        }
        float e0, e1;
        UNPACK2(e0, e1, f0);
        float eps[2] = { e0 + bf[cp * 2], e1 + bf[cp * 2 + 1] };

        const float* cf = &g_cf[i * 8];
        float sr  = __ldg(cf + 0), srm1 = __ldg(cf + 1);
        float c1  = __ldg(cf + 2), c2   = __ldg(cf + 3);
        float sig = __ldg(cf + 4);
        unsigned fk0 = __float_as_uint(__ldg(cf + 5));
        unsigned fk1 = __float_as_uint(__ldg(cf + 6));

        const int R = r0 + row;
#pragma unroll
        for (int cc = 0; cc < 2; ++cc) {
            int   j  = (cp << 1) + cc;
            float xv = XS[row * 33 + j];
            float x0 = fminf(1.f, fmaxf(-1.f, sr * xv - srm1 * eps[cc]));
            float mean = c1 * x0 + c2 * xv;
            if (i != 0) {
                unsigned f = (unsigned)(R * 32 + j);
                unsigned b0r = 0u, b1r = f;
                threefry2x32(fk0, fk1, b0r, b1r);
                unsigned bits = b0r ^ b1r;
                float fv = __uint_as_float((bits >> 9) | 0x3f800000u) - 1.0f;
                const float lo = -0.99999994f;
                float u   = fmaxf(lo, fmaf(fv, 2.0f, lo));
                float nrm = 1.4142135623730951f * erfinv_xla(u);
                XS[row * 33 + j] = mean + sig * nrm;
            } else {
                float xf = fminf(1.f, fmaxf(-1.f, mean));
                XS[row * 33 + j] = xf;
                outp[R * 32 + j] = xf;
            }
        }
        __syncthreads();
    }
}

extern "C" void kernel_launch(void* const* d_in, const int* in_sizes, int n_in,
                              void* d_out, int out_size) {
    const float* state = (const float*)d_in[0];
    const float* xinit = (const float*)d_in[1];
    const float* w_t1  = (const float*)d_in[2];
    const float* b_t1  = (const float*)d_in[3];
    const float* w_t2  = (const float*)d_in[4];
    const float* b_t2  = (const float*)d_in[5];
    const float* w0    = (const float*)d_in[6];
    const float* b0    = (const float*)d_in[7];
    const float* w1    = (const float*)d_in[8];
    const float* b1    = (const float*)d_in[9];
    const float* w2    = (const float*)d_in[10];
    const float* b2    = (const float*)d_in[11];
    const float* wf    = (const float*)d_in[12];
    const float* bf    = (const float*)d_in[13];
    float* outp = (float*)d_out;

    cudaFuncSetAttribute(diff_all, cudaFuncAttributeMaxDynamicSharedMemorySize, SMEM_BYTES);

    split_weights<<<(NCHUNK_TOT * 8192 + 255) / 256, 256>>>(w0, w1, w2);
    precompute<<<4, 256>>>(w_t1, b_t1, w_t2, b_t2);
    diff_all<<<NB, NT, SMEM_BYTES>>>(state, xinit,
        b0, b1, b2, wf, bf, outp);
}

// round 13
// speedup vs baseline: 2.0078x; 1.1860x over previous
#include <cuda_runtime.h>
#include <cuda_bf16.h>
#include <math.h>

#define NB 128
#define NT 512
#define BR 32
#define AS  264     // activation row stride (bf16 units) = 528B (conflict-free LDS)

// ---- smem layout ----
#define F_XS  0                    // 32*33 fp32 x state (1056 floats, 4224B)
#define MBAR_BYTE 4224             // 3 x 8B mbarriers
// bf16 region from byte 4352 = unit 2176
#define B_A0H 2176
#define B_A0L 10624
#define B_A1H 19072
#define B_A1L 27520                // end unit 35968
// final-layer weights bf16 hi/lo, [256 rows][stride 40]
#define WFH_UNIT 35968
#define WFL_UNIT 46208             // end unit 56448 = byte 112896
#define WB_BYTE 112896
#define WB_UNIT 56448
#define SMEM_BYTES (112896 + 3*32768)

// pre-split trunk weights: per 32-row chunk: 16KB hi then 16KB lo, XOR-swizzled.
#define NCHUNK_TOT 22
#define W_ELEMS (NCHUNK_TOT * 16384)
__device__ __align__(128) __nv_bfloat16 g_w[W_ELEMS];
// per-step scalars + time-MLP output
__device__ float g_cf[1000 * 8];
__device__ float g_tf[1000 * 16];

// ---------------- threefry2x32-20 (exact JAX) ------------------------------
__device__ __forceinline__ unsigned rotl32(unsigned x, int r) {
    return __funnelshift_l(x, x, r);
}
__device__ __forceinline__ void threefry2x32(unsigned k0, unsigned k1,
                                             unsigned &x0, unsigned &x1) {
    unsigned k2 = k0 ^ k1 ^ 0x1BD11BDAu;
#define TFR(r) { x0 += x1; x1 = rotl32(x1, r); x1 ^= x0; }
    x0 += k0; x1 += k1;
    TFR(13) TFR(15) TFR(26) TFR(6)
    x0 += k1; x1 += k2 + 1u;
    TFR(17) TFR(29) TFR(16) TFR(24)
    x0 += k2; x1 += k0 + 2u;
    TFR(13) TFR(15) TFR(26) TFR(6)
    x0 += k0; x1 += k1 + 3u;
    TFR(17) TFR(29) TFR(16) TFR(24)
    x0 += k1; x1 += k2 + 4u;
    TFR(13) TFR(15) TFR(26) TFR(6)
    x0 += k2; x1 += k0 + 5u;
#undef TFR
}

// ---------------- XLA ErfInv f32 (Giles) ------------------------------------
__device__ __forceinline__ float erfinv_xla(float x) {
    float w = -log1pf(-x * x);
    float p;
    if (w < 5.0f) {
        w -= 2.5f;
        p = 2.81022636e-08f;
        p = fmaf(p, w, 3.43273939e-07f);
        p = fmaf(p, w, -3.5233877e-06f);
        p = fmaf(p, w, -4.39150654e-06f);
        p = fmaf(p, w, 0.00021858087f);
        p = fmaf(p, w, -0.00125372503f);
        p = fmaf(p, w, -0.00417768164f);
        p = fmaf(p, w, 0.246640727f);
        p = fmaf(p, w, 1.50140941f);
    } else {
        w = sqrtf(w) - 3.0f;
        p = -0.000200214257f;
        p = fmaf(p, w, 0.000100950558f);
        p = fmaf(p, w, 0.00134934322f);
        p = fmaf(p, w, -0.00367342844f);
        p = fmaf(p, w, 0.00573950773f);
        p = fmaf(p, w, -0.0076224613f);
        p = fmaf(p, w, 0.00943887047f);
        p = fmaf(p, w, 1.00167406f);
        p = fmaf(p, w, 2.83297682f);
    }
    return p * x;
}

// ---------------- MUFU-free mish -------------------------------------------
__device__ __forceinline__ float exp_fma(float x) {
    float y = x * 1.4426950408889634f;
    y = fmaxf(y, -120.0f);
    float n = rintf(y);
    float f = y - n;
    float p =       1.5403530393381609e-4f;
    p = fmaf(p, f, 1.3333558146428443e-3f);
    p = fmaf(p, f, 9.6181298420718030e-3f);
    p = fmaf(p, f, 5.5504108664821580e-2f);
    p = fmaf(p, f, 2.4022650695910070e-1f);
    p = fmaf(p, f, 6.9314718055994530e-1f);
    p = fmaf(p, f, 1.0f);
    int e = (int)n;
    return p * __int_as_float((e + 127) << 23);
}
__device__ __forceinline__ float rcp_fma(float d) {
    float r = __int_as_float(0x7EF311C3 - __float_as_int(d));
    r = r * fmaf(-d, r, 2.0f);
    r = r * fmaf(-d, r, 2.0f);
    r = r * fmaf(-d, r, 2.0f);
    return r;
}
__device__ __forceinline__ float mish_f(float x) {
    if (x > 20.0f) return x;
    float u = exp_fma(x);
    float s = u * (u + 2.0f);
    return x * s * rcp_fma(s + 2.0f);
}

// ---------------- mbarrier + bulk-copy helpers --------------------------------
#define MBAR_INIT(addr, cnt) \
    asm volatile("mbarrier.init.shared.b64 [%0], %1;" :: "r"(addr), "r"(cnt) : "memory")
#define MBAR_EXPECT_TX(addr, bytes) \
    asm volatile("mbarrier.arrive.expect_tx.shared.b64 _, [%0], %1;" :: "r"(addr), "r"(bytes) : "memory")
#define MBAR_WAIT(addr, parity) do { \
    unsigned _done = 0; \
    while (!_done) { \
        asm volatile("{\n\t.reg .pred p;\n\t" \
            "mbarrier.try_wait.parity.acquire.cta.shared::cta.b64 p, [%1], %2, 0x989680;\n\t" \
            "selp.b32 %0, 1, 0, p;\n\t}" \
            : "=r"(_done) : "r"(addr), "r"(parity) : "memory"); \
    } } while (0)

__device__ __forceinline__ void bulk_stage(unsigned dst_smem,
                                           const __nv_bfloat16* src,
                                           unsigned mbar) {
    asm volatile(
        "cp.async.bulk.shared::cluster.global.mbarrier::complete_tx::bytes "
        "[%0], [%1], %2, [%3];"
        :: "r"(dst_smem), "l"(src), "r"(32768u), "r"(mbar) : "memory");
}

// ---------------- mma / ldmatrix wrappers ------------------------------------
__device__ __forceinline__ void mma_bf16(float* c, const unsigned* a,
                                         unsigned b0, unsigned b1) {
    asm volatile(
        "mma.sync.aligned.m16n8k16.row.col.f32.bf16.bf16.f32 "
        "{%0,%1,%2,%3}, {%4,%5,%6,%7}, {%8,%9}, {%0,%1,%2,%3};"
        : "+f"(c[0]), "+f"(c[1]), "+f"(c[2]), "+f"(c[3])
        : "r"(a[0]), "r"(a[1]), "r"(a[2]), "r"(a[3]), "r"(b0), "r"(b1));
}
__device__ __forceinline__ void ldsm4t(unsigned* r, const __nv_bfloat16* p) {
    unsigned addr = (unsigned)__cvta_generic_to_shared(p);
    asm volatile("ldmatrix.sync.aligned.m8n8.x4.trans.shared.b16 {%0,%1,%2,%3}, [%4];"
        : "=r"(r[0]), "=r"(r[1]), "=r"(r[2]), "=r"(r[3]) : "r"(addr));
}
__device__ __forceinline__ void ldsm2t(unsigned* r, const __nv_bfloat16* p) {
    unsigned addr = (unsigned)__cvta_generic_to_shared(p);
    asm volatile("ldmatrix.sync.aligned.m8n8.x2.trans.shared.b16 {%0,%1}, [%2];"
        : "=r"(r[0]), "=r"(r[1]) : "r"(addr));
}

__device__ __forceinline__ void store_split2(__nv_bfloat16* H, __nv_bfloat16* L,
                                             int off, float v0, float v1) {
    __nv_bfloat16 h0 = __float2bfloat16(v0), h1 = __float2bfloat16(v1);
    __nv_bfloat16 l0 = __float2bfloat16(v0 - __bfloat162float(h0));
    __nv_bfloat16 l1 = __float2bfloat16(v1 - __bfloat162float(h1));
    *reinterpret_cast<unsigned*>(H + off) =
        (unsigned)__bfloat16_as_ushort(h0) | ((unsigned)__bfloat16_as_ushort(h1) << 16);
    *reinterpret_cast<unsigned*>(L + off) =
        (unsigned)__bfloat16_as_ushort(l0) | ((unsigned)__bfloat16_as_ushort(l1) << 16);
}

// ------- split-bf16 dense layer, 16 warps, bulk-staged ring ------------------
template <int NCH>
__device__ __forceinline__ void gemm_layer(const __nv_bfloat16* __restrict__ Wsrc,
                                           const float* __restrict__ bias,
                                           const __nv_bfloat16* INh,
                                           const __nv_bfloat16* INl,
                                           __nv_bfloat16* OUTh, __nv_bfloat16* OUTl,
                                           __nv_bfloat16* smb, unsigned smem_u32,
                                           int& gc, unsigned& phbits, int tid) {
    const int lane = tid & 31, w = tid >> 5;    // 16 warps
    const int g = lane >> 2, t = lane & 3;
    const int mrow = (w & 1) << 4;              // 0 or 16
    const int q = w >> 1;                        // 0..7 -> cols 32q..32q+31
    const int krow_l = (lane & 7) + ((lane >> 3) & 1) * 8;
    const int nc_l = (lane >> 4) * 8;

    float acc[4][4];
#pragma unroll
    for (int i = 0; i < 4; ++i)
#pragma unroll
        for (int j = 0; j < 4; ++j) acc[i][j] = 0.f;

    __syncthreads();                 // prev layer's smem use complete
    if (tid == 0) {
        int b = gc % 3;
        unsigned mb = smem_u32 + MBAR_BYTE + 8u * b;
        MBAR_EXPECT_TX(mb, 32768u);
        bulk_stage(smem_u32 + WB_BYTE + 32768u * b, Wsrc, mb);
    }

#pragma unroll 1
    for (int c = 0; c < NCH; ++c) {
        if (c + 1 < NCH && tid == 0) {
            int nb = (gc + c + 1) % 3;
            unsigned mb = smem_u32 + MBAR_BYTE + 8u * nb;
            MBAR_EXPECT_TX(mb, 32768u);
            bulk_stage(smem_u32 + WB_BYTE + 32768u * nb, Wsrc + (c + 1) * 16384, mb);
        }
        int cb = (gc + c) % 3;
        if (tid == 0) MBAR_WAIT(smem_u32 + MBAR_BYTE + 8u * cb, (phbits >> cb) & 1u);
        phbits ^= (1u << cb);
        __syncthreads();
        const __nv_bfloat16* swh = smb + WB_UNIT + cb * 16384;   // hi half
        const __nv_bfloat16* swl = swh + 8192;                    // lo half
#pragma unroll
        for (int kk = 0; kk < 2; ++kk) {
            const int kg = c * 32 + kk * 16;
            const __nv_bfloat16* ah_p = INh + (mrow + g) * AS + kg + 2 * t;
            const __nv_bfloat16* al_p = INl + (mrow + g) * AS + kg + 2 * t;
            unsigned ah[4], al[4];
            ah[0] = *reinterpret_cast<const unsigned*>(ah_p);
            ah[1] = *reinterpret_cast<const unsigned*>(ah_p + 8 * AS);
            ah[2] = *reinterpret_cast<const unsigned*>(ah_p + 8);
            ah[3] = *reinterpret_cast<const unsigned*>(ah_p + 8 * AS + 8);
            al[0] = *reinterpret_cast<const unsigned*>(al_p);
            al[1] = *reinterpret_cast<const unsigned*>(al_p + 8 * AS);
            al[2] = *reinterpret_cast<const unsigned*>(al_p + 8);
            al[3] = *reinterpret_cast<const unsigned*>(al_p + 8 * AS + 8);
            const int krow = kk * 16 + krow_l;
            const int swz = (krow & 7);
            const int rbase = krow * 256;
#pragma unroll
            for (int p = 0; p < 2; ++p) {
                const int ncol = (q << 5) + (p << 4) + nc_l;
                const int off = rbase + ((((ncol >> 3) ^ swz)) << 3);
                unsigned bh[4], bl[4];
                ldsm4t(bh, swh + off);
                ldsm4t(bl, swl + off);
                mma_bf16(acc[2 * p],     ah, bh[0], bh[1]);
                mma_bf16(acc[2 * p],     ah, bl[0], bl[1]);
                mma_bf16(acc[2 * p],     al, bh[0], bh[1]);
                mma_bf16(acc[2 * p + 1], ah, bh[2], bh[3]);
                mma_bf16(acc[2 * p + 1], ah, bl[2], bl[3]);
                mma_bf16(acc[2 * p + 1], al, bh[2], bh[3]);
            }
        }
    }
    gc += NCH;

    // epilogue: bias + mish (MUFU-free), split-store
#pragma unroll
    for (int nt = 0; nt < 4; ++nt) {
        const int col = (q << 5) + (nt << 3) + 2 * t;
        float b0v = bias[col], b1v = bias[col + 1];
        float v00 = mish_f(acc[nt][0] + b0v);
        float v01 = mish_f(acc[nt][1] + b1v);
        float v10 = mish_f(acc[nt][2] + b0v);
        float v11 = mish_f(acc[nt][3] + b1v);
        store_split2(OUTh, OUTl, (mrow + g) * AS + col, v00, v01);
        store_split2(OUTh, OUTl, (mrow + g + 8) * AS + col, v10, v11);
    }
}

// ------- init: split fp32 weights -> swizzled interleaved bf16 hi/lo chunks --
__global__ void split_weights(const float* __restrict__ w0,
                              const float* __restrict__ w1,
                              const float* __restrict__ w2) {
    int idx = blockIdx.x * blockDim.x + threadIdx.x;
    if (idx >= NCHUNK_TOT * 8192) return;
    int gch = idx >> 13;
    int r   = (idx >> 8) & 31;
    int n   = idx & 255;
    float v;
    if (gch < 6) {
        int k = gch * 32 + r;
        v = (k < 176) ? w0[k * 256 + n] : 0.f;
    } else if (gch < 14) {
        int k = (gch - 6) * 32 + r;
        v = w1[k * 256 + n];
    } else {
        int k = (gch - 14) * 32 + r;
        v = w2[k * 256 + n];
    }
    __nv_bfloat16 hi = __float2bfloat16(v);
    __nv_bfloat16 lo = __float2bfloat16(v - __bfloat162float(hi));
    int pos = gch * 16384 + r * 256 + (((n >> 3) ^ (r & 7)) << 3) + (n & 7);
    g_w[pos] = hi;
    g_w[pos + 8192] = lo;
}

// ------- init: per-step coefficients + time-MLP output (same math as before) -
__global__ void precompute(const float* __restrict__ w_t1,
                           const float* __restrict__ b_t1,
                           const float* __restrict__ w_t2,
                           const float* __restrict__ b_t2) {
    int i = blockIdx.x * blockDim.x + threadIdx.x;
    if (i >= 1000) return;
    double nn    = (double)(i + 1);
    double ac    = exp(-1e-4 * nn - 4.95e-6 * nn * nn);
    double nm    = nn - 1.0;
    double acp   = (i == 0) ? 1.0 : exp(-1e-4 * nm - 4.95e-6 * nm * nm);
    double beta  = 1.0 - exp(-1e-4 - 4.95e-6 * (2.0 * nn - 1.0));
    double alpha = 1.0 - beta;
    g_cf[i * 8 + 0] = (float)sqrt(1.0 / ac);
    g_cf[i * 8 + 1] = (float)sqrt(1.0 / ac - 1.0);
    g_cf[i * 8 + 2] = (float)(beta * sqrt(acp) / (1.0 - ac));
    g_cf[i * 8 + 3] = (float)((1.0 - acp) * sqrt(alpha) / (1.0 - ac));
    double pv = beta * (1.0 - acp) / (1.0 - ac);
    if (pv < 1e-20) pv = 1e-20;
    float lv = (float)log(pv);
    g_cf[i * 8 + 4] = (float)exp((double)(0.5f * lv));
    unsigned a0 = 0u, a1 = (unsigned)i;
    threefry2x32(0u, 1u, a0, a1);
    g_cf[i * 8 + 5] = __uint_as_float(a0);
    g_cf[i * 8 + 6] = __uint_as_float(a1);
    float te[16];
    for (int t = 0; t < 8; ++t) {
        float c8   = (float)(-9.210340371976184 / 7.0);
        float freq = expf(c8 * (float)t);
        float ang  = (float)i * freq;
        te[t]     = (float)sin((double)ang);
        te[t + 8] = (float)cos((double)ang);
    }
    float ht[32];
    for (int j = 0; j < 32; ++j) {
        float h = b_t1[j];
        for (int k = 0; k < 16; ++k) h = fmaf(te[k], w_t1[k * 32 + j], h);
        ht[j] = mish_f(h);
    }
    for (int j = 0; j < 16; ++j) {
        float v = b_t2[j];
        for (int k = 0; k < 32; ++k) v = fmaf(ht[k], w_t2[k * 16 + j], v);
        g_tf[i * 16 + j] = v;
    }
}

// ---------------- persistent sampler -----------------------------------------
__global__ void __launch_bounds__(NT, 1)
diff_all(const float* __restrict__ state, const float* __restrict__ x_init,
         const float* __restrict__ b0,  const float* __restrict__ b1,
         const float* __restrict__ b2,
         const float* __restrict__ wf,  const float* __restrict__ bf,
         float* __restrict__ outp)
{
    extern __shared__ __align__(16) char smraw[];
    float* smf = reinterpret_cast<float*>(smraw);
    __nv_bfloat16* smb = reinterpret_cast<__nv_bfloat16*>(smraw);
    unsigned smem_u32 = (unsigned)__cvta_generic_to_shared(smraw);

    float* XS  = smf + F_XS;
    __nv_bfloat16* A0h = smb + B_A0H;  __nv_bfloat16* A0l = smb + B_A0L;
    __nv_bfloat16* A1h = smb + B_A1H;  __nv_bfloat16* A1l = smb + B_A1L;
    __nv_bfloat16* WFH = smb + WFH_UNIT;
    __nv_bfloat16* WFL = smb + WFL_UNIT;

    const int tid = threadIdx.x;
    const int r0  = blockIdx.x * BR;

    if (tid == 0) {
#pragma unroll
        for (int b = 0; b < 3; ++b) MBAR_INIT(smem_u32 + MBAR_BYTE + 8u * b, 1u);
    }
    for (int idx = tid; idx < BR * 32; idx += NT) {
        int r = idx >> 5, c = idx & 31;
        XS[r * 33 + c] = x_init[(r0 + r) * 32 + c];
    }
    // one-time: final-layer weights -> smem bf16 hi/lo, row stride 40
    for (int idx = tid; idx < 256 * 32; idx += NT) {
        int k = idx >> 5, n = idx & 31;
        float v = wf[idx];
        __nv_bfloat16 hi = __float2bfloat16(v);
        __nv_bfloat16 lo = __float2bfloat16(v - __bfloat162float(hi));
        WFH[k * 40 + n] = hi;
        WFL[k * 40 + n] = lo;
    }
    __syncthreads();

    int gc = 0;
    unsigned phbits = 0;

#pragma unroll 1
    for (int i = 999; i >= 0; --i) {
        // ---- rebuild A0 (aliased by layer-2 output last step)
        for (int idx = tid; idx < 32 * 48; idx += NT) {
            int r = idx & 31, c = idx >> 5;
            float v = (c < 32) ? XS[r * 33 + c] : __ldg(&g_tf[i * 16 + (c - 32)]);
            __nv_bfloat16 hi = __float2bfloat16(v);
            __nv_bfloat16 lo = __float2bfloat16(v - __bfloat162float(hi));
            A0h[r * AS + c] = hi;
            A0l[r * AS + c] = lo;
        }
        for (int idx = tid; idx < 32 * 128; idx += NT) {
            int r = idx >> 7, c = idx & 127;
            float v = state[(r0 + r) * 128 + c];
            __nv_bfloat16 hi = __float2bfloat16(v);
            __nv_bfloat16 lo = __float2bfloat16(v - __bfloat162float(hi));
            A0h[r * AS + 48 + c] = hi;
            A0l[r * AS + 48 + c] = lo;
        }
        for (int idx = tid; idx < 32 * 16; idx += NT) {
            int r = idx >> 4, c = idx & 15;
            __nv_bfloat16 z = __float2bfloat16(0.f);
            A0h[r * AS + 176 + c] = z;
            A0l[r * AS + 176 + c] = z;
        }

        gemm_layer<6>(g_w,              b0, A0h, A0l, A1h, A1l, smb, smem_u32, gc, phbits, tid);
        gemm_layer<8>(g_w + 6  * 16384, b1, A1h, A1l, A0h, A0l, smb, smem_u32, gc, phbits, tid);
        gemm_layer<8>(g_w + 14 * 16384, b2, A0h, A0l, A1h, A1l, smb, smem_u32, gc, phbits, tid);
        __syncthreads();

        // ---- final 256->32 via split-bf16 mma: warps 0-7, one m16n8 tile each
        if (tid < 256) {
            const int w = tid >> 5, lane = tid & 31;
            const int g = lane >> 2, t = lane & 3;
            const int mrow = (w & 1) << 4;      // 0 or 16
            const int nq = w >> 1;               // 0..3 -> cols 8*nq
            const int krow_l = (lane & 7) + ((lane >> 3) & 1) * 8;

            float aHH[4] = {0.f, 0.f, 0.f, 0.f};
            float aHL[4] = {0.f, 0.f, 0.f, 0.f};
            float aLH[4] = {0.f, 0.f, 0.f, 0.f};
#pragma unroll
            for (int ks = 0; ks < 16; ++ks) {
                const int kg = ks * 16;
                const __nv_bfloat16* ah_p = A1h + (mrow + g) * AS + kg + 2 * t;
                const __nv_bfloat16* al_p = A1l + (mrow + g) * AS + kg + 2 * t;
                unsigned ah[4], al[4];
                ah[0] = *reinterpret_cast<const unsigned*>(ah_p);
                ah[1] = *reinterpret_cast<const unsigned*>(ah_p + 8 * AS);
                ah[2] = *reinterpret_cast<const unsigned*>(ah_p + 8);
                ah[3] = *reinterpret_cast<const unsigned*>(ah_p + 8 * AS + 8);
                al[0] = *reinterpret_cast<const unsigned*>(al_p);
                al[1] = *reinterpret_cast<const unsigned*>(al_p + 8 * AS);
                al[2] = *reinterpret_cast<const unsigned*>(al_p + 8);
                al[3] = *reinterpret_cast<const unsigned*>(al_p + 8 * AS + 8);
                unsigned bh[2], bl[2];
                const int wfo = (kg + krow_l) * 40 + nq * 8;
                ldsm2t(bh, WFH + wfo);
                ldsm2t(bl, WFL + wfo);
                mma_bf16(aHH, ah, bh[0], bh[1]);
                mma_bf16(aHL, ah, bl[0], bl[1]);
                mma_bf16(aLH, al, bh[0], bh[1]);
            }

            const int c0 = nq * 8 + 2 * t;
            float bfc0 = __ldg(bf + c0), bfc1 = __ldg(bf + c0 + 1);
            float epsv[4] = {
                aHH[0] + aHL[0] + aLH[0] + bfc0,
                aHH[1] + aHL[1] + aLH[1] + bfc1,
                aHH[2] + aHL[2] + aLH[2] + bfc0,
                aHH[3] + aHL[3] + aLH[3] + bfc1 };

            const float* cf = &g_cf[i * 8];
            float sr  = __ldg(cf + 0), srm1 = __ldg(cf + 1);
            float c1  = __ldg(cf + 2), c2   = __ldg(cf + 3);
            float sig = __ldg(cf + 4);
            unsigned fk0 = __float_as_uint(__ldg(cf + 5));
            unsigned fk1 = __float_as_uint(__ldg(cf + 6));

#pragma unroll
            for (int rr = 0; rr < 2; ++rr) {
                const int row = mrow + g + rr * 8;
                const int R = r0 + row;
#pragma unroll
                for (int cc = 0; cc < 2; ++cc) {
                    const int j = c0 + cc;
                    float e  = epsv[rr * 2 + cc];
                    float xv = XS[row * 33 + j];
                    float x0 = fminf(1.f, fmaxf(-1.f, sr * xv - srm1 * e));
                    float mean = c1 * x0 + c2 * xv;
                    if (i != 0) {
                        unsigned f = (unsigned)(R * 32 + j);
                        unsigned b0r = 0u, b1r = f;
                        threefry2x32(fk0, fk1, b0r, b1r);
                        unsigned bits = b0r ^ b1r;
                        float fv = __uint_as_float((bits >> 9) | 0x3f800000u) - 1.0f;
                        const float lo = -0.99999994f;
                        float u   = fmaxf(lo, fmaf(fv, 2.0f, lo));
                        float nrm = 1.4142135623730951f * erfinv_xla(u);
                        XS[row * 33 + j] = mean + sig * nrm;
                    } else {
                        float xf = fminf(1.f, fmaxf(-1.f, mean));
                        XS[row * 33 + j] = xf;
                        outp[R * 32 + j] = xf;
                    }
                }
            }
        }
        __syncthreads();
    }
}

extern "C" void kernel_launch(void* const* d_in, const int* in_sizes, int n_in,
                              void* d_out, int out_size) {
    const float* state = (const float*)d_in[0];
    const float* xinit = (const float*)d_in[1];
    const float* w_t1  = (const float*)d_in[2];
    const float* b_t1  = (const float*)d_in[3];
    const float* w_t2  = (const float*)d_in[4];
    const float* b_t2  = (const float*)d_in[5];
    const float* w0    = (const float*)d_in[6];
    const float* b0    = (const float*)d_in[7];
    const float* w1    = (const float*)d_in[8];
    const float* b1    = (const float*)d_in[9];
    const float* w2    = (const float*)d_in[10];
    const float* b2    = (const float*)d_in[11];
    const float* wf    = (const float*)d_in[12];
    const float* bf    = (const float*)d_in[13];
    float* outp = (float*)d_out;

    cudaFuncSetAttribute(diff_all, cudaFuncAttributeMaxDynamicSharedMemorySize, SMEM_BYTES);

    split_weights<<<(NCHUNK_TOT * 8192 + 255) / 256, 256>>>(w0, w1, w2);
    precompute<<<4, 256>>>(w_t1, b_t1, w_t2, b_t2);
    diff_all<<<NB, NT, SMEM_BYTES>>>(state, xinit,
        b0, b1, b2, wf, bf, outp);
}

// round 14
// speedup vs baseline: 2.0423x; 1.0172x over previous
#include <cuda_runtime.h>
#include <cuda_bf16.h>
#include <math.h>

#define NB 128
#define NT 512
#define BR 32
#define AS  264     // activation row stride (bf16 units) = 528B (conflict-free LDS)

// ---- smem layout ----
#define F_XS  0                    // 32*33 fp32 x state
#define MBAR_BYTE 4224             // 3 x 8B mbarriers
#define B_A0H 2176
#define B_A0L 10624
#define B_A1H 19072
#define B_A1L 27520
#define WFH_UNIT 35968             // final weights hi, [256][40]
#define WFL_UNIT 46208
#define WB_BYTE 112896
#define WB_UNIT 56448
#define SMEM_BYTES (112896 + 3*32768)

// pre-split trunk weights: 22 chunks x (16KB hi + 16KB lo), XOR-swizzled, contiguous
#define NCHUNK_TOT 22
#define W_ELEMS (NCHUNK_TOT * 16384)
__device__ __align__(128) __nv_bfloat16 g_w[W_ELEMS];
__device__ float g_cf[1000 * 8];
__device__ float g_tf[1000 * 16];

// ---------------- threefry2x32-20 (exact JAX) ------------------------------
__device__ __forceinline__ unsigned rotl32(unsigned x, int r) {
    return __funnelshift_l(x, x, r);
}
__device__ __forceinline__ void threefry2x32(unsigned k0, unsigned k1,
                                             unsigned &x0, unsigned &x1) {
    unsigned k2 = k0 ^ k1 ^ 0x1BD11BDAu;
#define TFR(r) { x0 += x1; x1 = rotl32(x1, r); x1 ^= x0; }
    x0 += k0; x1 += k1;
    TFR(13) TFR(15) TFR(26) TFR(6)
    x0 += k1; x1 += k2 + 1u;
    TFR(17) TFR(29) TFR(16) TFR(24)
    x0 += k2; x1 += k0 + 2u;
    TFR(13) TFR(15) TFR(26) TFR(6)
    x0 += k0; x1 += k1 + 3u;
    TFR(17) TFR(29) TFR(16) TFR(24)
    x0 += k1; x1 += k2 + 4u;
    TFR(13) TFR(15) TFR(26) TFR(6)
    x0 += k2; x1 += k0 + 5u;
#undef TFR
}

// ---------------- XLA ErfInv f32 (Giles) ------------------------------------
__device__ __forceinline__ float erfinv_xla(float x) {
    float w = -log1pf(-x * x);
    float p;
    if (w < 5.0f) {
        w -= 2.5f;
        p = 2.81022636e-08f;
        p = fmaf(p, w, 3.43273939e-07f);
        p = fmaf(p, w, -3.5233877e-06f);
        p = fmaf(p, w, -4.39150654e-06f);
        p = fmaf(p, w, 0.00021858087f);
        p = fmaf(p, w, -0.00125372503f);
        p = fmaf(p, w, -0.00417768164f);
        p = fmaf(p, w, 0.246640727f);
        p = fmaf(p, w, 1.50140941f);
    } else {
        w = sqrtf(w) - 3.0f;
        p = -0.000200214257f;
        p = fmaf(p, w, 0.000100950558f);
        p = fmaf(p, w, 0.00134934322f);
        p = fmaf(p, w, -0.00367342844f);
        p = fmaf(p, w, 0.00573950773f);
        p = fmaf(p, w, -0.0076224613f);
        p = fmaf(p, w, 0.00943887047f);
        p = fmaf(p, w, 1.00167406f);
        p = fmaf(p, w, 2.83297682f);
    }
    return p * x;
}

// ---------------- MUFU-free mish -------------------------------------------
__device__ __forceinline__ float exp_fma(float x) {
    float y = x * 1.4426950408889634f;
    y = fmaxf(y, -120.0f);
    float n = rintf(y);
    float f = y - n;
    float p =       1.5403530393381609e-4f;
    p = fmaf(p, f, 1.3333558146428443e-3f);
    p = fmaf(p, f, 9.6181298420718030e-3f);
    p = fmaf(p, f, 5.5504108664821580e-2f);
    p = fmaf(p, f, 2.4022650695910070e-1f);
    p = fmaf(p, f, 6.9314718055994530e-1f);
    p = fmaf(p, f, 1.0f);
    int e = (int)n;
    return p * __int_as_float((e + 127) << 23);
}
__device__ __forceinline__ float rcp_fma(float d) {
    float r = __int_as_float(0x7EF311C3 - __float_as_int(d));
    r = r * fmaf(-d, r, 2.0f);
    r = r * fmaf(-d, r, 2.0f);
    r = r * fmaf(-d, r, 2.0f);
    return r;
}
__device__ __forceinline__ float mish_f(float x) {
    if (x > 20.0f) return x;
    float u = exp_fma(x);
    float s = u * (u + 2.0f);
    return x * s * rcp_fma(s + 2.0f);
}

// ---------------- mbarrier + bulk-copy helpers --------------------------------
#define MBAR_INIT(addr, cnt) \
    asm volatile("mbarrier.init.shared.b64 [%0], %1;" :: "r"(addr), "r"(cnt) : "memory")
#define MBAR_EXPECT_TX(addr, bytes) \
    asm volatile("mbarrier.arrive.expect_tx.shared.b64 _, [%0], %1;" :: "r"(addr), "r"(bytes) : "memory")
#define MBAR_WAIT(addr, parity) do { \
    unsigned _done = 0; \
    while (!_done) { \
        asm volatile("{\n\t.reg .pred p;\n\t" \
            "mbarrier.try_wait.parity.acquire.cta.shared::cta.b64 p, [%1], %2, 0x989680;\n\t" \
            "selp.b32 %0, 1, 0, p;\n\t}" \
            : "=r"(_done) : "r"(addr), "r"(parity) : "memory"); \
    } } while (0)

__device__ __forceinline__ void bulk_stage(unsigned dst_smem,
                                           const __nv_bfloat16* src,
                                           unsigned mbar) {
    asm volatile(
        "cp.async.bulk.shared::cluster.global.mbarrier::complete_tx::bytes "
        "[%0], [%1], %2, [%3];"
        :: "r"(dst_smem), "l"(src), "r"(32768u), "r"(mbar) : "memory");
}

// ---------------- mma / ldmatrix wrappers ------------------------------------
__device__ __forceinline__ void mma_bf16(float* c, const unsigned* a,
                                         unsigned b0, unsigned b1) {
    asm volatile(
        "mma.sync.aligned.m16n8k16.row.col.f32.bf16.bf16.f32 "
        "{%0,%1,%2,%3}, {%4,%5,%6,%7}, {%8,%9}, {%0,%1,%2,%3};"
        : "+f"(c[0]), "+f"(c[1]), "+f"(c[2]), "+f"(c[3])
        : "r"(a[0]), "r"(a[1]), "r"(a[2]), "r"(a[3]), "r"(b0), "r"(b1));
}
__device__ __forceinline__ void ldsm4t(unsigned* r, const __nv_bfloat16* p) {
    unsigned addr = (unsigned)__cvta_generic_to_shared(p);
    asm volatile("ldmatrix.sync.aligned.m8n8.x4.trans.shared.b16 {%0,%1,%2,%3}, [%4];"
        : "=r"(r[0]), "=r"(r[1]), "=r"(r[2]), "=r"(r[3]) : "r"(addr));
}
__device__ __forceinline__ void ldsm2t(unsigned* r, const __nv_bfloat16* p) {
    unsigned addr = (unsigned)__cvta_generic_to_shared(p);
    asm volatile("ldmatrix.sync.aligned.m8n8.x2.trans.shared.b16 {%0,%1}, [%2];"
        : "=r"(r[0]), "=r"(r[1]) : "r"(addr));
}

__device__ __forceinline__ void store_split2(__nv_bfloat16* H, __nv_bfloat16* L,
                                             int off, float v0, float v1) {
    __nv_bfloat16 h0 = __float2bfloat16(v0), h1 = __float2bfloat16(v1);
    __nv_bfloat16 l0 = __float2bfloat16(v0 - __bfloat162float(h0));
    __nv_bfloat16 l1 = __float2bfloat16(v1 - __bfloat162float(h1));
    *reinterpret_cast<unsigned*>(H + off) =
        (unsigned)__bfloat16_as_ushort(h0) | ((unsigned)__bfloat16_as_ushort(h1) << 16);
    *reinterpret_cast<unsigned*>(L + off) =
        (unsigned)__bfloat16_as_ushort(l0) | ((unsigned)__bfloat16_as_ushort(l1) << 16);
}

// ------- split-bf16 dense layer; free-running depth-2 weight prefetch --------
// cb = current ring buffer (0..2), stg = next g_w chunk to stage (0..21).
template <int NCH>
__device__ __forceinline__ void gemm_layer(const float* __restrict__ bias,
                                           const __nv_bfloat16* INh,
                                           const __nv_bfloat16* INl,
                                           __nv_bfloat16* OUTh, __nv_bfloat16* OUTl,
                                           __nv_bfloat16* smb, unsigned smem_u32,
                                           int& cb, int& stg, unsigned& phbits,
                                           int tid) {
    const int lane = tid & 31, w = tid >> 5;    // 16 warps
    const int g = lane >> 2, t = lane & 3;
    const int mrow = (w & 1) << 4;              // 0 or 16
    const int q = w >> 1;                        // 0..7 -> cols 32q..32q+31
    const int krow_l = (lane & 7) + ((lane >> 3) & 1) * 8;
    const int nc_l = (lane >> 4) * 8;

    // two independent accumulator sets: aP = Ahi*Whi, aQ = Ahi*Wlo + Alo*Whi
    float aP[4][4], aQ[4][4];
#pragma unroll
    for (int i = 0; i < 4; ++i)
#pragma unroll
        for (int j = 0; j < 4; ++j) { aP[i][j] = 0.f; aQ[i][j] = 0.f; }

#pragma unroll 1
    for (int c = 0; c < NCH; ++c) {
        if (tid == 0) MBAR_WAIT(smem_u32 + MBAR_BYTE + 8u * cb, (phbits >> cb) & 1u);
        phbits ^= (1u << cb);
        __syncthreads();             // all saw chunk data; all finished buffer cb-1(=cb+2)
        if (tid == 0) {
            int sb = cb + 2; if (sb >= 3) sb -= 3;
            unsigned mb = smem_u32 + MBAR_BYTE + 8u * sb;
            MBAR_EXPECT_TX(mb, 32768u);
            bulk_stage(smem_u32 + WB_BYTE + 32768u * sb, g_w + stg * 16384, mb);
        }
        if (++stg == NCHUNK_TOT) stg = 0;

        const __nv_bfloat16* swh = smb + WB_UNIT + cb * 16384;   // hi half
        const __nv_bfloat16* swl = swh + 8192;                    // lo half
#pragma unroll
        for (int kk = 0; kk < 2; ++kk) {
            const int kg = c * 32 + kk * 16;
            const __nv_bfloat16* ah_p = INh + (mrow + g) * AS + kg + 2 * t;
            const __nv_bfloat16* al_p = INl + (mrow + g) * AS + kg + 2 * t;
            unsigned ah[4], al[4];
            ah[0] = *reinterpret_cast<const unsigned*>(ah_p);
            ah[1] = *reinterpret_cast<const unsigned*>(ah_p + 8 * AS);
            ah[2] = *reinterpret_cast<const unsigned*>(ah_p + 8);
            ah[3] = *reinterpret_cast<const unsigned*>(ah_p + 8 * AS + 8);
            al[0] = *reinterpret_cast<const unsigned*>(al_p);
            al[1] = *reinterpret_cast<const unsigned*>(al_p + 8 * AS);
            al[2] = *reinterpret_cast<const unsigned*>(al_p + 8);
            al[3] = *reinterpret_cast<const unsigned*>(al_p + 8 * AS + 8);
            const int krow = kk * 16 + krow_l;
            const int swz = (krow & 7);
            const int rbase = krow * 256;
#pragma unroll
            for (int p = 0; p < 2; ++p) {
                const int ncol = (q << 5) + (p << 4) + nc_l;
                const int off = rbase + ((((ncol >> 3) ^ swz)) << 3);
                unsigned bh[4], bl[4];
                ldsm4t(bh, swh + off);
                ldsm4t(bl, swl + off);
                mma_bf16(aP[2 * p],     ah, bh[0], bh[1]);
                mma_bf16(aQ[2 * p],     ah, bl[0], bl[1]);
                mma_bf16(aQ[2 * p],     al, bh[0], bh[1]);
                mma_bf16(aP[2 * p + 1], ah, bh[2], bh[3]);
                mma_bf16(aQ[2 * p + 1], ah, bl[2], bl[3]);
                mma_bf16(aQ[2 * p + 1], al, bh[2], bh[3]);
            }
        }
        if (++cb == 3) cb = 0;
    }

    // epilogue: merge sets + bias + mish, split-store
#pragma unroll
    for (int nt = 0; nt < 4; ++nt) {
        const int col = (q << 5) + (nt << 3) + 2 * t;
        float b0v = bias[col], b1v = bias[col + 1];
        float v00 = mish_f(aP[nt][0] + aQ[nt][0] + b0v);
        float v01 = mish_f(aP[nt][1] + aQ[nt][1] + b1v);
        float v10 = mish_f(aP[nt][2] + aQ[nt][2] + b0v);
        float v11 = mish_f(aP[nt][3] + aQ[nt][3] + b1v);
        store_split2(OUTh, OUTl, (mrow + g) * AS + col, v00, v01);
        store_split2(OUTh, OUTl, (mrow + g + 8) * AS + col, v10, v11);
    }
}

// ------- init: split fp32 weights -> swizzled interleaved bf16 hi/lo chunks --
__global__ void split_weights(const float* __restrict__ w0,
                              const float* __restrict__ w1,
                              const float* __restrict__ w2) {
    int idx = blockIdx.x * blockDim.x + threadIdx.x;
    if (idx >= NCHUNK_TOT * 8192) return;
    int gch = idx >> 13;
    int r   = (idx >> 8) & 31;
    int n   = idx & 255;
    float v;
    if (gch < 6) {
        int k = gch * 32 + r;
        v = (k < 176) ? w0[k * 256 + n] : 0.f;
    } else if (gch < 14) {
        int k = (gch - 6) * 32 + r;
        v = w1[k * 256 + n];
    } else {
        int k = (gch - 14) * 32 + r;
        v = w2[k * 256 + n];
    }
    __nv_bfloat16 hi = __float2bfloat16(v);
    __nv_bfloat16 lo = __float2bfloat16(v - __bfloat162float(hi));
    int pos = gch * 16384 + r * 256 + (((n >> 3) ^ (r & 7)) << 3) + (n & 7);
    g_w[pos] = hi;
    g_w[pos + 8192] = lo;
}

// ------- init: per-step coefficients + time-MLP output -----------------------
__global__ void precompute(const float* __restrict__ w_t1,
                           const float* __restrict__ b_t1,
                           const float* __restrict__ w_t2,
                           const float* __restrict__ b_t2) {
    int i = blockIdx.x * blockDim.x + threadIdx.x;
    if (i >= 1000) return;
    double nn    = (double)(i + 1);
    double ac    = exp(-1e-4 * nn - 4.95e-6 * nn * nn);
    double nm    = nn - 1.0;
    double acp   = (i == 0) ? 1.0 : exp(-1e-4 * nm - 4.95e-6 * nm * nm);
    double beta  = 1.0 - exp(-1e-4 - 4.95e-6 * (2.0 * nn - 1.0));
    double alpha = 1.0 - beta;
    g_cf[i * 8 + 0] = (float)sqrt(1.0 / ac);
    g_cf[i * 8 + 1] = (float)sqrt(1.0 / ac - 1.0);
    g_cf[i * 8 + 2] = (float)(beta * sqrt(acp) / (1.0 - ac));
    g_cf[i * 8 + 3] = (float)((1.0 - acp) * sqrt(alpha) / (1.0 - ac));
    double pv = beta * (1.0 - acp) / (1.0 - ac);
    if (pv < 1e-20) pv = 1e-20;
    float lv = (float)log(pv);
    g_cf[i * 8 + 4] = (float)exp((double)(0.5f * lv));
    unsigned a0 = 0u, a1 = (unsigned)i;
    threefry2x32(0u, 1u, a0, a1);
    g_cf[i * 8 + 5] = __uint_as_float(a0);
    g_cf[i * 8 + 6] = __uint_as_float(a1);
    float te[16];
    for (int t = 0; t < 8; ++t) {
        float c8   = (float)(-9.210340371976184 / 7.0);
        float freq = expf(c8 * (float)t);
        float ang  = (float)i * freq;
        te[t]     = (float)sin((double)ang);
        te[t + 8] = (float)cos((double)ang);
    }
    float ht[32];
    for (int j = 0; j < 32; ++j) {
        float h = b_t1[j];
        for (int k = 0; k < 16; ++k) h = fmaf(te[k], w_t1[k * 32 + j], h);
        ht[j] = mish_f(h);
    }
    for (int j = 0; j < 16; ++j) {
        float v = b_t2[j];
        for (int k = 0; k < 32; ++k) v = fmaf(ht[k], w_t2[k * 16 + j], v);
        g_tf[i * 16 + j] = v;
    }
}

// ---------------- persistent sampler -----------------------------------------
__global__ void __launch_bounds__(NT, 1)
diff_all(const float* __restrict__ state, const float* __restrict__ x_init,
         const float* __restrict__ b0,  const float* __restrict__ b1,
         const float* __restrict__ b2,
         const float* __restrict__ wf,  const float* __restrict__ bf,
         float* __restrict__ outp)
{
    extern __shared__ __align__(16) char smraw[];
    float* smf = reinterpret_cast<float*>(smraw);
    __nv_bfloat16* smb = reinterpret_cast<__nv_bfloat16*>(smraw);
    unsigned smem_u32 = (unsigned)__cvta_generic_to_shared(smraw);

    float* XS  = smf + F_XS;
    __nv_bfloat16* A0h = smb + B_A0H;  __nv_bfloat16* A0l = smb + B_A0L;
    __nv_bfloat16* A1h = smb + B_A1H;  __nv_bfloat16* A1l = smb + B_A1L;
    __nv_bfloat16* WFH = smb + WFH_UNIT;
    __nv_bfloat16* WFL = smb + WFL_UNIT;

    const int tid = threadIdx.x;
    const int r0  = blockIdx.x * BR;

    if (tid == 0) {
#pragma unroll
        for (int b = 0; b < 3; ++b) MBAR_INIT(smem_u32 + MBAR_BYTE + 8u * b, 1u);
    }
    for (int idx = tid; idx < BR * 32; idx += NT) {
        int r = idx >> 5, c = idx & 31;
        XS[r * 33 + c] = x_init[(r0 + r) * 32 + c];
    }
    for (int idx = tid; idx < 256 * 32; idx += NT) {
        int k = idx >> 5, n = idx & 31;
        float v = wf[idx];
        __nv_bfloat16 hi = __float2bfloat16(v);
        __nv_bfloat16 lo = __float2bfloat16(v - __bfloat162float(hi));
        WFH[k * 40 + n] = hi;
        WFL[k * 40 + n] = lo;
    }
    __syncthreads();

    // ---- pipeline fill: stage chunks 0,1 into buffers 0,1
    if (tid == 0) {
#pragma unroll
        for (int b = 0; b < 2; ++b) {
            unsigned mb = smem_u32 + MBAR_BYTE + 8u * b;
            MBAR_EXPECT_TX(mb, 32768u);
            bulk_stage(smem_u32 + WB_BYTE + 32768u * b, g_w + b * 16384, mb);
        }
    }
    int cb = 0, stg = 2;
    unsigned phbits = 0;

#pragma unroll 1
    for (int i = 999; i >= 0; --i) {
        // ---- rebuild A0 (aliased by layer-2 output last step)
        for (int idx = tid; idx < 32 * 48; idx += NT) {
            int r = idx & 31, c = idx >> 5;
            float v = (c < 32) ? XS[r * 33 + c] : __ldg(&g_tf[i * 16 + (c - 32)]);
            __nv_bfloat16 hi = __float2bfloat16(v);
            __nv_bfloat16 lo = __float2bfloat16(v - __bfloat162float(hi));
            A0h[r * AS + c] = hi;
            A0l[r * AS + c] = lo;
        }
        for (int idx = tid; idx < 32 * 128; idx += NT) {
            int r = idx >> 7, c = idx & 127;
            float v = state[(r0 + r) * 128 + c];
            __nv_bfloat16 hi = __float2bfloat16(v);
            __nv_bfloat16 lo = __float2bfloat16(v - __bfloat162float(hi));
            A0h[r * AS + 48 + c] = hi;
            A0l[r * AS + 48 + c] = lo;
        }
        for (int idx = tid; idx < 32 * 16; idx += NT) {
            int r = idx >> 4, c = idx & 15;
            __nv_bfloat16 z = __float2bfloat16(0.f);
            A0h[r * AS + 176 + c] = z;
            A0l[r * AS + 176 + c] = z;
        }

        gemm_layer<6>(b0, A0h, A0l, A1h, A1l, smb, smem_u32, cb, stg, phbits, tid);
        gemm_layer<8>(b1, A1h, A1l, A0h, A0l, smb, smem_u32, cb, stg, phbits, tid);
        gemm_layer<8>(b2, A0h, A0l, A1h, A1l, smb, smem_u32, cb, stg, phbits, tid);
        __syncthreads();

        // ---- final 256->32 via split-bf16 mma: warps 0-7, one m16n8 tile each
        if (tid < 256) {
            const int w = tid >> 5, lane = tid & 31;
            const int g = lane >> 2, t = lane & 3;
            const int mrow = (w & 1) << 4;
            const int nq = w >> 1;
            const int krow_l = (lane & 7) + ((lane >> 3) & 1) * 8;

            float aHH[4] = {0.f, 0.f, 0.f, 0.f};
            float aHL[4] = {0.f, 0.f, 0.f, 0.f};
            float aLH[4] = {0.f, 0.f, 0.f, 0.f};
#pragma unroll
            for (int ks = 0; ks < 16; ++ks) {
                const int kg = ks * 16;
                const __nv_bfloat16* ah_p = A1h + (mrow + g) * AS + kg + 2 * t;
                const __nv_bfloat16* al_p = A1l + (mrow + g) * AS + kg + 2 * t;
                unsigned ah[4], al[4];
                ah[0] = *reinterpret_cast<const unsigned*>(ah_p);
                ah[1] = *reinterpret_cast<const unsigned*>(ah_p + 8 * AS);
                ah[2] = *reinterpret_cast<const unsigned*>(ah_p + 8);
                ah[3] = *reinterpret_cast<const unsigned*>(ah_p + 8 * AS + 8);
                al[0] = *reinterpret_cast<const unsigned*>(al_p);
                al[1] = *reinterpret_cast<const unsigned*>(al_p + 8 * AS);
                al[2] = *reinterpret_cast<const unsigned*>(al_p + 8);
                al[3] = *reinterpret_cast<const unsigned*>(al_p + 8 * AS + 8);
                unsigned bh[2], bl[2];
                const int wfo = (kg + krow_l) * 40 + nq * 8;
                ldsm2t(bh, WFH + wfo);
                ldsm2t(bl, WFL + wfo);
                mma_bf16(aHH, ah, bh[0], bh[1]);
                mma_bf16(aHL, ah, bl[0], bl[1]);
                mma_bf16(aLH, al, bh[0], bh[1]);
            }

            const int c0 = nq * 8 + 2 * t;
            float bfc0 = __ldg(bf + c0), bfc1 = __ldg(bf + c0 + 1);
            float epsv[4] = {
                aHH[0] + aHL[0] + aLH[0] + bfc0,
                aHH[1] + aHL[1] + aLH[1] + bfc1,
                aHH[2] + aHL[2] + aLH[2] + bfc0,
                aHH[3] + aHL[3] + aLH[3] + bfc1 };

            const float* cf = &g_cf[i * 8];
            float sr  = __ldg(cf + 0), srm1 = __ldg(cf + 1);
            float c1  = __ldg(cf + 2), c2   = __ldg(cf + 3);
            float sig = __ldg(cf + 4);
            unsigned fk0 = __float_as_uint(__ldg(cf + 5));
            unsigned fk1 = __float_as_uint(__ldg(cf + 6));

#pragma unroll
            for (int rr = 0; rr < 2; ++rr) {
                const int row = mrow + g + rr * 8;
                const int R = r0 + row;
#pragma unroll
                for (int cc = 0; cc < 2; ++cc) {
                    const int j = c0 + cc;
                    float e  = epsv[rr * 2 + cc];
                    float xv = XS[row * 33 + j];
                    float x0 = fminf(1.f, fmaxf(-1.f, sr * xv - srm1 * e));
                    float mean = c1 * x0 + c2 * xv;
                    if (i != 0) {
                        unsigned f = (unsigned)(R * 32 + j);
                        unsigned b0r = 0u, b1r = f;
                        threefry2x32(fk0, fk1, b0r, b1r);
                        unsigned bits = b0r ^ b1r;
                        float fv = __uint_as_float((bits >> 9) | 0x3f800000u) - 1.0f;
                        const float lo = -0.99999994f;
                        float u   = fmaxf(lo, fmaf(fv, 2.0f, lo));
                        float nrm = 1.4142135623730951f * erfinv_xla(u);
                        XS[row * 33 + j] = mean + sig * nrm;
                    } else {
                        float xf = fminf(1.f, fmaxf(-1.f, mean));
                        XS[row * 33 + j] = xf;
                        outp[R * 32 + j] = xf;
                    }
                }
            }
        }
        __syncthreads();
    }
}

extern "C" void kernel_launch(void* const* d_in, const int* in_sizes, int n_in,
                              void* d_out, int out_size) {
    const float* state = (const float*)d_in[0];
    const float* xinit = (const float*)d_in[1];
    const float* w_t1  = (const float*)d_in[2];
    const float* b_t1  = (const float*)d_in[3];
    const float* w_t2  = (const float*)d_in[4];
    const float* b_t2  = (const float*)d_in[5];
    const float* w0    = (const float*)d_in[6];
    const float* b0    = (const float*)d_in[7];
    const float* w1    = (const float*)d_in[8];
    const float* b1    = (const float*)d_in[9];
    const float* w2    = (const float*)d_in[10];
    const float* b2    = (const float*)d_in[11];
    const float* wf    = (const float*)d_in[12];
    const float* bf    = (const float*)d_in[13];
    float* outp = (float*)d_out;

    cudaFuncSetAttribute(diff_all, cudaFuncAttributeMaxDynamicSharedMemorySize, SMEM_BYTES);

    split_weights<<<(NCHUNK_TOT * 8192 + 255) / 256, 256>>>(w0, w1, w2);
    precompute<<<4, 256>>>(w_t1, b_t1, w_t2, b_t2);
    diff_all<<<NB, NT, SMEM_BYTES>>>(state, xinit,
        b0, b1, b2, wf, bf, outp);
}

// round 15
// speedup vs baseline: 2.5299x; 1.2387x over previous
#include <cuda_runtime.h>
#include <cuda_bf16.h>
#include <math.h>

#define NB 128
#define NT 512
#define BR 32
#define AS  264     // activation row stride (bf16 units) = 528B (conflict-free LDS)

// ---- smem layout ----
#define F_XS  0                    // 32*33 fp32 x state
#define MBAR_BYTE 4224             // full[3] @ +0,8,16 ; empty[3] @ +24,32,40
#define B_A0H 2176
#define B_A0L 10624
#define B_A1H 19072
#define B_A1L 27520
#define WFH_UNIT 35968             // final weights hi, [256][40]
#define WFL_UNIT 46208
#define WB_BYTE 112896
#define WB_UNIT 56448
#define SMEM_BYTES (112896 + 3*32768)

// pre-split trunk weights: 22 chunks x (16KB hi + 16KB lo), XOR-swizzled, contiguous
#define NCHUNK_TOT 22
#define W_ELEMS (NCHUNK_TOT * 16384)
__device__ __align__(128) __nv_bfloat16 g_w[W_ELEMS];
__device__ float g_cf[1000 * 8];
__device__ float g_tf[1000 * 16];

// ---------------- threefry2x32-20 (exact JAX) ------------------------------
__device__ __forceinline__ unsigned rotl32(unsigned x, int r) {
    return __funnelshift_l(x, x, r);
}
__device__ __forceinline__ void threefry2x32(unsigned k0, unsigned k1,
                                             unsigned &x0, unsigned &x1) {
    unsigned k2 = k0 ^ k1 ^ 0x1BD11BDAu;
#define TFR(r) { x0 += x1; x1 = rotl32(x1, r); x1 ^= x0; }
    x0 += k0; x1 += k1;
    TFR(13) TFR(15) TFR(26) TFR(6)
    x0 += k1; x1 += k2 + 1u;
    TFR(17) TFR(29) TFR(16) TFR(24)
    x0 += k2; x1 += k0 + 2u;
    TFR(13) TFR(15) TFR(26) TFR(6)
    x0 += k0; x1 += k1 + 3u;
    TFR(17) TFR(29) TFR(16) TFR(24)
    x0 += k1; x1 += k2 + 4u;
    TFR(13) TFR(15) TFR(26) TFR(6)
    x0 += k2; x1 += k0 + 5u;
#undef TFR
}

// ---------------- XLA ErfInv f32 (Giles) ------------------------------------
__device__ __forceinline__ float erfinv_xla(float x) {
    float w = -log1pf(-x * x);
    float p;
    if (w < 5.0f) {
        w -= 2.5f;
        p = 2.81022636e-08f;
        p = fmaf(p, w, 3.43273939e-07f);
        p = fmaf(p, w, -3.5233877e-06f);
        p = fmaf(p, w, -4.39150654e-06f);
        p = fmaf(p, w, 0.00021858087f);
        p = fmaf(p, w, -0.00125372503f);
        p = fmaf(p, w, -0.00417768164f);
        p = fmaf(p, w, 0.246640727f);
        p = fmaf(p, w, 1.50140941f);
    } else {
        w = sqrtf(w) - 3.0f;
        p = -0.000200214257f;
        p = fmaf(p, w, 0.000100950558f);
        p = fmaf(p, w, 0.00134934322f);
        p = fmaf(p, w, -0.00367342844f);
        p = fmaf(p, w, 0.00573950773f);
        p = fmaf(p, w, -0.0076224613f);
        p = fmaf(p, w, 0.00943887047f);
        p = fmaf(p, w, 1.00167406f);
        p = fmaf(p, w, 2.83297682f);
    }
    return p * x;
}

// ---------------- MUFU-free mish -------------------------------------------
__device__ __forceinline__ float exp_fma(float x) {
    float y = x * 1.4426950408889634f;
    y = fmaxf(y, -120.0f);
    float n = rintf(y);
    float f = y - n;
    float p =       1.5403530393381609e-4f;
    p = fmaf(p, f, 1.3333558146428443e-3f);
    p = fmaf(p, f, 9.6181298420718030e-3f);
    p = fmaf(p, f, 5.5504108664821580e-2f);
    p = fmaf(p, f, 2.4022650695910070e-1f);
    p = fmaf(p, f, 6.9314718055994530e-1f);
    p = fmaf(p, f, 1.0f);
    int e = (int)n;
    return p * __int_as_float((e + 127) << 23);
}
__device__ __forceinline__ float rcp_fma(float d) {
    float r = __int_as_float(0x7EF311C3 - __float_as_int(d));
    r = r * fmaf(-d, r, 2.0f);
    r = r * fmaf(-d, r, 2.0f);
    r = r * fmaf(-d, r, 2.0f);
    return r;
}
__device__ __forceinline__ float mish_f(float x) {
    if (x > 20.0f) return x;
    float u = exp_fma(x);
    float s = u * (u + 2.0f);
    return x * s * rcp_fma(s + 2.0f);
}

// ---------------- mbarrier + bulk-copy helpers --------------------------------
#define MBAR_INIT(addr, cnt) \
    asm volatile("mbarrier.init.shared.b64 [%0], %1;" :: "r"(addr), "r"(cnt) : "memory")
#define MBAR_EXPECT_TX(addr, bytes) \
    asm volatile("mbarrier.arrive.expect_tx.shared.b64 _, [%0], %1;" :: "r"(addr), "r"(bytes) : "memory")
#define MBAR_ARRIVE(addr) \
    asm volatile("mbarrier.arrive.shared.b64 _, [%0];" :: "r"(addr) : "memory")
#define MBAR_WAIT(addr, parity) do { \
    unsigned _done = 0; \
    while (!_done) { \
        asm volatile("{\n\t.reg .pred p;\n\t" \
            "mbarrier.try_wait.parity.acquire.cta.shared::cta.b64 p, [%1], %2, 0x989680;\n\t" \
            "selp.b32 %0, 1, 0, p;\n\t}" \
            : "=r"(_done) : "r"(addr), "r"(parity) : "memory"); \
    } } while (0)

__device__ __forceinline__ void bulk_stage(unsigned dst_smem,
                                           const __nv_bfloat16* src,
                                           unsigned mbar) {
    asm volatile(
        "cp.async.bulk.shared::cluster.global.mbarrier::complete_tx::bytes "
        "[%0], [%1], %2, [%3];"
        :: "r"(dst_smem), "l"(src), "r"(32768u), "r"(mbar) : "memory");
}

// ---------------- mma / ldmatrix wrappers ------------------------------------
__device__ __forceinline__ void mma_bf16(float* c, const unsigned* a,
                                         unsigned b0, unsigned b1) {
    asm volatile(
        "mma.sync.aligned.m16n8k16.row.col.f32.bf16.bf16.f32 "
        "{%0,%1,%2,%3}, {%4,%5,%6,%7}, {%8,%9}, {%0,%1,%2,%3};"
        : "+f"(c[0]), "+f"(c[1]), "+f"(c[2]), "+f"(c[3])
        : "r"(a[0]), "r"(a[1]), "r"(a[2]), "r"(a[3]), "r"(b0), "r"(b1));
}
__device__ __forceinline__ void ldsm4t(unsigned* r, const __nv_bfloat16* p) {
    unsigned addr = (unsigned)__cvta_generic_to_shared(p);
    asm volatile("ldmatrix.sync.aligned.m8n8.x4.trans.shared.b16 {%0,%1,%2,%3}, [%4];"
        : "=r"(r[0]), "=r"(r[1]), "=r"(r[2]), "=r"(r[3]) : "r"(addr));
}
__device__ __forceinline__ void ldsm2t(unsigned* r, const __nv_bfloat16* p) {
    unsigned addr = (unsigned)__cvta_generic_to_shared(p);
    asm volatile("ldmatrix.sync.aligned.m8n8.x2.trans.shared.b16 {%0,%1}, [%2];"
        : "=r"(r[0]), "=r"(r[1]) : "r"(addr));
}

__device__ __forceinline__ void store_split2(__nv_bfloat16* H, __nv_bfloat16* L,
                                             int off, float v0, float v1) {
    __nv_bfloat16 h0 = __float2bfloat16(v0), h1 = __float2bfloat16(v1);
    __nv_bfloat16 l0 = __float2bfloat16(v0 - __bfloat162float(h0));
    __nv_bfloat16 l1 = __float2bfloat16(v1 - __bfloat162float(h1));
    *reinterpret_cast<unsigned*>(H + off) =
        (unsigned)__bfloat16_as_ushort(h0) | ((unsigned)__bfloat16_as_ushort(h1) << 16);
    *reinterpret_cast<unsigned*>(L + off) =
        (unsigned)__bfloat16_as_ushort(l0) | ((unsigned)__bfloat16_as_ushort(l1) << 16);
}

// ------- split-bf16 dense layer; per-warp full/empty mbarrier pipeline -------
// full[b]: count=1, completed by bulk-copy tx. empty[b]: count=16 (one arrive
// per warp after consuming a chunk). NO per-chunk __syncthreads.
template <int NCH>
__device__ __forceinline__ void gemm_layer(const float* __restrict__ bias,
                                           const __nv_bfloat16* INh,
                                           const __nv_bfloat16* INl,
                                           __nv_bfloat16* OUTh, __nv_bfloat16* OUTl,
                                           __nv_bfloat16* smb, unsigned smem_u32,
                                           int& cb, int& stg,
                                           unsigned& fph, unsigned& eph,
                                           int tid) {
    const int lane = tid & 31, w = tid >> 5;    // 16 warps
    const int g = lane >> 2, t = lane & 3;
    const int mrow = (w & 1) << 4;              // 0 or 16
    const int q = w >> 1;                        // 0..7 -> cols 32q..32q+31
    const int krow_l = (lane & 7) + ((lane >> 3) & 1) * 8;
    const int nc_l = (lane >> 4) * 8;
    const bool producer = (tid == 0);

    float aP[4][4], aQ[4][4];
#pragma unroll
    for (int i = 0; i < 4; ++i)
#pragma unroll
        for (int j = 0; j < 4; ++j) { aP[i][j] = 0.f; aQ[i][j] = 0.f; }

#pragma unroll 1
    for (int c = 0; c < NCH; ++c) {
        int sb = cb + 2; if (sb >= 3) sb -= 3;
        if (producer) {
            // wait buffer sb fully consumed, then stage chunk stg into it
            MBAR_WAIT(smem_u32 + MBAR_BYTE + 24u + 8u * sb, (eph >> sb) & 1u);
            unsigned mb = smem_u32 + MBAR_BYTE + 8u * sb;
            MBAR_EXPECT_TX(mb, 32768u);
            bulk_stage(smem_u32 + WB_BYTE + 32768u * sb, g_w + stg * 16384, mb);
        }
        eph ^= (1u << sb);
        if (++stg == NCHUNK_TOT) stg = 0;

        // consumer: wait chunk data (per-warp, no CTA barrier)
        MBAR_WAIT(smem_u32 + MBAR_BYTE + 8u * cb, (fph >> cb) & 1u);
        fph ^= (1u << cb);

        const __nv_bfloat16* swh = smb + WB_UNIT + cb * 16384;   // hi half
        const __nv_bfloat16* swl = swh + 8192;                    // lo half
#pragma unroll
        for (int kk = 0; kk < 2; ++kk) {
            const int kg = c * 32 + kk * 16;
            const __nv_bfloat16* ah_p = INh + (mrow + g) * AS + kg + 2 * t;
            const __nv_bfloat16* al_p = INl + (mrow + g) * AS + kg + 2 * t;
            unsigned ah[4], al[4];
            ah[0] = *reinterpret_cast<const unsigned*>(ah_p);
            ah[1] = *reinterpret_cast<const unsigned*>(ah_p + 8 * AS);
            ah[2] = *reinterpret_cast<const unsigned*>(ah_p + 8);
            ah[3] = *reinterpret_cast<const unsigned*>(ah_p + 8 * AS + 8);
            al[0] = *reinterpret_cast<const unsigned*>(al_p);
            al[1] = *reinterpret_cast<const unsigned*>(al_p + 8 * AS);
            al[2] = *reinterpret_cast<const unsigned*>(al_p + 8);
            al[3] = *reinterpret_cast<const unsigned*>(al_p + 8 * AS + 8);
            const int krow = kk * 16 + krow_l;
            const int swz = (krow & 7);
            const int rbase = krow * 256;
#pragma unroll
            for (int p = 0; p < 2; ++p) {
                const int ncol = (q << 5) + (p << 4) + nc_l;
                const int off = rbase + ((((ncol >> 3) ^ swz)) << 3);
                unsigned bh[4], bl[4];
                ldsm4t(bh, swh + off);
                ldsm4t(bl, swl + off);
                mma_bf16(aP[2 * p],     ah, bh[0], bh[1]);
                mma_bf16(aQ[2 * p],     ah, bl[0], bl[1]);
                mma_bf16(aQ[2 * p],     al, bh[0], bh[1]);
                mma_bf16(aP[2 * p + 1], ah, bh[2], bh[3]);
                mma_bf16(aQ[2 * p + 1], ah, bl[2], bl[3]);
                mma_bf16(aQ[2 * p + 1], al, bh[2], bh[3]);
            }
        }
        __syncwarp();
        if (lane == 0) MBAR_ARRIVE(smem_u32 + MBAR_BYTE + 24u + 8u * cb);
        if (++cb == 3) cb = 0;
    }

    // epilogue: merge sets + bias + mish, split-store
#pragma unroll
    for (int nt = 0; nt < 4; ++nt) {
        const int col = (q << 5) + (nt << 3) + 2 * t;
        float b0v = bias[col], b1v = bias[col + 1];
        float v00 = mish_f(aP[nt][0] + aQ[nt][0] + b0v);
        float v01 = mish_f(aP[nt][1] + aQ[nt][1] + b1v);
        float v10 = mish_f(aP[nt][2] + aQ[nt][2] + b0v);
        float v11 = mish_f(aP[nt][3] + aQ[nt][3] + b1v);
        store_split2(OUTh, OUTl, (mrow + g) * AS + col, v00, v01);
        store_split2(OUTh, OUTl, (mrow + g + 8) * AS + col, v10, v11);
    }
}

// ------- init: split fp32 weights -> swizzled interleaved bf16 hi/lo chunks --
__global__ void split_weights(const float* __restrict__ w0,
                              const float* __restrict__ w1,
                              const float* __restrict__ w2) {
    int idx = blockIdx.x * blockDim.x + threadIdx.x;
    if (idx >= NCHUNK_TOT * 8192) return;
    int gch = idx >> 13;
    int r   = (idx >> 8) & 31;
    int n   = idx & 255;
    float v;
    if (gch < 6) {
        int k = gch * 32 + r;
        v = (k < 176) ? w0[k * 256 + n] : 0.f;
    } else if (gch < 14) {
        int k = (gch - 6) * 32 + r;
        v = w1[k * 256 + n];
    } else {
        int k = (gch - 14) * 32 + r;
        v = w2[k * 256 + n];
    }
    __nv_bfloat16 hi = __float2bfloat16(v);
    __nv_bfloat16 lo = __float2bfloat16(v - __bfloat162float(hi));
    int pos = gch * 16384 + r * 256 + (((n >> 3) ^ (r & 7)) << 3) + (n & 7);
    g_w[pos] = hi;
    g_w[pos + 8192] = lo;
}

// ------- init: per-step coefficients + time-MLP output -----------------------
__global__ void precompute(const float* __restrict__ w_t1,
                           const float* __restrict__ b_t1,
                           const float* __restrict__ w_t2,
                           const float* __restrict__ b_t2) {
    int i = blockIdx.x * blockDim.x + threadIdx.x;
    if (i >= 1000) return;
    double nn    = (double)(i + 1);
    double ac    = exp(-1e-4 * nn - 4.95e-6 * nn * nn);
    double nm    = nn - 1.0;
    double acp   = (i == 0) ? 1.0 : exp(-1e-4 * nm - 4.95e-6 * nm * nm);
    double beta  = 1.0 - exp(-1e-4 - 4.95e-6 * (2.0 * nn - 1.0));
    double alpha = 1.0 - beta;
    g_cf[i * 8 + 0] = (float)sqrt(1.0 / ac);
    g_cf[i * 8 + 1] = (float)sqrt(1.0 / ac - 1.0);
    g_cf[i * 8 + 2] = (float)(beta * sqrt(acp) / (1.0 - ac));
    g_cf[i * 8 + 3] = (float)((1.0 - acp) * sqrt(alpha) / (1.0 - ac));
    double pv = beta * (1.0 - acp) / (1.0 - ac);
    if (pv < 1e-20) pv = 1e-20;
    float lv = (float)log(pv);
    g_cf[i * 8 + 4] = (float)exp((double)(0.5f * lv));
    unsigned a0 = 0u, a1 = (unsigned)i;
    threefry2x32(0u, 1u, a0, a1);
    g_cf[i * 8 + 5] = __uint_as_float(a0);
    g_cf[i * 8 + 6] = __uint_as_float(a1);
    float te[16];
    for (int t = 0; t < 8; ++t) {
        float c8   = (float)(-9.210340371976184 / 7.0);
        float freq = expf(c8 * (float)t);
        float ang  = (float)i * freq;
        te[t]     = (float)sin((double)ang);
        te[t + 8] = (float)cos((double)ang);
    }
    float ht[32];
    for (int j = 0; j < 32; ++j) {
        float h = b_t1[j];
        for (int k = 0; k < 16; ++k) h = fmaf(te[k], w_t1[k * 32 + j], h);
        ht[j] = mish_f(h);
    }
    for (int j = 0; j < 16; ++j) {
        float v = b_t2[j];
        for (int k = 0; k < 32; ++k) v = fmaf(ht[k], w_t2[k * 16 + j], v);
        g_tf[i * 16 + j] = v;
    }
}

// ---------------- persistent sampler -----------------------------------------
__global__ void __launch_bounds__(NT, 1)
diff_all(const float* __restrict__ state, const float* __restrict__ x_init,
         const float* __restrict__ b0,  const float* __restrict__ b1,
         const float* __restrict__ b2,
         const float* __restrict__ wf,  const float* __restrict__ bf,
         float* __restrict__ outp)
{
    extern __shared__ __align__(16) char smraw[];
    float* smf = reinterpret_cast<float*>(smraw);
    __nv_bfloat16* smb = reinterpret_cast<__nv_bfloat16*>(smraw);
    unsigned smem_u32 = (unsigned)__cvta_generic_to_shared(smraw);

    float* XS  = smf + F_XS;
    __nv_bfloat16* A0h = smb + B_A0H;  __nv_bfloat16* A0l = smb + B_A0L;
    __nv_bfloat16* A1h = smb + B_A1H;  __nv_bfloat16* A1l = smb + B_A1L;
    __nv_bfloat16* WFH = smb + WFH_UNIT;
    __nv_bfloat16* WFL = smb + WFL_UNIT;

    const int tid = threadIdx.x;
    const int r0  = blockIdx.x * BR;

    if (tid == 0) {
#pragma unroll
        for (int b = 0; b < 3; ++b) {
            MBAR_INIT(smem_u32 + MBAR_BYTE + 8u * b, 1u);        // full
            MBAR_INIT(smem_u32 + MBAR_BYTE + 24u + 8u * b, 16u); // empty
        }
    }
    for (int idx = tid; idx < BR * 32; idx += NT) {
        int r = idx >> 5, c = idx & 31;
        XS[r * 33 + c] = x_init[(r0 + r) * 32 + c];
    }
    for (int idx = tid; idx < 256 * 32; idx += NT) {
        int k = idx >> 5, n = idx & 31;
        float v = wf[idx];
        __nv_bfloat16 hi = __float2bfloat16(v);
        __nv_bfloat16 lo = __float2bfloat16(v - __bfloat162float(hi));
        WFH[k * 40 + n] = hi;
        WFL[k * 40 + n] = lo;
    }
    __syncthreads();   // barriers initialized before any arrive/stage

    // pre-complete empty[2] phase 0 (its first producer wait has no consumers yet)
    if ((tid & 31) == 0) MBAR_ARRIVE(smem_u32 + MBAR_BYTE + 24u + 16u);
    // pipeline fill: stage chunks 0,1 into buffers 0,1 (no empty wait needed)
    if (tid == 0) {
#pragma unroll
        for (int b = 0; b < 2; ++b) {
            unsigned mb = smem_u32 + MBAR_BYTE + 8u * b;
            MBAR_EXPECT_TX(mb, 32768u);
            bulk_stage(smem_u32 + WB_BYTE + 32768u * b, g_w + b * 16384, mb);
        }
    }
    int cb = 0, stg = 2;
    unsigned fph = 0, eph = 0;

#pragma unroll 1
    for (int i = 999; i >= 0; --i) {
        // ---- rebuild A0 (aliased by layer-1 output)
        for (int idx = tid; idx < 32 * 48; idx += NT) {
            int r = idx & 31, c = idx >> 5;
            float v = (c < 32) ? XS[r * 33 + c] : __ldg(&g_tf[i * 16 + (c - 32)]);
            __nv_bfloat16 hi = __float2bfloat16(v);
            __nv_bfloat16 lo = __float2bfloat16(v - __bfloat162float(hi));
            A0h[r * AS + c] = hi;
            A0l[r * AS + c] = lo;
        }
        for (int idx = tid; idx < 32 * 128; idx += NT) {
            int r = idx >> 7, c = idx & 127;
            float v = state[(r0 + r) * 128 + c];
            __nv_bfloat16 hi = __float2bfloat16(v);
            __nv_bfloat16 lo = __float2bfloat16(v - __bfloat162float(hi));
            A0h[r * AS + 48 + c] = hi;
            A0l[r * AS + 48 + c] = lo;
        }
        for (int idx = tid; idx < 32 * 16; idx += NT) {
            int r = idx >> 4, c = idx & 15;
            __nv_bfloat16 z = __float2bfloat16(0.f);
            A0h[r * AS + 176 + c] = z;
            A0l[r * AS + 176 + c] = z;
        }
        __syncthreads();

        gemm_layer<6>(b0, A0h, A0l, A1h, A1l, smb, smem_u32, cb, stg, fph, eph, tid);
        __syncthreads();
        gemm_layer<8>(b1, A1h, A1l, A0h, A0l, smb, smem_u32, cb, stg, fph, eph, tid);
        __syncthreads();
        gemm_layer<8>(b2, A0h, A0l, A1h, A1l, smb, smem_u32, cb, stg, fph, eph, tid);
        __syncthreads();

        // ---- final 256->32 via split-bf16 mma: warps 0-7, one m16n8 tile each
        if (tid < 256) {
            const int w = tid >> 5, lane = tid & 31;
            const int g = lane >> 2, t = lane & 3;
            const int mrow = (w & 1) << 4;
            const int nq = w >> 1;
            const int krow_l = (lane & 7) + ((lane >> 3) & 1) * 8;

            float aHH[4] = {0.f, 0.f, 0.f, 0.f};
            float aHL[4] = {0.f, 0.f, 0.f, 0.f};
            float aLH[4] = {0.f, 0.f, 0.f, 0.f};
#pragma unroll
            for (int ks = 0; ks < 16; ++ks) {
                const int kg = ks * 16;
                const __nv_bfloat16* ah_p = A1h + (mrow + g) * AS + kg + 2 * t;
                const __nv_bfloat16* al_p = A1l + (mrow + g) * AS + kg + 2 * t;
                unsigned ah[4], al[4];
                ah[0] = *reinterpret_cast<const unsigned*>(ah_p);
                ah[1] = *reinterpret_cast<const unsigned*>(ah_p + 8 * AS);
                ah[2] = *reinterpret_cast<const unsigned*>(ah_p + 8);
                ah[3] = *reinterpret_cast<const unsigned*>(ah_p + 8 * AS + 8);
                al[0] = *reinterpret_cast<const unsigned*>(al_p);
                al[1] = *reinterpret_cast<const unsigned*>(al_p + 8 * AS);
                al[2] = *reinterpret_cast<const unsigned*>(al_p + 8);
                al[3] = *reinterpret_cast<const unsigned*>(al_p + 8 * AS + 8);
                unsigned bh[2], bl[2];
                const int wfo = (kg + krow_l) * 40 + nq * 8;
                ldsm2t(bh, WFH + wfo);
                ldsm2t(bl, WFL + wfo);
                mma_bf16(aHH, ah, bh[0], bh[1]);
                mma_bf16(aHL, ah, bl[0], bl[1]);
                mma_bf16(aLH, al, bh[0], bh[1]);
            }

            const int c0 = nq * 8 + 2 * t;
            float bfc0 = __ldg(bf + c0), bfc1 = __ldg(bf + c0 + 1);
            float epsv[4] = {
                aHH[0] + aHL[0] + aLH[0] + bfc0,
                aHH[1] + aHL[1] + aLH[1] + bfc1,
                aHH[2] + aHL[2] + aLH[2] + bfc0,
                aHH[3] + aHL[3] + aLH[3] + bfc1 };

            const float* cf = &g_cf[i * 8];
            float sr  = __ldg(cf + 0), srm1 = __ldg(cf + 1);
            float c1  = __ldg(cf + 2), c2   = __ldg(cf + 3);
            float sig = __ldg(cf + 4);
            unsigned fk0 = __float_as_uint(__ldg(cf + 5));
            unsigned fk1 = __float_as_uint(__ldg(cf + 6));

#pragma unroll
            for (int rr = 0; rr < 2; ++rr) {
                const int row = mrow + g + rr * 8;
                const int R = r0 + row;
#pragma unroll
                for (int cc = 0; cc < 2; ++cc) {
                    const int j = c0 + cc;
                    float e  = epsv[rr * 2 + cc];
                    float xv = XS[row * 33 + j];
                    float x0 = fminf(1.f, fmaxf(-1.f, sr * xv - srm1 * e));
                    float mean = c1 * x0 + c2 * xv;
                    if (i != 0) {
                        unsigned f = (unsigned)(R * 32 + j);
                        unsigned b0r = 0u, b1r = f;
                        threefry2x32(fk0, fk1, b0r, b1r);
                        unsigned bits = b0r ^ b1r;
                        float fv = __uint_as_float((bits >> 9) | 0x3f800000u) - 1.0f;
                        const float lo = -0.99999994f;
                        float u   = fmaxf(lo, fmaf(fv, 2.0f, lo));
                        float nrm = 1.4142135623730951f * erfinv_xla(u);
                        XS[row * 33 + j] = mean + sig * nrm;
                    } else {
                        float xf = fminf(1.f, fmaxf(-1.f, mean));
                        XS[row * 33 + j] = xf;
                        outp[R * 32 + j] = xf;
                    }
                }
            }
        }
        __syncthreads();
    }
}

extern "C" void kernel_launch(void* const* d_in, const int* in_sizes, int n_in,
                              void* d_out, int out_size) {
    const float* state = (const float*)d_in[0];
    const float* xinit = (const float*)d_in[1];
    const float* w_t1  = (const float*)d_in[2];
    const float* b_t1  = (const float*)d_in[3];
    const float* w_t2  = (const float*)d_in[4];
    const float* b_t2  = (const float*)d_in[5];
    const float* w0    = (const float*)d_in[6];
    const float* b0    = (const float*)d_in[7];
    const float* w1    = (const float*)d_in[8];
    const float* b1    = (const float*)d_in[9];
    const float* w2    = (const float*)d_in[10];
    const float* b2    = (const float*)d_in[11];
    const float* wf    = (const float*)d_in[12];
    const float* bf    = (const float*)d_in[13];
    float* outp = (float*)d_out;

    cudaFuncSetAttribute(diff_all, cudaFuncAttributeMaxDynamicSharedMemorySize, SMEM_BYTES);

    split_weights<<<(NCHUNK_TOT * 8192 + 255) / 256, 256>>>(w0, w1, w2);
    precompute<<<4, 256>>>(w_t1, b_t1, w_t2, b_t2);
    diff_all<<<NB, NT, SMEM_BYTES>>>(state, xinit,
        b0, b1, b2, wf, bf, outp);
}

// round 16
// speedup vs baseline: 2.5870x; 1.0226x over previous
#include <cuda_runtime.h>
#include <cuda_bf16.h>
#include <math.h>

#define NB 128
#define NT 512
#define BR 32
#define AS  264     // activation row stride (bf16 units) = 528B (conflict-free LDS)

// ---- smem layout ----
#define MBAR_BYTE 0                // full[3] @ +0,8,16 ; empty[3] @ +24,32,40
// bf16 region from byte 64 = unit 32
#define B_A0H 32
#define B_A0L 8480
#define B_A1H 16928
#define B_A1L 25376
#define WFH_UNIT 33824             // final weights hi, [256][40]
#define WFL_UNIT 44064             // end unit 54304 = byte 108608, pad to 108672
#define WB_BYTE 108672
#define WB_UNIT 54336
#define SMEM_BYTES (108672 + 3*32768)

// pre-split trunk weights: 22 chunks x (16KB hi + 16KB lo), XOR-swizzled, contiguous
#define NCHUNK_TOT 22
#define W_ELEMS (NCHUNK_TOT * 16384)
__device__ __align__(128) __nv_bfloat16 g_w[W_ELEMS];
__device__ float g_cf[1000 * 8];
__device__ float g_tf[1000 * 16];

// ---------------- threefry2x32-20 (exact JAX) ------------------------------
__device__ __forceinline__ unsigned rotl32(unsigned x, int r) {
    return __funnelshift_l(x, x, r);
}
__device__ __forceinline__ void threefry2x32(unsigned k0, unsigned k1,
                                             unsigned &x0, unsigned &x1) {
    unsigned k2 = k0 ^ k1 ^ 0x1BD11BDAu;
#define TFR(r) { x0 += x1; x1 = rotl32(x1, r); x1 ^= x0; }
    x0 += k0; x1 += k1;
    TFR(13) TFR(15) TFR(26) TFR(6)
    x0 += k1; x1 += k2 + 1u;
    TFR(17) TFR(29) TFR(16) TFR(24)
    x0 += k2; x1 += k0 + 2u;
    TFR(13) TFR(15) TFR(26) TFR(6)
    x0 += k0; x1 += k1 + 3u;
    TFR(17) TFR(29) TFR(16) TFR(24)
    x0 += k1; x1 += k2 + 4u;
    TFR(13) TFR(15) TFR(26) TFR(6)
    x0 += k2; x1 += k0 + 5u;
#undef TFR
}

// ---------------- XLA ErfInv f32 (Giles) ------------------------------------
__device__ __forceinline__ float erfinv_xla(float x) {
    float w = -log1pf(-x * x);
    float p;
    if (w < 5.0f) {
        w -= 2.5f;
        p = 2.81022636e-08f;
        p = fmaf(p, w, 3.43273939e-07f);
        p = fmaf(p, w, -3.5233877e-06f);
        p = fmaf(p, w, -4.39150654e-06f);
        p = fmaf(p, w, 0.00021858087f);
        p = fmaf(p, w, -0.00125372503f);
        p = fmaf(p, w, -0.00417768164f);
        p = fmaf(p, w, 0.246640727f);
        p = fmaf(p, w, 1.50140941f);
    } else {
        w = sqrtf(w) - 3.0f;
        p = -0.000200214257f;
        p = fmaf(p, w, 0.000100950558f);
        p = fmaf(p, w, 0.00134934322f);
        p = fmaf(p, w, -0.00367342844f);
        p = fmaf(p, w, 0.00573950773f);
        p = fmaf(p, w, -0.0076224613f);
        p = fmaf(p, w, 0.00943887047f);
        p = fmaf(p, w, 1.00167406f);
        p = fmaf(p, w, 2.83297682f);
    }
    return p * x;
}

// ---------------- MUFU-free mish -------------------------------------------
__device__ __forceinline__ float exp_fma(float x) {
    float y = x * 1.4426950408889634f;
    y = fmaxf(y, -120.0f);
    float n = rintf(y);
    float f = y - n;
    float p =       1.5403530393381609e-4f;
    p = fmaf(p, f, 1.3333558146428443e-3f);
    p = fmaf(p, f, 9.6181298420718030e-3f);
    p = fmaf(p, f, 5.5504108664821580e-2f);
    p = fmaf(p, f, 2.4022650695910070e-1f);
    p = fmaf(p, f, 6.9314718055994530e-1f);
    p = fmaf(p, f, 1.0f);
    int e = (int)n;
    return p * __int_as_float((e + 127) << 23);
}
__device__ __forceinline__ float rcp_fma(float d) {
    float r = __int_as_float(0x7EF311C3 - __float_as_int(d));
    r = r * fmaf(-d, r, 2.0f);
    r = r * fmaf(-d, r, 2.0f);
    r = r * fmaf(-d, r, 2.0f);
    return r;
}
__device__ __forceinline__ float mish_f(float x) {
    if (x > 20.0f) return x;
    float u = exp_fma(x);
    float s = u * (u + 2.0f);
    return x * s * rcp_fma(s + 2.0f);
}

// ---------------- mbarrier + bulk-copy helpers --------------------------------
#define MBAR_INIT(addr, cnt) \
    asm volatile("mbarrier.init.shared.b64 [%0], %1;" :: "r"(addr), "r"(cnt) : "memory")
#define MBAR_EXPECT_TX(addr, bytes) \
    asm volatile("mbarrier.arrive.expect_tx.shared.b64 _, [%0], %1;" :: "r"(addr), "r"(bytes) : "memory")
#define MBAR_ARRIVE(addr) \
    asm volatile("mbarrier.arrive.shared.b64 _, [%0];" :: "r"(addr) : "memory")
#define MBAR_WAIT(addr, parity) do { \
    unsigned _done = 0; \
    while (!_done) { \
        asm volatile("{\n\t.reg .pred p;\n\t" \
            "mbarrier.try_wait.parity.acquire.cta.shared::cta.b64 p, [%1], %2, 0x989680;\n\t" \
            "selp.b32 %0, 1, 0, p;\n\t}" \
            : "=r"(_done) : "r"(addr), "r"(parity) : "memory"); \
    } } while (0)

__device__ __forceinline__ void bulk_stage(unsigned dst_smem,
                                           const __nv_bfloat16* src,
                                           unsigned mbar) {
    asm volatile(
        "cp.async.bulk.shared::cluster.global.mbarrier::complete_tx::bytes "
        "[%0], [%1], %2, [%3];"
        :: "r"(dst_smem), "l"(src), "r"(32768u), "r"(mbar) : "memory");
}

// ---------------- mma / ldmatrix wrappers ------------------------------------
__device__ __forceinline__ void mma_bf16(float* c, const unsigned* a,
                                         unsigned b0, unsigned b1) {
    asm volatile(
        "mma.sync.aligned.m16n8k16.row.col.f32.bf16.bf16.f32 "
        "{%0,%1,%2,%3}, {%4,%5,%6,%7}, {%8,%9}, {%0,%1,%2,%3};"
        : "+f"(c[0]), "+f"(c[1]), "+f"(c[2]), "+f"(c[3])
        : "r"(a[0]), "r"(a[1]), "r"(a[2]), "r"(a[3]), "r"(b0), "r"(b1));
}
__device__ __forceinline__ void ldsm4t(unsigned* r, const __nv_bfloat16* p) {
    unsigned addr = (unsigned)__cvta_generic_to_shared(p);
    asm volatile("ldmatrix.sync.aligned.m8n8.x4.trans.shared.b16 {%0,%1,%2,%3}, [%4];"
        : "=r"(r[0]), "=r"(r[1]), "=r"(r[2]), "=r"(r[3]) : "r"(addr));
}
__device__ __forceinline__ void ldsm2t(unsigned* r, const __nv_bfloat16* p) {
    unsigned addr = (unsigned)__cvta_generic_to_shared(p);
    asm volatile("ldmatrix.sync.aligned.m8n8.x2.trans.shared.b16 {%0,%1}, [%2];"
        : "=r"(r[0]), "=r"(r[1]) : "r"(addr));
}

__device__ __forceinline__ void store_split1(__nv_bfloat16* H, __nv_bfloat16* L,
                                             int off, float v) {
    __nv_bfloat16 hi = __float2bfloat16(v);
    __nv_bfloat16 lo = __float2bfloat16(v - __bfloat162float(hi));
    H[off] = hi;
    L[off] = lo;
}
__device__ __forceinline__ void store_split2(__nv_bfloat16* H, __nv_bfloat16* L,
                                             int off, float v0, float v1) {
    __nv_bfloat16 h0 = __float2bfloat16(v0), h1 = __float2bfloat16(v1);
    __nv_bfloat16 l0 = __float2bfloat16(v0 - __bfloat162float(h0));
    __nv_bfloat16 l1 = __float2bfloat16(v1 - __bfloat162float(h1));
    *reinterpret_cast<unsigned*>(H + off) =
        (unsigned)__bfloat16_as_ushort(h0) | ((unsigned)__bfloat16_as_ushort(h1) << 16);
    *reinterpret_cast<unsigned*>(L + off) =
        (unsigned)__bfloat16_as_ushort(l0) | ((unsigned)__bfloat16_as_ushort(l1) << 16);
}

// ------- split-bf16 dense layer; per-warp full/empty mbarrier pipeline -------
template <int NCH>
__device__ __forceinline__ void gemm_layer(const float* __restrict__ bias,
                                           const __nv_bfloat16* INh,
                                           const __nv_bfloat16* INl,
                                           __nv_bfloat16* OUTh, __nv_bfloat16* OUTl,
                                           __nv_bfloat16* smb, unsigned smem_u32,
                                           int& cb, int& stg,
                                           unsigned& fph, unsigned& eph,
                                           int tid) {
    const int lane = tid & 31, w = tid >> 5;    // 16 warps
    const int g = lane >> 2, t = lane & 3;
    const int mrow = (w & 1) << 4;              // 0 or 16
    const int q = w >> 1;                        // 0..7 -> cols 32q..32q+31
    const int krow_l = (lane & 7) + ((lane >> 3) & 1) * 8;
    const int nc_l = (lane >> 4) * 8;
    const bool producer = (tid == 0);

    float aP[4][4], aQ[4][4];
#pragma unroll
    for (int i = 0; i < 4; ++i)
#pragma unroll
        for (int j = 0; j < 4; ++j) { aP[i][j] = 0.f; aQ[i][j] = 0.f; }

#pragma unroll 1
    for (int c = 0; c < NCH; ++c) {
        int sb = cb + 2; if (sb >= 3) sb -= 3;
        if (producer) {
            MBAR_WAIT(smem_u32 + MBAR_BYTE + 24u + 8u * sb, (eph >> sb) & 1u);
            unsigned mb = smem_u32 + MBAR_BYTE + 8u * sb;
            MBAR_EXPECT_TX(mb, 32768u);
            bulk_stage(smem_u32 + WB_BYTE + 32768u * sb, g_w + stg * 16384, mb);
        }
        eph ^= (1u << sb);
        if (++stg == NCHUNK_TOT) stg = 0;

        MBAR_WAIT(smem_u32 + MBAR_BYTE + 8u * cb, (fph >> cb) & 1u);
        fph ^= (1u << cb);

        const __nv_bfloat16* swh = smb + WB_UNIT + cb * 16384;
        const __nv_bfloat16* swl = swh + 8192;
#pragma unroll
        for (int kk = 0; kk < 2; ++kk) {
            const int kg = c * 32 + kk * 16;
            const __nv_bfloat16* ah_p = INh + (mrow + g) * AS + kg + 2 * t;
            const __nv_bfloat16* al_p = INl + (mrow + g) * AS + kg + 2 * t;
            unsigned ah[4], al[4];
            ah[0] = *reinterpret_cast<const unsigned*>(ah_p);
            ah[1] = *reinterpret_cast<const unsigned*>(ah_p + 8 * AS);
            ah[2] = *reinterpret_cast<const unsigned*>(ah_p + 8);
            ah[3] = *reinterpret_cast<const unsigned*>(ah_p + 8 * AS + 8);
            al[0] = *reinterpret_cast<const unsigned*>(al_p);
            al[1] = *reinterpret_cast<const unsigned*>(al_p + 8 * AS);
            al[2] = *reinterpret_cast<const unsigned*>(al_p + 8);
            al[3] = *reinterpret_cast<const unsigned*>(al_p + 8 * AS + 8);
            const int krow = kk * 16 + krow_l;
            const int swz = (krow & 7);
            const int rbase = krow * 256;
#pragma unroll
            for (int p = 0; p < 2; ++p) {
                const int ncol = (q << 5) + (p << 4) + nc_l;
                const int off = rbase + ((((ncol >> 3) ^ swz)) << 3);
                unsigned bh[4], bl[4];
                ldsm4t(bh, swh + off);
                ldsm4t(bl, swl + off);
                mma_bf16(aP[2 * p],     ah, bh[0], bh[1]);
                mma_bf16(aQ[2 * p],     ah, bl[0], bl[1]);
                mma_bf16(aQ[2 * p],     al, bh[0], bh[1]);
                mma_bf16(aP[2 * p + 1], ah, bh[2], bh[3]);
                mma_bf16(aQ[2 * p + 1], ah, bl[2], bl[3]);
                mma_bf16(aQ[2 * p + 1], al, bh[2], bh[3]);
            }
        }
        __syncwarp();
        if (lane == 0) MBAR_ARRIVE(smem_u32 + MBAR_BYTE + 24u + 8u * cb);
        if (++cb == 3) cb = 0;
    }

#pragma unroll
    for (int nt = 0; nt < 4; ++nt) {
        const int col = (q << 5) + (nt << 3) + 2 * t;
        float b0v = bias[col], b1v = bias[col + 1];
        float v00 = mish_f(aP[nt][0] + aQ[nt][0] + b0v);
        float v01 = mish_f(aP[nt][1] + aQ[nt][1] + b1v);
        float v10 = mish_f(aP[nt][2] + aQ[nt][2] + b0v);
        float v11 = mish_f(aP[nt][3] + aQ[nt][3] + b1v);
        store_split2(OUTh, OUTl, (mrow + g) * AS + col, v00, v01);
        store_split2(OUTh, OUTl, (mrow + g + 8) * AS + col, v10, v11);
    }
}

// ------- init: split fp32 weights -> swizzled interleaved bf16 hi/lo chunks --
__global__ void split_weights(const float* __restrict__ w0,
                              const float* __restrict__ w1,
                              const float* __restrict__ w2) {
    int idx = blockIdx.x * blockDim.x + threadIdx.x;
    if (idx >= NCHUNK_TOT * 8192) return;
    int gch = idx >> 13;
    int r   = (idx >> 8) & 31;
    int n   = idx & 255;
    float v;
    if (gch < 6) {
        int k = gch * 32 + r;
        v = (k < 176) ? w0[k * 256 + n] : 0.f;
    } else if (gch < 14) {
        int k = (gch - 6) * 32 + r;
        v = w1[k * 256 + n];
    } else {
        int k = (gch - 14) * 32 + r;
        v = w2[k * 256 + n];
    }
    __nv_bfloat16 hi = __float2bfloat16(v);
    __nv_bfloat16 lo = __float2bfloat16(v - __bfloat162float(hi));
    int pos = gch * 16384 + r * 256 + (((n >> 3) ^ (r & 7)) << 3) + (n & 7);
    g_w[pos] = hi;
    g_w[pos + 8192] = lo;
}

// ------- init: per-step coefficients + time-MLP output -----------------------
__global__ void precompute(const float* __restrict__ w_t1,
                           const float* __restrict__ b_t1,
                           const float* __restrict__ w_t2,
                           const float* __restrict__ b_t2) {
    int i = blockIdx.x * blockDim.x + threadIdx.x;
    if (i >= 1000) return;
    double nn    = (double)(i + 1);
    double ac    = exp(-1e-4 * nn - 4.95e-6 * nn * nn);
    double nm    = nn - 1.0;
    double acp   = (i == 0) ? 1.0 : exp(-1e-4 * nm - 4.95e-6 * nm * nm);
    double beta  = 1.0 - exp(-1e-4 - 4.95e-6 * (2.0 * nn - 1.0));
    double alpha = 1.0 - beta;
    g_cf[i * 8 + 0] = (float)sqrt(1.0 / ac);
    g_cf[i * 8 + 1] = (float)sqrt(1.0 / ac - 1.0);
    g_cf[i * 8 + 2] = (float)(beta * sqrt(acp) / (1.0 - ac));
    g_cf[i * 8 + 3] = (float)((1.0 - acp) * sqrt(alpha) / (1.0 - ac));
    double pv = beta * (1.0 - acp) / (1.0 - ac);
    if (pv < 1e-20) pv = 1e-20;
    float lv = (float)log(pv);
    g_cf[i * 8 + 4] = (float)exp((double)(0.5f * lv));
    unsigned a0 = 0u, a1 = (unsigned)i;
    threefry2x32(0u, 1u, a0, a1);
    g_cf[i * 8 + 5] = __uint_as_float(a0);
    g_cf[i * 8 + 6] = __uint_as_float(a1);
    float te[16];
    for (int t = 0; t < 8; ++t) {
        float c8   = (float)(-9.210340371976184 / 7.0);
        float freq = expf(c8 * (float)t);
        float ang  = (float)i * freq;
        te[t]     = (float)sin((double)ang);
        te[t + 8] = (float)cos((double)ang);
    }
    float ht[32];
    for (int j = 0; j < 32; ++j) {
        float h = b_t1[j];
        for (int k = 0; k < 16; ++k) h = fmaf(te[k], w_t1[k * 32 + j], h);
        ht[j] = mish_f(h);
    }
    for (int j = 0; j < 16; ++j) {
        float v = b_t2[j];
        for (int k = 0; k < 32; ++k) v = fmaf(ht[k], w_t2[k * 16 + j], v);
        g_tf[i * 16 + j] = v;
    }
}

// ---------------- persistent sampler -----------------------------------------
__global__ void __launch_bounds__(NT, 1)
diff_all(const float* __restrict__ state, const float* __restrict__ x_init,
         const float* __restrict__ b0,  const float* __restrict__ b1,
         const float* __restrict__ b2,
         const float* __restrict__ wf,  const float* __restrict__ bf,
         float* __restrict__ outp)
{
    extern __shared__ __align__(16) char smraw[];
    __nv_bfloat16* smb = reinterpret_cast<__nv_bfloat16*>(smraw);
    unsigned smem_u32 = (unsigned)__cvta_generic_to_shared(smraw);

    __nv_bfloat16* A0h = smb + B_A0H;  __nv_bfloat16* A0l = smb + B_A0L;
    __nv_bfloat16* A1h = smb + B_A1H;  __nv_bfloat16* A1l = smb + B_A1L;
    __nv_bfloat16* WFH = smb + WFH_UNIT;
    __nv_bfloat16* WFL = smb + WFL_UNIT;

    const int tid = threadIdx.x;
    const int r0  = blockIdx.x * BR;

    if (tid == 0) {
#pragma unroll
        for (int b = 0; b < 3; ++b) {
            MBAR_INIT(smem_u32 + MBAR_BYTE + 8u * b, 1u);        // full
            MBAR_INIT(smem_u32 + MBAR_BYTE + 24u + 8u * b, 16u); // empty
        }
    }
    // final-layer weights -> smem bf16 hi/lo, row stride 40
    for (int idx = tid; idx < 256 * 32; idx += NT) {
        int k = idx >> 5, n = idx & 31;
        float v = wf[idx];
        store_split1(WFH, WFL, k * 40 + n, v);
    }
    // initial A0: x | tf(999) | state | zeros
    for (int idx = tid; idx < 32 * 48; idx += NT) {
        int r = idx & 31, c = idx >> 5;
        float v = (c < 32) ? x_init[(r0 + r) * 32 + c] : g_tf[999 * 16 + (c - 32)];
        store_split1(A0h, A0l, r * AS + c, v);
    }
    for (int idx = tid; idx < 32 * 128; idx += NT) {
        int r = idx >> 7, c = idx & 127;
        store_split1(A0h, A0l, r * AS + 48 + c, state[(r0 + r) * 128 + c]);
    }
    for (int idx = tid; idx < 32 * 16; idx += NT) {
        int r = idx >> 4, c = idx & 15;
        A0h[r * AS + 176 + c] = __float2bfloat16(0.f);
        A0l[r * AS + 176 + c] = __float2bfloat16(0.f);
    }

    // register-resident x for the x-update lanes (warps 0-7)
    const int wq = tid >> 5, lane = tid & 31;
    const int gq = lane >> 2, tq = lane & 3;
    const int mrowq = (wq & 1) << 4;
    const int nqq = wq >> 1;
    const int c0q = nqq * 8 + 2 * tq;
    float xreg[4];
    if (tid < 256) {
#pragma unroll
        for (int rr = 0; rr < 2; ++rr)
#pragma unroll
            for (int cc = 0; cc < 2; ++cc)
                xreg[rr * 2 + cc] = x_init[(r0 + mrowq + gq + rr * 8) * 32 + c0q + cc];
    }
    __syncthreads();   // barriers + A0 + WF ready

    // pre-complete empty[2] phase 0; pipeline fill chunks 0,1
    if ((tid & 31) == 0) MBAR_ARRIVE(smem_u32 + MBAR_BYTE + 24u + 16u);
    if (tid == 0) {
#pragma unroll
        for (int b = 0; b < 2; ++b) {
            unsigned mb = smem_u32 + MBAR_BYTE + 8u * b;
            MBAR_EXPECT_TX(mb, 32768u);
            bulk_stage(smem_u32 + WB_BYTE + 32768u * b, g_w + b * 16384, mb);
        }
    }
    int cb = 0, stg = 2;
    unsigned fph = 0, eph = 0;

#pragma unroll 1
    for (int i = 999; i >= 0; --i) {
        gemm_layer<6>(b0, A0h, A0l, A1h, A1l, smb, smem_u32, cb, stg, fph, eph, tid);
        __syncthreads();
        gemm_layer<8>(b1, A1h, A1l, A0h, A0l, smb, smem_u32, cb, stg, fph, eph, tid);
        __syncthreads();
        gemm_layer<8>(b2, A0h, A0l, A1h, A1l, smb, smem_u32, cb, stg, fph, eph, tid);
        __syncthreads();

        if (tid < 256) {
            // ---- final 256->32 via split-bf16 mma + in-register x-update
            const int krow_l = (lane & 7) + ((lane >> 3) & 1) * 8;
            const float* cf = &g_cf[i * 8];
            float sr  = __ldg(cf + 0), srm1 = __ldg(cf + 1);
            float c1  = __ldg(cf + 2), c2   = __ldg(cf + 3);
            float sig = __ldg(cf + 4);
            unsigned fk0 = __float_as_uint(__ldg(cf + 5));
            unsigned fk1 = __float_as_uint(__ldg(cf + 6));

            float aHH[4] = {0.f, 0.f, 0.f, 0.f};
            float aHL[4] = {0.f, 0.f, 0.f, 0.f};
            float aLH[4] = {0.f, 0.f, 0.f, 0.f};
#pragma unroll
            for (int ks = 0; ks < 16; ++ks) {
                const int kg = ks * 16;
                const __nv_bfloat16* ah_p = A1h + (mrowq + gq) * AS + kg + 2 * tq;
                const __nv_bfloat16* al_p = A1l + (mrowq + gq) * AS + kg + 2 * tq;
                unsigned ah[4], al[4];
                ah[0] = *reinterpret_cast<const unsigned*>(ah_p);
                ah[1] = *reinterpret_cast<const unsigned*>(ah_p + 8 * AS);
                ah[2] = *reinterpret_cast<const unsigned*>(ah_p + 8);
                ah[3] = *reinterpret_cast<const unsigned*>(ah_p + 8 * AS + 8);
                al[0] = *reinterpret_cast<const unsigned*>(al_p);
                al[1] = *reinterpret_cast<const unsigned*>(al_p + 8 * AS);
                al[2] = *reinterpret_cast<const unsigned*>(al_p + 8);
                al[3] = *reinterpret_cast<const unsigned*>(al_p + 8 * AS + 8);
                unsigned bh[2], bl[2];
                const int wfo = (kg + krow_l) * 40 + nqq * 8;
                ldsm2t(bh, WFH + wfo);
                ldsm2t(bl, WFL + wfo);
                mma_bf16(aHH, ah, bh[0], bh[1]);
                mma_bf16(aHL, ah, bl[0], bl[1]);
                mma_bf16(aLH, al, bh[0], bh[1]);
            }

            float bfc0 = __ldg(bf + c0q), bfc1 = __ldg(bf + c0q + 1);
            float epsv[4] = {
                aHH[0] + aHL[0] + aLH[0] + bfc0,
                aHH[1] + aHL[1] + aLH[1] + bfc1,
                aHH[2] + aHL[2] + aLH[2] + bfc0,
                aHH[3] + aHL[3] + aLH[3] + bfc1 };

#pragma unroll
            for (int rr = 0; rr < 2; ++rr) {
                const int row = mrowq + gq + rr * 8;
                const int R = r0 + row;
#pragma unroll
                for (int cc = 0; cc < 2; ++cc) {
                    const int j = c0q + cc;
                    float e  = epsv[rr * 2 + cc];
                    float xv = xreg[rr * 2 + cc];
                    float x0 = fminf(1.f, fmaxf(-1.f, sr * xv - srm1 * e));
                    float mean = c1 * x0 + c2 * xv;
                    if (i != 0) {
                        unsigned f = (unsigned)(R * 32 + j);
                        unsigned b0r = 0u, b1r = f;
                        threefry2x32(fk0, fk1, b0r, b1r);
                        unsigned bits = b0r ^ b1r;
                        float fv = __uint_as_float((bits >> 9) | 0x3f800000u) - 1.0f;
                        const float lo = -0.99999994f;
                        float u   = fmaxf(lo, fmaf(fv, 2.0f, lo));
                        float nrm = 1.4142135623730951f * erfinv_xla(u);
                        float xn = mean + sig * nrm;
                        xreg[rr * 2 + cc] = xn;
                        store_split1(A0h, A0l, row * AS + j, xn);  // x part of next A0
                    } else {
                        float xf = fminf(1.f, fmaxf(-1.f, mean));
                        outp[R * 32 + j] = xf;
                    }
                }
            }
        } else if (i != 0) {
            // ---- warps 8-15: rebuild A0 state/zero/tf for the NEXT step
            const int t2 = tid - 256;
#pragma unroll
            for (int l = 0; l < 16; ++l) {
                int idx = t2 + l * 256;
                int r = idx >> 7, c = idx & 127;
                store_split1(A0h, A0l, r * AS + 48 + c, __ldg(&state[(r0 + r) * 128 + c]));
            }
#pragma unroll
            for (int l = 0; l < 2; ++l) {
                int idx = t2 + l * 256;
                int r = idx >> 4, c = idx & 15;
                A0h[r * AS + 176 + c] = __float2bfloat16(0.f);
                A0l[r * AS + 176 + c] = __float2bfloat16(0.f);
            }
#pragma unroll
            for (int l = 0; l < 2; ++l) {
                int idx = t2 + l * 256;
                int r = idx & 31, c = idx >> 5;      // c = 0..15 -> col 32+c
                float v = __ldg(&g_tf[(i - 1) * 16 + c]);
                store_split1(A0h, A0l, r * AS + 32 + c, v);
            }
        }
        __syncthreads();
    }
}

extern "C" void kernel_launch(void* const* d_in, const int* in_sizes, int n_in,
                              void* d_out, int out_size) {
    const float* state = (const float*)d_in[0];
    const float* xinit = (const float*)d_in[1];
    const float* w_t1  = (const float*)d_in[2];
    const float* b_t1  = (const float*)d_in[3];
    const float* w_t2  = (const float*)d_in[4];
    const float* b_t2  = (const float*)d_in[5];
    const float* w0    = (const float*)d_in[6];
    const float* b0    = (const float*)d_in[7];
    const float* w1    = (const float*)d_in[8];
    const float* b1    = (const float*)d_in[9];
    const float* w2    = (const float*)d_in[10];
    const float* b2    = (const float*)d_in[11];
    const float* wf    = (const float*)d_in[12];
    const float* bf    = (const float*)d_in[13];
    float* outp = (float*)d_out;

    cudaFuncSetAttribute(diff_all, cudaFuncAttributeMaxDynamicSharedMemorySize, SMEM_BYTES);

    split_weights<<<(NCHUNK_TOT * 8192 + 255) / 256, 256>>>(w0, w1, w2);
    precompute<<<4, 256>>>(w_t1, b_t1, w_t2, b_t2);
    diff_all<<<NB, NT, SMEM_BYTES>>>(state, xinit,
        b0, b1, b2, wf, bf, outp);
}

// round 17
// speedup vs baseline: 2.9119x; 1.1256x over previous
#include <cuda_runtime.h>
#include <cuda_bf16.h>
#include <math.h>

#define NB 128
#define NT 512
#define BR 32
#define AS  264     // wide activation row stride (bf16 units) = 528B
#define A0S 72      // layer-0 activation row stride (64 cols used)

// ---- smem layout ----
#define MBAR_BYTE 0                // full[3] @ +0,8,16 ; empty[3] @ +24,32,40
// bf16 units from byte 64 = unit 32
#define B_A0H 32
#define B_A0L 2336
#define B_A1H 4640
#define B_A1L 13088
#define B_A2H 21536
#define B_A2L 29984
#define WFH_UNIT 38432             // final weights hi, [256][40]
#define WFL_UNIT 48672             // end unit 58912 = byte 117824
#define WB_BYTE 117888
#define WB_UNIT 58944
#define SMEM_BYTES (117888 + 3*32768)

// trunk weights: 18 chunks x (16KB hi + 16KB lo), XOR-swizzled, contiguous
// chunks 0-1: w0 rows 0..47 (x+tf) zero-padded to 64; 2-9: w1; 10-17: w2
#define NCHUNK_TOT 18
#define W_ELEMS (NCHUNK_TOT * 16384)
__device__ __align__(128) __nv_bfloat16 g_w[W_ELEMS];
__device__ float g_cf[1000 * 8];
__device__ float g_tf[1000 * 16];
__device__ float g_c0[4096 * 256];   // state @ w0[48:176] + b0 (exact fp32)

// ---------------- threefry2x32-20 (exact JAX) ------------------------------
__device__ __forceinline__ unsigned rotl32(unsigned x, int r) {
    return __funnelshift_l(x, x, r);
}
__device__ __forceinline__ void threefry2x32(unsigned k0, unsigned k1,
                                             unsigned &x0, unsigned &x1) {
    unsigned k2 = k0 ^ k1 ^ 0x1BD11BDAu;
#define TFR(r) { x0 += x1; x1 = rotl32(x1, r); x1 ^= x0; }
    x0 += k0; x1 += k1;
    TFR(13) TFR(15) TFR(26) TFR(6)
    x0 += k1; x1 += k2 + 1u;
    TFR(17) TFR(29) TFR(16) TFR(24)
    x0 += k2; x1 += k0 + 2u;
    TFR(13) TFR(15) TFR(26) TFR(6)
    x0 += k0; x1 += k1 + 3u;
    TFR(17) TFR(29) TFR(16) TFR(24)
    x0 += k1; x1 += k2 + 4u;
    TFR(13) TFR(15) TFR(26) TFR(6)
    x0 += k2; x1 += k0 + 5u;
#undef TFR
}

// ---------------- XLA ErfInv f32 (Giles) ------------------------------------
__device__ __forceinline__ float erfinv_xla(float x) {
    float w = -log1pf(-x * x);
    float p;
    if (w < 5.0f) {
        w -= 2.5f;
        p = 2.81022636e-08f;
        p = fmaf(p, w, 3.43273939e-07f);
        p = fmaf(p, w, -3.5233877e-06f);
        p = fmaf(p, w, -4.39150654e-06f);
        p = fmaf(p, w, 0.00021858087f);
        p = fmaf(p, w, -0.00125372503f);
        p = fmaf(p, w, -0.00417768164f);
        p = fmaf(p, w, 0.246640727f);
        p = fmaf(p, w, 1.50140941f);
    } else {
        w = sqrtf(w) - 3.0f;
        p = -0.000200214257f;
        p = fmaf(p, w, 0.000100950558f);
        p = fmaf(p, w, 0.00134934322f);
        p = fmaf(p, w, -0.00367342844f);
        p = fmaf(p, w, 0.00573950773f);
        p = fmaf(p, w, -0.0076224613f);
        p = fmaf(p, w, 0.00943887047f);
        p = fmaf(p, w, 1.00167406f);
        p = fmaf(p, w, 2.83297682f);
    }
    return p * x;
}

// ---------------- MUFU-free mish -------------------------------------------
__device__ __forceinline__ float exp_fma(float x) {
    float y = x * 1.4426950408889634f;
    y = fmaxf(y, -120.0f);
    float n = rintf(y);
    float f = y - n;
    float p =       1.5403530393381609e-4f;
    p = fmaf(p, f, 1.3333558146428443e-3f);
    p = fmaf(p, f, 9.6181298420718030e-3f);
    p = fmaf(p, f, 5.5504108664821580e-2f);
    p = fmaf(p, f, 2.4022650695910070e-1f);
    p = fmaf(p, f, 6.9314718055994530e-1f);
    p = fmaf(p, f, 1.0f);
    int e = (int)n;
    return p * __int_as_float((e + 127) << 23);
}
__device__ __forceinline__ float rcp_fma(float d) {
    float r = __int_as_float(0x7EF311C3 - __float_as_int(d));
    r = r * fmaf(-d, r, 2.0f);
    r = r * fmaf(-d, r, 2.0f);
    r = r * fmaf(-d, r, 2.0f);
    return r;
}
__device__ __forceinline__ float mish_f(float x) {
    if (x > 20.0f) return x;
    float u = exp_fma(x);
    float s = u * (u + 2.0f);
    return x * s * rcp_fma(s + 2.0f);
}

// ---------------- mbarrier + bulk-copy helpers --------------------------------
#define MBAR_INIT(addr, cnt) \
    asm volatile("mbarrier.init.shared.b64 [%0], %1;" :: "r"(addr), "r"(cnt) : "memory")
#define MBAR_EXPECT_TX(addr, bytes) \
    asm volatile("mbarrier.arrive.expect_tx.shared.b64 _, [%0], %1;" :: "r"(addr), "r"(bytes) : "memory")
#define MBAR_ARRIVE(addr) \
    asm volatile("mbarrier.arrive.shared.b64 _, [%0];" :: "r"(addr) : "memory")
#define MBAR_WAIT(addr, parity) do { \
    unsigned _done = 0; \
    while (!_done) { \
        asm volatile("{\n\t.reg .pred p;\n\t" \
            "mbarrier.try_wait.parity.acquire.cta.shared::cta.b64 p, [%1], %2, 0x989680;\n\t" \
            "selp.b32 %0, 1, 0, p;\n\t}" \
            : "=r"(_done) : "r"(addr), "r"(parity) : "memory"); \
    } } while (0)

__device__ __forceinline__ void bulk_stage(unsigned dst_smem,
                                           const __nv_bfloat16* src,
                                           unsigned mbar) {
    asm volatile(
        "cp.async.bulk.shared::cluster.global.mbarrier::complete_tx::bytes "
        "[%0], [%1], %2, [%3];"
        :: "r"(dst_smem), "l"(src), "r"(32768u), "r"(mbar) : "memory");
}

// ---------------- mma / ldmatrix wrappers ------------------------------------
__device__ __forceinline__ void mma_bf16(float* c, const unsigned* a,
                                         unsigned b0, unsigned b1) {
    asm volatile(
        "mma.sync.aligned.m16n8k16.row.col.f32.bf16.bf16.f32 "
        "{%0,%1,%2,%3}, {%4,%5,%6,%7}, {%8,%9}, {%0,%1,%2,%3};"
        : "+f"(c[0]), "+f"(c[1]), "+f"(c[2]), "+f"(c[3])
        : "r"(a[0]), "r"(a[1]), "r"(a[2]), "r"(a[3]), "r"(b0), "r"(b1));
}
__device__ __forceinline__ void ldsm4t(unsigned* r, const __nv_bfloat16* p) {
    unsigned addr = (unsigned)__cvta_generic_to_shared(p);
    asm volatile("ldmatrix.sync.aligned.m8n8.x4.trans.shared.b16 {%0,%1,%2,%3}, [%4];"
        : "=r"(r[0]), "=r"(r[1]), "=r"(r[2]), "=r"(r[3]) : "r"(addr));
}
__device__ __forceinline__ void ldsm2t(unsigned* r, const __nv_bfloat16* p) {
    unsigned addr = (unsigned)__cvta_generic_to_shared(p);
    asm volatile("ldmatrix.sync.aligned.m8n8.x2.trans.shared.b16 {%0,%1}, [%2];"
        : "=r"(r[0]), "=r"(r[1]) : "r"(addr));
}

__device__ __forceinline__ void store_split1(__nv_bfloat16* H, __nv_bfloat16* L,
                                             int off, float v) {
    __nv_bfloat16 hi = __float2bfloat16(v);
    __nv_bfloat16 lo = __float2bfloat16(v - __bfloat162float(hi));
    H[off] = hi;
    L[off] = lo;
}
__device__ __forceinline__ void store_split2(__nv_bfloat16* H, __nv_bfloat16* L,
                                             int off, float v0, float v1) {
    __nv_bfloat16 h0 = __float2bfloat16(v0), h1 = __float2bfloat16(v1);
    __nv_bfloat16 l0 = __float2bfloat16(v0 - __bfloat162float(h0));
    __nv_bfloat16 l1 = __float2bfloat16(v1 - __bfloat162float(h1));
    *reinterpret_cast<unsigned*>(H + off) =
        (unsigned)__bfloat16_as_ushort(h0) | ((unsigned)__bfloat16_as_ushort(h1) << 16);
    *reinterpret_cast<unsigned*>(L + off) =
        (unsigned)__bfloat16_as_ushort(l0) | ((unsigned)__bfloat16_as_ushort(l1) << 16);
}

// ------- split-bf16 dense layer; per-warp full/empty mbarrier pipeline -------
// INIT: initialize aP from c0 (16 per-thread floats, bias folded in).
template <int NCH, int INS, bool INIT>
__device__ __forceinline__ void gemm_layer(const float* __restrict__ bias,
                                           const float* __restrict__ c0,
                                           const __nv_bfloat16* INh,
                                           const __nv_bfloat16* INl,
                                           __nv_bfloat16* OUTh, __nv_bfloat16* OUTl,
                                           __nv_bfloat16* smb, unsigned smem_u32,
                                           int& cb, int& stg,
                                           unsigned& fph, unsigned& eph,
                                           int tid) {
    const int lane = tid & 31, w = tid >> 5;    // 16 warps
    const int g = lane >> 2, t = lane & 3;
    const int mrow = (w & 1) << 4;              // 0 or 16
    const int q = w >> 1;                        // 0..7 -> cols 32q..32q+31
    const int krow_l = (lane & 7) + ((lane >> 3) & 1) * 8;
    const int nc_l = (lane >> 4) * 8;
    const bool producer = (tid == 0);

    float aP[4][4], aQ[4][4];
#pragma unroll
    for (int i = 0; i < 4; ++i)
#pragma unroll
        for (int j = 0; j < 4; ++j) {
            aP[i][j] = INIT ? c0[i * 4 + j] : 0.f;
            aQ[i][j] = 0.f;
        }

#pragma unroll 1
    for (int c = 0; c < NCH; ++c) {
        int sb = cb + 2; if (sb >= 3) sb -= 3;
        if (producer) {
            MBAR_WAIT(smem_u32 + MBAR_BYTE + 24u + 8u * sb, (eph >> sb) & 1u);
            unsigned mb = smem_u32 + MBAR_BYTE + 8u * sb;
            MBAR_EXPECT_TX(mb, 32768u);
            bulk_stage(smem_u32 + WB_BYTE + 32768u * sb, g_w + stg * 16384, mb);
        }
        eph ^= (1u << sb);
        if (++stg == NCHUNK_TOT) stg = 0;

        MBAR_WAIT(smem_u32 + MBAR_BYTE + 8u * cb, (fph >> cb) & 1u);
        fph ^= (1u << cb);

        const __nv_bfloat16* swh = smb + WB_UNIT + cb * 16384;
        const __nv_bfloat16* swl = swh + 8192;
#pragma unroll
        for (int kk = 0; kk < 2; ++kk) {
            const int kg = c * 32 + kk * 16;
            const __nv_bfloat16* ah_p = INh + (mrow + g) * INS + kg + 2 * t;
            const __nv_bfloat16* al_p = INl + (mrow + g) * INS + kg + 2 * t;
            unsigned ah[4], al[4];
            ah[0] = *reinterpret_cast<const unsigned*>(ah_p);
            ah[1] = *reinterpret_cast<const unsigned*>(ah_p + 8 * INS);
            ah[2] = *reinterpret_cast<const unsigned*>(ah_p + 8);
            ah[3] = *reinterpret_cast<const unsigned*>(ah_p + 8 * INS + 8);
            al[0] = *reinterpret_cast<const unsigned*>(al_p);
            al[1] = *reinterpret_cast<const unsigned*>(al_p + 8 * INS);
            al[2] = *reinterpret_cast<const unsigned*>(al_p + 8);
            al[3] = *reinterpret_cast<const unsigned*>(al_p + 8 * INS + 8);
            const int krow = kk * 16 + krow_l;
            const int swz = (krow & 7);
            const int rbase = krow * 256;
#pragma unroll
            for (int p = 0; p < 2; ++p) {
                const int ncol = (q << 5) + (p << 4) + nc_l;
                const int off = rbase + ((((ncol >> 3) ^ swz)) << 3);
                unsigned bh[4], bl[4];
                ldsm4t(bh, swh + off);
                ldsm4t(bl, swl + off);
                mma_bf16(aP[2 * p],     ah, bh[0], bh[1]);
                mma_bf16(aQ[2 * p],     ah, bl[0], bl[1]);
                mma_bf16(aQ[2 * p],     al, bh[0], bh[1]);
                mma_bf16(aP[2 * p + 1], ah, bh[2], bh[3]);
                mma_bf16(aQ[2 * p + 1], ah, bl[2], bl[3]);
                mma_bf16(aQ[2 * p + 1], al, bh[2], bh[3]);
            }
        }
        __syncwarp();
        if (lane == 0) MBAR_ARRIVE(smem_u32 + MBAR_BYTE + 24u + 8u * cb);
        if (++cb == 3) cb = 0;
    }

#pragma unroll
    for (int nt = 0; nt < 4; ++nt) {
        const int col = (q << 5) + (nt << 3) + 2 * t;
        float b0v = INIT ? 0.f : bias[col];
        float b1v = INIT ? 0.f : bias[col + 1];
        float v00 = mish_f(aP[nt][0] + aQ[nt][0] + b0v);
        float v01 = mish_f(aP[nt][1] + aQ[nt][1] + b1v);
        float v10 = mish_f(aP[nt][2] + aQ[nt][2] + b0v);
        float v11 = mish_f(aP[nt][3] + aQ[nt][3] + b1v);
        store_split2(OUTh, OUTl, (mrow + g) * AS + col, v00, v01);
        store_split2(OUTh, OUTl, (mrow + g + 8) * AS + col, v10, v11);
    }
}

// ------- init: split fp32 weights -> swizzled interleaved bf16 hi/lo chunks --
__global__ void split_weights(const float* __restrict__ w0,
                              const float* __restrict__ w1,
                              const float* __restrict__ w2) {
    int idx = blockIdx.x * blockDim.x + threadIdx.x;
    if (idx >= NCHUNK_TOT * 8192) return;
    int gch = idx >> 13;
    int r   = (idx >> 8) & 31;
    int n   = idx & 255;
    float v;
    if (gch < 2) {
        int k = gch * 32 + r;                 // 0..63; rows 0..47 = x+tf weights
        v = (k < 48) ? w0[k * 256 + n] : 0.f;
    } else if (gch < 10) {
        int k = (gch - 2) * 32 + r;
        v = w1[k * 256 + n];
    } else {
        int k = (gch - 10) * 32 + r;
        v = w2[k * 256 + n];
    }
    __nv_bfloat16 hi = __float2bfloat16(v);
    __nv_bfloat16 lo = __float2bfloat16(v - __bfloat162float(hi));
    int pos = gch * 16384 + r * 256 + (((n >> 3) ^ (r & 7)) << 3) + (n & 7);
    g_w[pos] = hi;
    g_w[pos + 8192] = lo;
}

// ------- init: C0 = state @ w0[48:176] + b0, exact fp32 ----------------------
__global__ void precompute_c0(const float* __restrict__ state,
                              const float* __restrict__ w0,
                              const float* __restrict__ b0) {
    int idx = blockIdx.x * blockDim.x + threadIdx.x;
    if (idx >= 4096 * 256) return;
    int r = idx >> 8, n = idx & 255;
    float acc = b0[n];
#pragma unroll 4
    for (int k = 0; k < 128; ++k)
        acc = fmaf(state[r * 128 + k], w0[(48 + k) * 256 + n], acc);
    g_c0[idx] = acc;
}

// ------- init: per-step coefficients + time-MLP output -----------------------
__global__ void precompute(const float* __restrict__ w_t1,
                           const float* __restrict__ b_t1,
                           const float* __restrict__ w_t2,
                           const float* __restrict__ b_t2) {
    int i = blockIdx.x * blockDim.x + threadIdx.x;
    if (i >= 1000) return;
    double nn    = (double)(i + 1);
    double ac    = exp(-1e-4 * nn - 4.95e-6 * nn * nn);
    double nm    = nn - 1.0;
    double acp   = (i == 0) ? 1.0 : exp(-1e-4 * nm - 4.95e-6 * nm * nm);
    double beta  = 1.0 - exp(-1e-4 - 4.95e-6 * (2.0 * nn - 1.0));
    double alpha = 1.0 - beta;
    g_cf[i * 8 + 0] = (float)sqrt(1.0 / ac);
    g_cf[i * 8 + 1] = (float)sqrt(1.0 / ac - 1.0);
    g_cf[i * 8 + 2] = (float)(beta * sqrt(acp) / (1.0 - ac));
    g_cf[i * 8 + 3] = (float)((1.0 - acp) * sqrt(alpha) / (1.0 - ac));
    double pv = beta * (1.0 - acp) / (1.0 - ac);
    if (pv < 1e-20) pv = 1e-20;
    float lv = (float)log(pv);
    g_cf[i * 8 + 4] = (float)exp((double)(0.5f * lv));
    unsigned a0 = 0u, a1 = (unsigned)i;
    threefry2x32(0u, 1u, a0, a1);
    g_cf[i * 8 + 5] = __uint_as_float(a0);
    g_cf[i * 8 + 6] = __uint_as_float(a1);
    float te[16];
    for (int t = 0; t < 8; ++t) {
        float c8   = (float)(-9.210340371976184 / 7.0);
        float freq = expf(c8 * (float)t);
        float ang  = (float)i * freq;
        te[t]     = (float)sin((double)ang);
        te[t + 8] = (float)cos((double)ang);
    }
    float ht[32];
    for (int j = 0; j < 32; ++j) {
        float h = b_t1[j];
        for (int k = 0; k < 16; ++k) h = fmaf(te[k], w_t1[k * 32 + j], h);
        ht[j] = mish_f(h);
    }
    for (int j = 0; j < 16; ++j) {
        float v = b_t2[j];
        for (int k = 0; k < 32; ++k) v = fmaf(ht[k], w_t2[k * 16 + j], v);
        g_tf[i * 16 + j] = v;
    }
}

// ---------------- persistent sampler -----------------------------------------
__global__ void __launch_bounds__(NT, 1)
diff_all(const float* __restrict__ x_init,
         const float* __restrict__ b1,  const float* __restrict__ b2,
         const float* __restrict__ wf,  const float* __restrict__ bf,
         float* __restrict__ outp)
{
    extern __shared__ __align__(16) char smraw[];
    __nv_bfloat16* smb = reinterpret_cast<__nv_bfloat16*>(smraw);
    unsigned smem_u32 = (unsigned)__cvta_generic_to_shared(smraw);

    __nv_bfloat16* A0h = smb + B_A0H;  __nv_bfloat16* A0l = smb + B_A0L;
    __nv_bfloat16* A1h = smb + B_A1H;  __nv_bfloat16* A1l = smb + B_A1L;
    __nv_bfloat16* A2h = smb + B_A2H;  __nv_bfloat16* A2l = smb + B_A2L;
    __nv_bfloat16* WFH = smb + WFH_UNIT;
    __nv_bfloat16* WFL = smb + WFL_UNIT;

    const int tid = threadIdx.x;
    const int r0  = blockIdx.x * BR;

    if (tid == 0) {
#pragma unroll
        for (int b = 0; b < 3; ++b) {
            MBAR_INIT(smem_u32 + MBAR_BYTE + 8u * b, 1u);        // full
            MBAR_INIT(smem_u32 + MBAR_BYTE + 24u + 8u * b, 16u); // empty
        }
    }
    // final-layer weights -> smem bf16 hi/lo, row stride 40
    for (int idx = tid; idx < 256 * 32; idx += NT) {
        int k = idx >> 5, n = idx & 31;
        store_split1(WFH, WFL, k * 40 + n, wf[idx]);
    }
    // initial A0: x | tf(999) | zeros (cols 48..63, one-time)
    for (int idx = tid; idx < 32 * 48; idx += NT) {
        int r = idx & 31, c = idx >> 5;
        float v = (c < 32) ? x_init[(r0 + r) * 32 + c] : g_tf[999 * 16 + (c - 32)];
        store_split1(A0h, A0l, r * A0S + c, v);
    }
    for (int idx = tid; idx < 32 * 16; idx += NT) {
        int r = idx >> 4, c = idx & 15;
        A0h[r * A0S + 48 + c] = __float2bfloat16(0.f);
        A0l[r * A0S + 48 + c] = __float2bfloat16(0.f);
    }

    // lane geometry (shared by gemm layers / final layer / c0 slice)
    const int wq = tid >> 5, lane = tid & 31;
    const int gq = lane >> 2, tq = lane & 3;
    const int mrowq = (wq & 1) << 4;
    const int qq = wq >> 1;                 // 0..7 (trunk col group)
    const int c0q = qq * 8 + 2 * tq;        // final-layer col base (warps 0-7)

    // per-thread C0 slice (state contribution to layer 0, bias folded)
    float c0reg[16];
#pragma unroll
    for (int nt = 0; nt < 4; ++nt) {
        const int col = (qq << 5) + (nt << 3) + 2 * tq;
#pragma unroll
        for (int jj = 0; jj < 4; ++jj) {
            int row = mrowq + gq + ((jj >> 1) << 3);
            c0reg[nt * 4 + jj] = g_c0[(r0 + row) * 256 + col + (jj & 1)];
        }
    }

    // register-resident x for the x-update lanes (warps 0-7)
    float xreg[4];
    if (tid < 256) {
#pragma unroll
        for (int rr = 0; rr < 2; ++rr)
#pragma unroll
            for (int cc = 0; cc < 2; ++cc)
                xreg[rr * 2 + cc] = x_init[(r0 + mrowq + gq + rr * 8) * 32 + c0q + cc];
    }
    __syncthreads();   // barriers + A0 + WF ready

    // pre-complete empty[2] phase 0; pipeline fill chunks 0,1
    if ((tid & 31) == 0) MBAR_ARRIVE(smem_u32 + MBAR_BYTE + 24u + 16u);
    if (tid == 0) {
#pragma unroll
        for (int b = 0; b < 2; ++b) {
            unsigned mb = smem_u32 + MBAR_BYTE + 8u * b;
            MBAR_EXPECT_TX(mb, 32768u);
            bulk_stage(smem_u32 + WB_BYTE + 32768u * b, g_w + b * 16384, mb);
        }
    }
    int cb = 0, stg = 2;
    unsigned fph = 0, eph = 0;

#pragma unroll 1
    for (int i = 999; i >= 0; --i) {
        gemm_layer<2, A0S, true >(nullptr, c0reg, A0h, A0l, A1h, A1l, smb, smem_u32, cb, stg, fph, eph, tid);
        __syncthreads();
        gemm_layer<8, AS,  false>(b1, nullptr, A1h, A1l, A2h, A2l, smb, smem_u32, cb, stg, fph, eph, tid);
        __syncthreads();
        gemm_layer<8, AS,  false>(b2, nullptr, A2h, A2l, A1h, A1l, smb, smem_u32, cb, stg, fph, eph, tid);
        __syncthreads();

        if (tid < 256) {
            // ---- final 256->32 via split-bf16 mma + in-register x-update
            const int krow_l = (lane & 7) + ((lane >> 3) & 1) * 8;
            const float* cf = &g_cf[i * 8];
            float sr  = __ldg(cf + 0), srm1 = __ldg(cf + 1);
            float c1  = __ldg(cf + 2), c2   = __ldg(cf + 3);
            float sig = __ldg(cf + 4);
            unsigned fk0 = __float_as_uint(__ldg(cf + 5));
            unsigned fk1 = __float_as_uint(__ldg(cf + 6));

            float aHH[4] = {0.f, 0.f, 0.f, 0.f};
            float aHL[4] = {0.f, 0.f, 0.f, 0.f};
            float aLH[4] = {0.f, 0.f, 0.f, 0.f};
#pragma unroll
            for (int ks = 0; ks < 16; ++ks) {
                const int kg = ks * 16;
                const __nv_bfloat16* ah_p = A1h + (mrowq + gq) * AS + kg + 2 * tq;
                const __nv_bfloat16* al_p = A1l + (mrowq + gq) * AS + kg + 2 * tq;
                unsigned ah[4], al[4];
                ah[0] = *reinterpret_cast<const unsigned*>(ah_p);
                ah[1] = *reinterpret_cast<const unsigned*>(ah_p + 8 * AS);
                ah[2] = *reinterpret_cast<const unsigned*>(ah_p + 8);
                ah[3] = *reinterpret_cast<const unsigned*>(ah_p + 8 * AS + 8);
                al[0] = *reinterpret_cast<const unsigned*>(al_p);
                al[1] = *reinterpret_cast<const unsigned*>(al_p + 8 * AS);
                al[2] = *reinterpret_cast<const unsigned*>(al_p + 8);
                al[3] = *reinterpret_cast<const unsigned*>(al_p + 8 * AS + 8);
                unsigned bh[2], bl[2];
                const int wfo = (kg + krow_l) * 40 + qq * 8;
                ldsm2t(bh, WFH + wfo);
                ldsm2t(bl, WFL + wfo);
                mma_bf16(aHH, ah, bh[0], bh[1]);
                mma_bf16(aHL, ah, bl[0], bl[1]);
                mma_bf16(aLH, al, bh[0], bh[1]);
            }

            float bfc0 = __ldg(bf + c0q), bfc1 = __ldg(bf + c0q + 1);
            float epsv[4] = {
                aHH[0] + aHL[0] + aLH[0] + bfc0,
                aHH[1] + aHL[1] + aLH[1] + bfc1,
                aHH[2] + aHL[2] + aLH[2] + bfc0,
                aHH[3] + aHL[3] + aLH[3] + bfc1 };

#pragma unroll
            for (int rr = 0; rr < 2; ++rr) {
                const int row = mrowq + gq + rr * 8;
                const int R = r0 + row;
#pragma unroll
                for (int cc = 0; cc < 2; ++cc) {
                    const int j = c0q + cc;
                    float e  = epsv[rr * 2 + cc];
                    float xv = xreg[rr * 2 + cc];
                    float x0 = fminf(1.f, fmaxf(-1.f, sr * xv - srm1 * e));
                    float mean = c1 * x0 + c2 * xv;
                    if (i != 0) {
                        unsigned f = (unsigned)(R * 32 + j);
                        unsigned b0r = 0u, b1r = f;
                        threefry2x32(fk0, fk1, b0r, b1r);
                        unsigned bits = b0r ^ b1r;
                        float fv = __uint_as_float((bits >> 9) | 0x3f800000u) - 1.0f;
                        const float lo = -0.99999994f;
                        float u   = fmaxf(lo, fmaf(fv, 2.0f, lo));
                        float nrm = 1.4142135623730951f * erfinv_xla(u);
                        float xn = mean + sig * nrm;
                        xreg[rr * 2 + cc] = xn;
                        store_split1(A0h, A0l, row * A0S + j, xn);
                    } else {
                        float xf = fminf(1.f, fmaxf(-1.f, mean));
                        outp[R * 32 + j] = xf;
                    }
                }
            }
        } else if (i != 0) {
            // ---- warps 8-15: write tf (cols 32..47) for the NEXT step
            const int t2 = tid - 256;
#pragma unroll
            for (int l = 0; l < 2; ++l) {
                int idx = t2 + l * 256;
                int r = idx & 31, c = idx >> 5;      // c = 0..15 -> col 32+c
                float v = __ldg(&g_tf[(i - 1) * 16 + c]);
                store_split1(A0h, A0l, r * A0S + 32 + c, v);
            }
        }
        __syncthreads();
    }
}

extern "C" void kernel_launch(void* const* d_in, const int* in_sizes, int n_in,
                              void* d_out, int out_size) {
    const float* state = (const float*)d_in[0];
    const float* xinit = (const float*)d_in[1];
    const float* w_t1  = (const float*)d_in[2];
    const float* b_t1  = (const float*)d_in[3];
    const float* w_t2  = (const float*)d_in[4];
    const float* b_t2  = (const float*)d_in[5];
    const float* w0    = (const float*)d_in[6];
    const float* b0    = (const float*)d_in[7];
    const float* w1    = (const float*)d_in[8];
    const float* b1    = (const float*)d_in[9];
    const float* w2    = (const float*)d_in[10];
    const float* b2    = (const float*)d_in[11];
    const float* wf    = (const float*)d_in[12];
    const float* bf    = (const float*)d_in[13];
    float* outp = (float*)d_out;

    cudaFuncSetAttribute(diff_all, cudaFuncAttributeMaxDynamicSharedMemorySize, SMEM_BYTES);

    split_weights<<<(NCHUNK_TOT * 8192 + 255) / 256, 256>>>(w0, w1, w2);
    precompute<<<4, 256>>>(w_t1, b_t1, w_t2, b_t2);
    precompute_c0<<<4096, 256>>>(state, w0, b0);
    diff_all<<<NB, NT, SMEM_BYTES>>>(xinit, b1, b2, wf, bf, outp);
}